// round 1
// baseline (speedup 1.0000x reference)
#include <cuda_runtime.h>
#include <math.h>

// Problem constants
#define BD 4
#define SD 2048
#define DM 1024
#define NH 16
#define DK 64
#define MTOK (BD*SD)   // 8192 tokens

// ---------------- scratch (static device memory: allowed) ----------------
__device__ float g_q [(size_t)MTOK * DM];
__device__ float g_k [(size_t)MTOK * DM];
__device__ float g_v [(size_t)MTOK * DM];
__device__ float g_ao[(size_t)MTOK * DM];

// ---------------- SGEMM: C[M,N] = A[M,K] @ W[N,K]^T ----------------
// M=8192, N=1024, K=1024 fixed. 128x128 block, 8x8 microtile, BK=8.
#define BM 128
#define BN 128
#define BKK 8
#define TM 8
#define TN 8

__global__ __launch_bounds__(256)
void sgemm_nt(const float* __restrict__ A,
              const float* __restrict__ W,
              float* __restrict__ C) {
    const int N = DM, K = DM;
    __shared__ float As[BKK][BM];
    __shared__ float Ws[BKK][BN];

    const int bm  = blockIdx.y * BM;
    const int bn  = blockIdx.x * BN;
    const int tid = threadIdx.x;
    const int lrow = tid >> 1;          // 0..127
    const int lcol = (tid & 1) * 4;     // 0 or 4
    const int ty = tid >> 4;            // 0..15
    const int tx = tid & 15;            // 0..15

    float acc[TM][TN];
#pragma unroll
    for (int i = 0; i < TM; i++)
#pragma unroll
        for (int j = 0; j < TN; j++) acc[i][j] = 0.f;

    const float* Ap = A + (size_t)(bm + lrow) * K + lcol;
    const float* Wp = W + (size_t)(bn + lrow) * K + lcol;

    for (int k0 = 0; k0 < K; k0 += BKK) {
        float4 av = *reinterpret_cast<const float4*>(Ap + k0);
        float4 wv = *reinterpret_cast<const float4*>(Wp + k0);
        As[lcol+0][lrow] = av.x; As[lcol+1][lrow] = av.y;
        As[lcol+2][lrow] = av.z; As[lcol+3][lrow] = av.w;
        Ws[lcol+0][lrow] = wv.x; Ws[lcol+1][lrow] = wv.y;
        Ws[lcol+2][lrow] = wv.z; Ws[lcol+3][lrow] = wv.w;
        __syncthreads();
#pragma unroll
        for (int kk = 0; kk < BKK; kk++) {
            float4 a0 = *reinterpret_cast<const float4*>(&As[kk][ty*TM]);
            float4 a1 = *reinterpret_cast<const float4*>(&As[kk][ty*TM+4]);
            float4 w0 = *reinterpret_cast<const float4*>(&Ws[kk][tx*TN]);
            float4 w1 = *reinterpret_cast<const float4*>(&Ws[kk][tx*TN+4]);
            float af[TM] = {a0.x,a0.y,a0.z,a0.w,a1.x,a1.y,a1.z,a1.w};
            float wf[TN] = {w0.x,w0.y,w0.z,w0.w,w1.x,w1.y,w1.z,w1.w};
#pragma unroll
            for (int i = 0; i < TM; i++)
#pragma unroll
                for (int j = 0; j < TN; j++)
                    acc[i][j] += af[i] * wf[j];
        }
        __syncthreads();
    }

#pragma unroll
    for (int i = 0; i < TM; i++) {
        float* crow = C + (size_t)(bm + ty*TM + i) * N + bn + tx*TN;
        *reinterpret_cast<float4*>(crow)     = make_float4(acc[i][0],acc[i][1],acc[i][2],acc[i][3]);
        *reinterpret_cast<float4*>(crow + 4) = make_float4(acc[i][4],acc[i][5],acc[i][6],acc[i][7]);
    }
}

// ---------------- RoPE on q and k in place ----------------
// Layout: [tok, DM]; within a head, pairs (2i, 2i+1); inv_freq = theta^(-d0/DK)
__global__ void rope_kernel(float* __restrict__ q, float* __restrict__ k,
                            const int* __restrict__ pos) {
    int idx = blockIdx.x * blockDim.x + threadIdx.x;
    const int total = MTOK * (DM / 2);
    if (idx >= total) return;
    int tok  = idx >> 9;          // / 512
    int pr   = idx & 511;
    int col  = pr * 2;
    int d0   = col & (DK - 1);    // position within head
    float p  = (float)pos[tok];
    const float ln_theta = 9.210340371976184f;  // ln(10000)
    float inv_freq = __expf(-(float)d0 * (ln_theta / (float)DK));
    float ang = p * inv_freq;
    float s, c;
    sincosf(ang, &s, &c);
    size_t off = (size_t)tok * DM + col;
    float2 qv = *reinterpret_cast<float2*>(q + off);
    float2 kv = *reinterpret_cast<float2*>(k + off);
    float2 qo = make_float2(qv.x * c - qv.y * s, qv.x * s + qv.y * c);
    float2 ko = make_float2(kv.x * c - kv.y * s, kv.x * s + kv.y * c);
    *reinterpret_cast<float2*>(q + off) = qo;
    *reinterpret_cast<float2*>(k + off) = ko;
}

// ---------------- causal flash attention ----------------
// One block = 64 query rows of one (b,h). One thread = one query row.
// K tile / V tile in smem; ks[j][kk]/vs[j][d] reads are warp-broadcast.
#define QB 64
#define KBL 32

__global__ __launch_bounds__(64)
void flash_kernel(const float* __restrict__ q,
                  const float* __restrict__ k,
                  const float* __restrict__ v,
                  float* __restrict__ o) {
    __shared__ float ks[KBL][DK + 1];
    __shared__ float vs[KBL][DK + 1];
    __shared__ float ps[QB][KBL + 1];

    const int t  = threadIdx.x;                 // query row in tile
    const int qb = gridDim.x - 1 - blockIdx.x;  // heavy tiles scheduled first
    const int h  = blockIdx.y;
    const int b  = blockIdx.z;
    const int q0 = qb * QB;
    const size_t tokBase = (size_t)b * SD;

    // load my query row into registers, fold in 1/sqrt(DK)=0.125
    const float* qrow = q + (tokBase + q0 + t) * DM + h * DK;
    float qr[DK];
#pragma unroll
    for (int i = 0; i < DK / 4; i++) {
        float4 t4 = *reinterpret_cast<const float4*>(qrow + i * 4);
        qr[i*4+0] = t4.x * 0.125f; qr[i*4+1] = t4.y * 0.125f;
        qr[i*4+2] = t4.z * 0.125f; qr[i*4+3] = t4.w * 0.125f;
    }

    float m = -1e30f, l = 0.f;
    float out[DK];
#pragma unroll
    for (int d = 0; d < DK; d++) out[d] = 0.f;

    const int ntiles = (q0 + QB) / KBL;   // causal extent
    for (int kt = 0; kt < ntiles; kt++) {
        const int k0 = kt * KBL;
        __syncthreads();
        const float* kbase = k + (tokBase + k0) * DM + h * DK;
        const float* vbase = v + (tokBase + k0) * DM + h * DK;
        // coalesced tile load: iter it loads row 'it', col 't'
#pragma unroll 4
        for (int it = 0; it < KBL; it++) {
            ks[it][t] = kbase[(size_t)it * DM + t];
            vs[it][t] = vbase[(size_t)it * DM + t];
        }
        __syncthreads();

        // pass 1: scores + tile max
        float tmax = -1e30f;
        for (int j = 0; j < KBL; j++) {
            float s0 = 0.f, s1 = 0.f;
#pragma unroll
            for (int kk = 0; kk < DK; kk += 2) {
                s0 += qr[kk]   * ks[j][kk];
                s1 += qr[kk+1] * ks[j][kk+1];
            }
            float s = s0 + s1;
            if (k0 + j > q0 + t) s = -1e30f;   // causal mask
            ps[t][j] = s;
            tmax = fmaxf(tmax, s);
        }

        float mnew  = fmaxf(m, tmax);
        float alpha = __expf(m - mnew);
        m = mnew;
        l *= alpha;
#pragma unroll
        for (int d = 0; d < DK; d++) out[d] *= alpha;

        // pass 2: P @ V
        for (int j = 0; j < KBL; j++) {
            float p = __expf(ps[t][j] - mnew);
            l += p;
#pragma unroll
            for (int d = 0; d < DK; d++)
                out[d] += p * vs[j][d];
        }
    }

    float inv = 1.0f / l;
    float* optr = o + (tokBase + q0 + t) * DM + h * DK;
#pragma unroll
    for (int i = 0; i < DK / 4; i++) {
        *reinterpret_cast<float4*>(optr + i * 4) =
            make_float4(out[i*4+0]*inv, out[i*4+1]*inv, out[i*4+2]*inv, out[i*4+3]*inv);
    }
}

// ---------------- launch ----------------
extern "C" void kernel_launch(void* const* d_in, const int* in_sizes, int n_in,
                              void* d_out, int out_size) {
    const float* x  = (const float*)d_in[0];
    const int*   tp = (const int*)  d_in[1];
    const float* Qw = (const float*)d_in[2];
    const float* Kw = (const float*)d_in[3];
    const float* Vw = (const float*)d_in[4];
    const float* Ow = (const float*)d_in[5];
    float* out = (float*)d_out;

    float *gq, *gk, *gv, *gao;
    cudaGetSymbolAddress((void**)&gq,  g_q);
    cudaGetSymbolAddress((void**)&gk,  g_k);
    cudaGetSymbolAddress((void**)&gv,  g_v);
    cudaGetSymbolAddress((void**)&gao, g_ao);

    dim3 ggrid(DM / BN, MTOK / BM);   // (8, 64)
    sgemm_nt<<<ggrid, 256>>>(x, Qw, gq);
    sgemm_nt<<<ggrid, 256>>>(x, Kw, gk);
    sgemm_nt<<<ggrid, 256>>>(x, Vw, gv);

    int rope_total  = MTOK * (DM / 2);
    int rope_blocks = (rope_total + 255) / 256;
    rope_kernel<<<rope_blocks, 256>>>(gq, gk, tp);

    dim3 fgrid(SD / QB, NH, BD);      // (32, 16, 4)
    flash_kernel<<<fgrid, QB>>>(gq, gk, gv, gao);

    sgemm_nt<<<ggrid, 256>>>(gao, Ow, out);
}

// round 3
// speedup vs baseline: 1.2263x; 1.2263x over previous
#include <cuda_runtime.h>
#include <math.h>
#include <stdint.h>
#include <mma.h>

using namespace nvcuda;

// Problem constants
#define BD 4
#define SD 2048
#define DM 1024
#define NH 16
#define DK 64
#define MTOK (BD*SD)   // 8192 tokens

// ---------------- scratch (static device memory: allowed) ----------------
__device__ float g_q [(size_t)MTOK * DM];
__device__ float g_k [(size_t)MTOK * DM];
__device__ float g_v [(size_t)MTOK * DM];
__device__ float g_ao[(size_t)MTOK * DM];

__device__ __forceinline__ float f32_to_tf32_rna(float f) {
    uint32_t r;
    asm("cvt.rna.tf32.f32 %0, %1;" : "=r"(r) : "f"(f));
    return __uint_as_float(r);
}

// ======================================================================
// tf32 mma.sync GEMM: C[M,N] = A[M,K] @ W[N,K]^T, M=8192, N=K=1024
// CTA tile 128x128, 8 warps (2m x 4n), warp tile 64x32, K-chunk 32.
// Double-buffered smem; LDG of chunk kt+1 overlaps wmma of chunk kt.
// ======================================================================
#define GBM 128
#define GBN 128
#define GBK 32
#define LDS_PAD 4
#define LDSW (GBK + LDS_PAD)          // 36 floats per smem row
#define TILE_FLOATS (GBM * LDSW)      // 4608
#define NCHUNK (DM / GBK)             // 32

// smem: As[2][128][36], Ws[2][128][36]  (floats)
#define SM_FLOATS (4 * TILE_FLOATS)   // 18432 floats = 73728 B

__global__ __launch_bounds__(256)
void gemm_tf32(const float* __restrict__ A,
               const float* __restrict__ W,
               float* __restrict__ C) {
    extern __shared__ float smem[];
    float* As[2] = { smem,                  smem + TILE_FLOATS };
    float* Ws[2] = { smem + 2*TILE_FLOATS,  smem + 3*TILE_FLOATS };

    const int tid  = threadIdx.x;
    const int wid  = tid >> 5;
    const int bm = blockIdx.y * GBM;
    const int bn = blockIdx.x * GBN;
    const int wm = wid >> 2;          // 0..1
    const int wn = wid & 3;           // 0..3

    // fill mapping: row = tid>>1 (0..127), cbase = (tid&1)*16
    const int row   = tid >> 1;
    const int cbase = (tid & 1) * 16;
    const float* Ap = A + (size_t)(bm + row) * DM + cbase;
    const float* Wp = W + (size_t)(bn + row) * DM + cbase;

    wmma::fragment<wmma::accumulator, 16, 16, 8, float> acc[4][2];
#pragma unroll
    for (int i = 0; i < 4; i++)
#pragma unroll
        for (int j = 0; j < 2; j++)
            wmma::fill_fragment(acc[i][j], 0.0f);

    float4 ra[4], rw[4];

    // prologue: load chunk 0
#pragma unroll
    for (int i = 0; i < 4; i++) {
        ra[i] = *reinterpret_cast<const float4*>(Ap + i * 4);
        rw[i] = *reinterpret_cast<const float4*>(Wp + i * 4);
    }
    {
        float* dA = As[0] + row * LDSW + cbase;
        float* dW = Ws[0] + row * LDSW + cbase;
#pragma unroll
        for (int i = 0; i < 4; i++) {
            float4 ca = make_float4(f32_to_tf32_rna(ra[i].x), f32_to_tf32_rna(ra[i].y),
                                    f32_to_tf32_rna(ra[i].z), f32_to_tf32_rna(ra[i].w));
            float4 cw = make_float4(f32_to_tf32_rna(rw[i].x), f32_to_tf32_rna(rw[i].y),
                                    f32_to_tf32_rna(rw[i].z), f32_to_tf32_rna(rw[i].w));
            *reinterpret_cast<float4*>(dA + i * 4) = ca;
            *reinterpret_cast<float4*>(dW + i * 4) = cw;
        }
    }
    __syncthreads();

    for (int kt = 0; kt < NCHUNK; kt++) {
        const int cur = kt & 1;
        const int nxt = cur ^ 1;

        // issue LDGs for the next chunk (latency overlaps compute below)
        if (kt + 1 < NCHUNK) {
            const float* ap = Ap + (kt + 1) * GBK;
            const float* wp = Wp + (kt + 1) * GBK;
#pragma unroll
            for (int i = 0; i < 4; i++) {
                ra[i] = *reinterpret_cast<const float4*>(ap + i * 4);
                rw[i] = *reinterpret_cast<const float4*>(wp + i * 4);
            }
        }

        // compute current chunk: 4 k-steps of 8
        const float* Abuf = As[cur] + (wm * 64) * LDSW;
        const float* Wbuf = Ws[cur] + (wn * 32) * LDSW;
#pragma unroll
        for (int ks = 0; ks < 4; ks++) {
            wmma::fragment<wmma::matrix_a, 16, 16, 8, wmma::precision::tf32, wmma::row_major> afr[4];
            wmma::fragment<wmma::matrix_b, 16, 16, 8, wmma::precision::tf32, wmma::col_major> bfr[2];
#pragma unroll
            for (int i = 0; i < 4; i++)
                wmma::load_matrix_sync(afr[i], Abuf + (i * 16) * LDSW + ks * 8, LDSW);
#pragma unroll
            for (int j = 0; j < 2; j++)
                wmma::load_matrix_sync(bfr[j], Wbuf + (j * 16) * LDSW + ks * 8, LDSW);
#pragma unroll
            for (int i = 0; i < 4; i++)
#pragma unroll
                for (int j = 0; j < 2; j++)
                    wmma::mma_sync(acc[i][j], afr[i], bfr[j], acc[i][j]);
        }

        // store next chunk into the other buffer
        if (kt + 1 < NCHUNK) {
            float* dA = As[nxt] + row * LDSW + cbase;
            float* dW = Ws[nxt] + row * LDSW + cbase;
#pragma unroll
            for (int i = 0; i < 4; i++) {
                float4 ca = make_float4(f32_to_tf32_rna(ra[i].x), f32_to_tf32_rna(ra[i].y),
                                        f32_to_tf32_rna(ra[i].z), f32_to_tf32_rna(ra[i].w));
                float4 cw = make_float4(f32_to_tf32_rna(rw[i].x), f32_to_tf32_rna(rw[i].y),
                                        f32_to_tf32_rna(rw[i].z), f32_to_tf32_rna(rw[i].w));
                *reinterpret_cast<float4*>(dA + i * 4) = ca;
                *reinterpret_cast<float4*>(dW + i * 4) = cw;
            }
        }
        __syncthreads();
    }

    // epilogue: each warp stores its 64x32 region
    const int m0 = bm + wm * 64;
    const int n0 = bn + wn * 32;
#pragma unroll
    for (int i = 0; i < 4; i++)
#pragma unroll
        for (int j = 0; j < 2; j++)
            wmma::store_matrix_sync(C + (size_t)(m0 + i * 16) * DM + n0 + j * 16,
                                    acc[i][j], DM, wmma::mem_row_major);
}

// ---------------- RoPE on q and k in place ----------------
__global__ void rope_kernel(float* __restrict__ q, float* __restrict__ k,
                            const int* __restrict__ pos) {
    int idx = blockIdx.x * blockDim.x + threadIdx.x;
    const int total = MTOK * (DM / 2);
    if (idx >= total) return;
    int tok  = idx >> 9;
    int pr   = idx & 511;
    int col  = pr * 2;
    int d0   = col & (DK - 1);
    float p  = (float)pos[tok];
    const float ln_theta = 9.210340371976184f;
    float inv_freq = __expf(-(float)d0 * (ln_theta / (float)DK));
    float ang = p * inv_freq;
    float s, c;
    sincosf(ang, &s, &c);
    size_t off = (size_t)tok * DM + col;
    float2 qv = *reinterpret_cast<float2*>(q + off);
    float2 kv = *reinterpret_cast<float2*>(k + off);
    float2 qo = make_float2(qv.x * c - qv.y * s, qv.x * s + qv.y * c);
    float2 ko = make_float2(kv.x * c - kv.y * s, kv.x * s + kv.y * c);
    *reinterpret_cast<float2*>(q + off) = qo;
    *reinterpret_cast<float2*>(k + off) = ko;
}

// ---------------- causal flash attention ----------------
#define QB 64
#define KBL 32

__global__ __launch_bounds__(64)
void flash_kernel(const float* __restrict__ q,
                  const float* __restrict__ k,
                  const float* __restrict__ v,
                  float* __restrict__ o) {
    __shared__ float ks[KBL][DK + 1];
    __shared__ float vs[KBL][DK + 1];
    __shared__ float ps[QB][KBL + 1];

    const int t  = threadIdx.x;
    const int qb = gridDim.x - 1 - blockIdx.x;
    const int h  = blockIdx.y;
    const int b  = blockIdx.z;
    const int q0 = qb * QB;
    const size_t tokBase = (size_t)b * SD;

    const float* qrow = q + (tokBase + q0 + t) * DM + h * DK;
    float qr[DK];
#pragma unroll
    for (int i = 0; i < DK / 4; i++) {
        float4 t4 = *reinterpret_cast<const float4*>(qrow + i * 4);
        qr[i*4+0] = t4.x * 0.125f; qr[i*4+1] = t4.y * 0.125f;
        qr[i*4+2] = t4.z * 0.125f; qr[i*4+3] = t4.w * 0.125f;
    }

    float m = -1e30f, l = 0.f;
    float out[DK];
#pragma unroll
    for (int d = 0; d < DK; d++) out[d] = 0.f;

    const int ntiles = (q0 + QB) / KBL;
    for (int kt = 0; kt < ntiles; kt++) {
        const int k0 = kt * KBL;
        __syncthreads();
        const float* kbase = k + (tokBase + k0) * DM + h * DK;
        const float* vbase = v + (tokBase + k0) * DM + h * DK;
#pragma unroll 4
        for (int it = 0; it < KBL; it++) {
            ks[it][t] = kbase[(size_t)it * DM + t];
            vs[it][t] = vbase[(size_t)it * DM + t];
        }
        __syncthreads();

        float tmax = -1e30f;
        for (int j = 0; j < KBL; j++) {
            float s0 = 0.f, s1 = 0.f;
#pragma unroll
            for (int kk = 0; kk < DK; kk += 2) {
                s0 += qr[kk]   * ks[j][kk];
                s1 += qr[kk+1] * ks[j][kk+1];
            }
            float s = s0 + s1;
            if (k0 + j > q0 + t) s = -1e30f;
            ps[t][j] = s;
            tmax = fmaxf(tmax, s);
        }

        float mnew  = fmaxf(m, tmax);
        float alpha = __expf(m - mnew);
        m = mnew;
        l *= alpha;
#pragma unroll
        for (int d = 0; d < DK; d++) out[d] *= alpha;

        for (int j = 0; j < KBL; j++) {
            float p = __expf(ps[t][j] - mnew);
            l += p;
#pragma unroll
            for (int d = 0; d < DK; d++)
                out[d] += p * vs[j][d];
        }
    }

    float inv = 1.0f / l;
    float* optr = o + (tokBase + q0 + t) * DM + h * DK;
#pragma unroll
    for (int i = 0; i < DK / 4; i++) {
        *reinterpret_cast<float4*>(optr + i * 4) =
            make_float4(out[i*4+0]*inv, out[i*4+1]*inv, out[i*4+2]*inv, out[i*4+3]*inv);
    }
}

// ---------------- launch ----------------
extern "C" void kernel_launch(void* const* d_in, const int* in_sizes, int n_in,
                              void* d_out, int out_size) {
    const float* x  = (const float*)d_in[0];
    const int*   tp = (const int*)  d_in[1];
    const float* Qw = (const float*)d_in[2];
    const float* Kw = (const float*)d_in[3];
    const float* Vw = (const float*)d_in[4];
    const float* Ow = (const float*)d_in[5];
    float* out = (float*)d_out;

    float *gq, *gk, *gv, *gao;
    cudaGetSymbolAddress((void**)&gq,  g_q);
    cudaGetSymbolAddress((void**)&gk,  g_k);
    cudaGetSymbolAddress((void**)&gv,  g_v);
    cudaGetSymbolAddress((void**)&gao, g_ao);

    const int smem_bytes = SM_FLOATS * 4;   // 73728
    cudaFuncSetAttribute(gemm_tf32, cudaFuncAttributeMaxDynamicSharedMemorySize, smem_bytes);

    dim3 ggrid(DM / GBN, MTOK / GBM);   // (8, 64)
    gemm_tf32<<<ggrid, 256, smem_bytes>>>(x, Qw, gq);
    gemm_tf32<<<ggrid, 256, smem_bytes>>>(x, Kw, gk);
    gemm_tf32<<<ggrid, 256, smem_bytes>>>(x, Vw, gv);

    int rope_total  = MTOK * (DM / 2);
    int rope_blocks = (rope_total + 255) / 256;
    rope_kernel<<<rope_blocks, 256>>>(gq, gk, tp);

    dim3 fgrid(SD / QB, NH, BD);        // (32, 16, 4)
    flash_kernel<<<fgrid, QB>>>(gq, gk, gv, gao);

    gemm_tf32<<<ggrid, 256, smem_bytes>>>(gao, Ow, out);
}

// round 4
// speedup vs baseline: 2.1004x; 1.7128x over previous
#include <cuda_runtime.h>
#include <math.h>
#include <stdint.h>

// Problem constants
#define BD 4
#define SD 2048
#define DM 1024
#define NH 16
#define DK 64
#define MTOK (BD*SD)   // 8192 tokens

// ---------------- scratch (static device memory: allowed) ----------------
__device__ float g_q [(size_t)MTOK * DM];
__device__ float g_k [(size_t)MTOK * DM];
__device__ float g_v [(size_t)MTOK * DM];
__device__ float g_ao[(size_t)MTOK * DM];

__device__ __forceinline__ uint32_t f32_to_tf32_rna_u(float f) {
    uint32_t r;
    asm("cvt.rna.tf32.f32 %0, %1;" : "=r"(r) : "f"(f));
    return r;
}

__device__ __forceinline__ void mma_tf32(float* c, uint32_t a0, uint32_t a1,
                                         uint32_t a2, uint32_t a3,
                                         uint32_t b0, uint32_t b1) {
    asm volatile(
        "mma.sync.aligned.m16n8k8.row.col.f32.tf32.tf32.f32 "
        "{%0,%1,%2,%3}, {%4,%5,%6,%7}, {%8,%9}, {%0,%1,%2,%3};"
        : "+f"(c[0]), "+f"(c[1]), "+f"(c[2]), "+f"(c[3])
        : "r"(a0), "r"(a1), "r"(a2), "r"(a3), "r"(b0), "r"(b1));
}

// ======================================================================
// tf32 mma GEMM: C[M,N] = A[M,K] @ W[N,K]^T, M=8192, N=K=1024
// CTA tile 128x128, 8 warps (2m x 4n), warp tile 64x32, K-chunk 32.
// Explicit m16n8k8 mma, hoisted smem addressing, double-buffered smem.
// ======================================================================
#define GBM 128
#define GBN 128
#define GBK 32
#define LDSW 36
#define TILE_FLOATS (GBM * LDSW)      // 4608
#define NCHUNK (DM / GBK)             // 32
#define SM_FLOATS (4 * TILE_FLOATS)   // 18432 floats = 73728 B

__global__ __launch_bounds__(256)
void gemm_tf32(const float* __restrict__ A,
               const float* __restrict__ W,
               float* __restrict__ C) {
    extern __shared__ float smem[];
    float* Abuf[2] = { smem,                 smem + TILE_FLOATS };
    float* Wbuf[2] = { smem + 2*TILE_FLOATS, smem + 3*TILE_FLOATS };

    const int tid  = threadIdx.x;
    const int wid  = tid >> 5;
    const int lane = tid & 31;
    const int bm = blockIdx.y * GBM;
    const int bn = blockIdx.x * GBN;
    const int wm = wid >> 2;          // 0..1  (64-row slab)
    const int wn = wid & 3;           // 0..3  (32-col slab)
    const int g   = lane >> 2;        // 0..7
    const int tig = lane & 3;         // 0..3

    // fill mapping: row = tid>>1 (0..127), cbase = (tid&1)*16
    const int row   = tid >> 1;
    const int cbase = (tid & 1) * 16;
    const float* Ap = A + (size_t)(bm + row) * DM + cbase;
    const float* Wp = W + (size_t)(bn + row) * DM + cbase;
    const int sdst = row * LDSW + cbase;

    float acc[4][4][4];
#pragma unroll
    for (int i = 0; i < 4; i++)
#pragma unroll
        for (int j = 0; j < 4; j++)
#pragma unroll
            for (int r2 = 0; r2 < 4; r2++) acc[i][j][r2] = 0.f;

    float4 ra[4], rw[4];

    // prologue: chunk 0
#pragma unroll
    for (int i = 0; i < 4; i++) {
        ra[i] = *reinterpret_cast<const float4*>(Ap + i * 4);
        rw[i] = *reinterpret_cast<const float4*>(Wp + i * 4);
    }
#pragma unroll
    for (int i = 0; i < 4; i++) {
        uint4 ca = make_uint4(f32_to_tf32_rna_u(ra[i].x), f32_to_tf32_rna_u(ra[i].y),
                              f32_to_tf32_rna_u(ra[i].z), f32_to_tf32_rna_u(ra[i].w));
        uint4 cw = make_uint4(f32_to_tf32_rna_u(rw[i].x), f32_to_tf32_rna_u(rw[i].y),
                              f32_to_tf32_rna_u(rw[i].z), f32_to_tf32_rna_u(rw[i].w));
        *reinterpret_cast<uint4*>(Abuf[0] + sdst + i * 4) = ca;
        *reinterpret_cast<uint4*>(Wbuf[0] + sdst + i * 4) = cw;
    }
    __syncthreads();

    // per-warp hoisted smem fragment bases
    const int aoff = (wm * 64 + g) * LDSW + tig;
    const int boff = (wn * 32 + g) * LDSW + tig;

    for (int kt = 0; kt < NCHUNK; kt++) {
        const int cur = kt & 1;
        const int nxt = cur ^ 1;

        if (kt + 1 < NCHUNK) {
            const float* ap = Ap + (kt + 1) * GBK;
            const float* wp = Wp + (kt + 1) * GBK;
#pragma unroll
            for (int i = 0; i < 4; i++) {
                ra[i] = *reinterpret_cast<const float4*>(ap + i * 4);
                rw[i] = *reinterpret_cast<const float4*>(wp + i * 4);
            }
        }

        const float* aB = Abuf[cur] + aoff;
        const float* bB = Wbuf[cur] + boff;
#pragma unroll
        for (int ks = 0; ks < 4; ks++) {
            uint32_t af[4][4];
#pragma unroll
            for (int mt = 0; mt < 4; mt++) {
                const float* p = aB + mt * (16 * LDSW) + ks * 8;
                af[mt][0] = __float_as_uint(p[0]);
                af[mt][1] = __float_as_uint(p[8 * LDSW]);
                af[mt][2] = __float_as_uint(p[4]);
                af[mt][3] = __float_as_uint(p[8 * LDSW + 4]);
            }
            uint32_t bf[4][2];
#pragma unroll
            for (int nt = 0; nt < 4; nt++) {
                const float* p = bB + nt * (8 * LDSW) + ks * 8;
                bf[nt][0] = __float_as_uint(p[0]);
                bf[nt][1] = __float_as_uint(p[4]);
            }
#pragma unroll
            for (int mt = 0; mt < 4; mt++)
#pragma unroll
                for (int nt = 0; nt < 4; nt++)
                    mma_tf32(acc[mt][nt], af[mt][0], af[mt][1], af[mt][2], af[mt][3],
                             bf[nt][0], bf[nt][1]);
        }

        if (kt + 1 < NCHUNK) {
#pragma unroll
            for (int i = 0; i < 4; i++) {
                uint4 ca = make_uint4(f32_to_tf32_rna_u(ra[i].x), f32_to_tf32_rna_u(ra[i].y),
                                      f32_to_tf32_rna_u(ra[i].z), f32_to_tf32_rna_u(ra[i].w));
                uint4 cw = make_uint4(f32_to_tf32_rna_u(rw[i].x), f32_to_tf32_rna_u(rw[i].y),
                                      f32_to_tf32_rna_u(rw[i].z), f32_to_tf32_rna_u(rw[i].w));
                *reinterpret_cast<uint4*>(Abuf[nxt] + sdst + i * 4) = ca;
                *reinterpret_cast<uint4*>(Wbuf[nxt] + sdst + i * 4) = cw;
            }
        }
        __syncthreads();
    }

    // epilogue: c0,c1 at (row g, cols 2tig,2tig+1); c2,c3 at row g+8
    const int m0 = bm + wm * 64 + g;
    const int n0 = bn + wn * 32 + 2 * tig;
#pragma unroll
    for (int mt = 0; mt < 4; mt++) {
#pragma unroll
        for (int nt = 0; nt < 4; nt++) {
            float* p0 = C + (size_t)(m0 + mt * 16) * DM + n0 + nt * 8;
            float* p1 = p0 + 8 * DM;
            *reinterpret_cast<float2*>(p0) = make_float2(acc[mt][nt][0], acc[mt][nt][1]);
            *reinterpret_cast<float2*>(p1) = make_float2(acc[mt][nt][2], acc[mt][nt][3]);
        }
    }
}

// ---------------- RoPE on q and k in place ----------------
__global__ void rope_kernel(float* __restrict__ q, float* __restrict__ k,
                            const int* __restrict__ pos) {
    int idx = blockIdx.x * blockDim.x + threadIdx.x;
    const int total = MTOK * (DM / 2);
    if (idx >= total) return;
    int tok  = idx >> 9;
    int pr   = idx & 511;
    int col  = pr * 2;
    int d0   = col & (DK - 1);
    float p  = (float)pos[tok];
    const float ln_theta = 9.210340371976184f;
    float inv_freq = __expf(-(float)d0 * (ln_theta / (float)DK));
    float ang = p * inv_freq;
    float s, c;
    sincosf(ang, &s, &c);
    size_t off = (size_t)tok * DM + col;
    float2 qv = *reinterpret_cast<float2*>(q + off);
    float2 kv = *reinterpret_cast<float2*>(k + off);
    float2 qo = make_float2(qv.x * c - qv.y * s, qv.x * s + qv.y * c);
    float2 ko = make_float2(kv.x * c - kv.y * s, kv.x * s + kv.y * c);
    *reinterpret_cast<float2*>(q + off) = qo;
    *reinterpret_cast<float2*>(k + off) = ko;
}

// ---------------- causal flash attention ----------------
// 128 q-rows per block, 1 thread per row, KBL=32 key tile.
#define QB 128
#define KBL 32
#define KSW (DK + 4)   // 68 floats: float4-aligned rows

__global__ __launch_bounds__(QB)
void flash_kernel(const float* __restrict__ q,
                  const float* __restrict__ k,
                  const float* __restrict__ v,
                  float* __restrict__ o) {
    __shared__ float ks[KBL][KSW];
    __shared__ float vs[KBL][KSW];
    __shared__ float ps[QB][KBL + 1];

    const int t  = threadIdx.x;
    const int qb = gridDim.x - 1 - blockIdx.x;   // heavy tiles first
    const int h  = blockIdx.y;
    const int b  = blockIdx.z;
    const int q0 = qb * QB;
    const size_t tokBase = (size_t)b * SD;

    const float* qrow = q + (tokBase + q0 + t) * DM + h * DK;
    float qr[DK];
#pragma unroll
    for (int i = 0; i < DK / 4; i++) {
        float4 t4 = *reinterpret_cast<const float4*>(qrow + i * 4);
        qr[i*4+0] = t4.x * 0.125f; qr[i*4+1] = t4.y * 0.125f;
        qr[i*4+2] = t4.z * 0.125f; qr[i*4+3] = t4.w * 0.125f;
    }

    float m = -1e30f, l = 0.f;
    float out[DK];
#pragma unroll
    for (int d = 0; d < DK; d++) out[d] = 0.f;

    const int ntiles = (q0 + QB) / KBL;
    for (int kt = 0; kt < ntiles; kt++) {
        const int k0 = kt * KBL;
        __syncthreads();
        const float* kbase = k + (tokBase + k0) * DM + h * DK;
        const float* vbase = v + (tokBase + k0) * DM + h * DK;
        // 32 rows x 64 cols, 128 threads -> 16 elems each, coalesced
#pragma unroll
        for (int i = 0; i < 16; i++) {
            int idx = t + QB * i;
            int r = idx >> 6, c = idx & 63;
            ks[r][c] = kbase[(size_t)r * DM + c];
            vs[r][c] = vbase[(size_t)r * DM + c];
        }
        __syncthreads();

        // pass 1: scores + tile max
        float tmax = -1e30f;
#pragma unroll 4
        for (int j = 0; j < KBL; j++) {
            float ax = 0.f, ay = 0.f, az = 0.f, aw = 0.f;
#pragma unroll
            for (int c = 0; c < DK / 4; c++) {
                float4 kv = *reinterpret_cast<const float4*>(&ks[j][c * 4]);
                ax += qr[c*4+0] * kv.x;
                ay += qr[c*4+1] * kv.y;
                az += qr[c*4+2] * kv.z;
                aw += qr[c*4+3] * kv.w;
            }
            float s = (ax + ay) + (az + aw);
            if (k0 + j > q0 + t) s = -1e30f;
            ps[t][j] = s;
            tmax = fmaxf(tmax, s);
        }

        float mnew  = fmaxf(m, tmax);
        float alpha = __expf(m - mnew);
        m = mnew;
        l *= alpha;
#pragma unroll
        for (int d = 0; d < DK; d++) out[d] *= alpha;

        // pass 2: P @ V
#pragma unroll 4
        for (int j = 0; j < KBL; j++) {
            float p = __expf(ps[t][j] - mnew);
            l += p;
#pragma unroll
            for (int c = 0; c < DK / 4; c++) {
                float4 vv = *reinterpret_cast<const float4*>(&vs[j][c * 4]);
                out[c*4+0] += p * vv.x;
                out[c*4+1] += p * vv.y;
                out[c*4+2] += p * vv.z;
                out[c*4+3] += p * vv.w;
            }
        }
    }

    float inv = 1.0f / l;
    float* optr = o + (tokBase + q0 + t) * DM + h * DK;
#pragma unroll
    for (int i = 0; i < DK / 4; i++) {
        *reinterpret_cast<float4*>(optr + i * 4) =
            make_float4(out[i*4+0]*inv, out[i*4+1]*inv, out[i*4+2]*inv, out[i*4+3]*inv);
    }
}

// ---------------- launch ----------------
extern "C" void kernel_launch(void* const* d_in, const int* in_sizes, int n_in,
                              void* d_out, int out_size) {
    const float* x  = (const float*)d_in[0];
    const int*   tp = (const int*)  d_in[1];
    const float* Qw = (const float*)d_in[2];
    const float* Kw = (const float*)d_in[3];
    const float* Vw = (const float*)d_in[4];
    const float* Ow = (const float*)d_in[5];
    float* out = (float*)d_out;

    float *gq, *gk, *gv, *gao;
    cudaGetSymbolAddress((void**)&gq,  g_q);
    cudaGetSymbolAddress((void**)&gk,  g_k);
    cudaGetSymbolAddress((void**)&gv,  g_v);
    cudaGetSymbolAddress((void**)&gao, g_ao);

    const int smem_bytes = SM_FLOATS * 4;   // 73728
    cudaFuncSetAttribute(gemm_tf32, cudaFuncAttributeMaxDynamicSharedMemorySize, smem_bytes);

    dim3 ggrid(DM / GBN, MTOK / GBM);   // (8, 64)
    gemm_tf32<<<ggrid, 256, smem_bytes>>>(x, Qw, gq);
    gemm_tf32<<<ggrid, 256, smem_bytes>>>(x, Kw, gk);
    gemm_tf32<<<ggrid, 256, smem_bytes>>>(x, Vw, gv);

    int rope_total  = MTOK * (DM / 2);
    int rope_blocks = (rope_total + 255) / 256;
    rope_kernel<<<rope_blocks, 256>>>(gq, gk, tp);

    dim3 fgrid(SD / QB, NH, BD);        // (16, 16, 4)
    flash_kernel<<<fgrid, QB>>>(gq, gk, gv, gao);

    gemm_tf32<<<ggrid, 256, smem_bytes>>>(gao, Ow, out);
}

// round 5
// speedup vs baseline: 3.7462x; 1.7836x over previous
#include <cuda_runtime.h>
#include <math.h>
#include <stdint.h>

// Problem constants
#define BD 4
#define SD 2048
#define DM 1024
#define NH 16
#define DK 64
#define MTOK (BD*SD)   // 8192 tokens

// ---------------- scratch (static device memory: allowed) ----------------
__device__ float g_q [(size_t)MTOK * DM];
__device__ float g_k [(size_t)MTOK * DM];
__device__ float g_v [(size_t)MTOK * DM];
__device__ float g_ao[(size_t)MTOK * DM];

__device__ __forceinline__ uint32_t f32_to_tf32_rna_u(float f) {
    uint32_t r;
    asm("cvt.rna.tf32.f32 %0, %1;" : "=r"(r) : "f"(f));
    return r;
}

__device__ __forceinline__ void mma_tf32(float* c, uint32_t a0, uint32_t a1,
                                         uint32_t a2, uint32_t a3,
                                         uint32_t b0, uint32_t b1) {
    asm volatile(
        "mma.sync.aligned.m16n8k8.row.col.f32.tf32.tf32.f32 "
        "{%0,%1,%2,%3}, {%4,%5,%6,%7}, {%8,%9}, {%0,%1,%2,%3};"
        : "+f"(c[0]), "+f"(c[1]), "+f"(c[2]), "+f"(c[3])
        : "r"(a0), "r"(a1), "r"(a2), "r"(a3), "r"(b0), "r"(b1));
}

// ======================================================================
// tf32 mma GEMM: C[M,N] = A[M,K] @ W[N,K]^T, M=8192, N=K=1024
// ======================================================================
#define GBM 128
#define GBN 128
#define GBK 32
#define LDSW 36
#define TILE_FLOATS (GBM * LDSW)      // 4608
#define NCHUNK (DM / GBK)             // 32
#define SM_FLOATS (4 * TILE_FLOATS)   // 18432 floats = 73728 B

__global__ __launch_bounds__(256)
void gemm_tf32(const float* __restrict__ A,
               const float* __restrict__ W,
               float* __restrict__ C) {
    extern __shared__ float smem[];
    float* Abuf[2] = { smem,                 smem + TILE_FLOATS };
    float* Wbuf[2] = { smem + 2*TILE_FLOATS, smem + 3*TILE_FLOATS };

    const int tid  = threadIdx.x;
    const int wid  = tid >> 5;
    const int lane = tid & 31;
    const int bm = blockIdx.y * GBM;
    const int bn = blockIdx.x * GBN;
    const int wm = wid >> 2;
    const int wn = wid & 3;
    const int g   = lane >> 2;
    const int tig = lane & 3;

    const int row   = tid >> 1;
    const int cbase = (tid & 1) * 16;
    const float* Ap = A + (size_t)(bm + row) * DM + cbase;
    const float* Wp = W + (size_t)(bn + row) * DM + cbase;
    const int sdst = row * LDSW + cbase;

    float acc[4][4][4];
#pragma unroll
    for (int i = 0; i < 4; i++)
#pragma unroll
        for (int j = 0; j < 4; j++)
#pragma unroll
            for (int r2 = 0; r2 < 4; r2++) acc[i][j][r2] = 0.f;

    float4 ra[4], rw[4];

#pragma unroll
    for (int i = 0; i < 4; i++) {
        ra[i] = *reinterpret_cast<const float4*>(Ap + i * 4);
        rw[i] = *reinterpret_cast<const float4*>(Wp + i * 4);
    }
#pragma unroll
    for (int i = 0; i < 4; i++) {
        uint4 ca = make_uint4(f32_to_tf32_rna_u(ra[i].x), f32_to_tf32_rna_u(ra[i].y),
                              f32_to_tf32_rna_u(ra[i].z), f32_to_tf32_rna_u(ra[i].w));
        uint4 cw = make_uint4(f32_to_tf32_rna_u(rw[i].x), f32_to_tf32_rna_u(rw[i].y),
                              f32_to_tf32_rna_u(rw[i].z), f32_to_tf32_rna_u(rw[i].w));
        *reinterpret_cast<uint4*>(Abuf[0] + sdst + i * 4) = ca;
        *reinterpret_cast<uint4*>(Wbuf[0] + sdst + i * 4) = cw;
    }
    __syncthreads();

    const int aoff = (wm * 64 + g) * LDSW + tig;
    const int boff = (wn * 32 + g) * LDSW + tig;

    for (int kt = 0; kt < NCHUNK; kt++) {
        const int cur = kt & 1;
        const int nxt = cur ^ 1;

        if (kt + 1 < NCHUNK) {
            const float* ap = Ap + (kt + 1) * GBK;
            const float* wp = Wp + (kt + 1) * GBK;
#pragma unroll
            for (int i = 0; i < 4; i++) {
                ra[i] = *reinterpret_cast<const float4*>(ap + i * 4);
                rw[i] = *reinterpret_cast<const float4*>(wp + i * 4);
            }
        }

        const float* aB = Abuf[cur] + aoff;
        const float* bB = Wbuf[cur] + boff;
#pragma unroll
        for (int ks = 0; ks < 4; ks++) {
            uint32_t af[4][4];
#pragma unroll
            for (int mt = 0; mt < 4; mt++) {
                const float* p = aB + mt * (16 * LDSW) + ks * 8;
                af[mt][0] = __float_as_uint(p[0]);
                af[mt][1] = __float_as_uint(p[8 * LDSW]);
                af[mt][2] = __float_as_uint(p[4]);
                af[mt][3] = __float_as_uint(p[8 * LDSW + 4]);
            }
            uint32_t bf[4][2];
#pragma unroll
            for (int nt = 0; nt < 4; nt++) {
                const float* p = bB + nt * (8 * LDSW) + ks * 8;
                bf[nt][0] = __float_as_uint(p[0]);
                bf[nt][1] = __float_as_uint(p[4]);
            }
#pragma unroll
            for (int mt = 0; mt < 4; mt++)
#pragma unroll
                for (int nt = 0; nt < 4; nt++)
                    mma_tf32(acc[mt][nt], af[mt][0], af[mt][1], af[mt][2], af[mt][3],
                             bf[nt][0], bf[nt][1]);
        }

        if (kt + 1 < NCHUNK) {
#pragma unroll
            for (int i = 0; i < 4; i++) {
                uint4 ca = make_uint4(f32_to_tf32_rna_u(ra[i].x), f32_to_tf32_rna_u(ra[i].y),
                                      f32_to_tf32_rna_u(ra[i].z), f32_to_tf32_rna_u(ra[i].w));
                uint4 cw = make_uint4(f32_to_tf32_rna_u(rw[i].x), f32_to_tf32_rna_u(rw[i].y),
                                      f32_to_tf32_rna_u(rw[i].z), f32_to_tf32_rna_u(rw[i].w));
                *reinterpret_cast<uint4*>(Abuf[nxt] + sdst + i * 4) = ca;
                *reinterpret_cast<uint4*>(Wbuf[nxt] + sdst + i * 4) = cw;
            }
        }
        __syncthreads();
    }

    const int m0 = bm + wm * 64 + g;
    const int n0 = bn + wn * 32 + 2 * tig;
#pragma unroll
    for (int mt = 0; mt < 4; mt++) {
#pragma unroll
        for (int nt = 0; nt < 4; nt++) {
            float* p0 = C + (size_t)(m0 + mt * 16) * DM + n0 + nt * 8;
            float* p1 = p0 + 8 * DM;
            *reinterpret_cast<float2*>(p0) = make_float2(acc[mt][nt][0], acc[mt][nt][1]);
            *reinterpret_cast<float2*>(p1) = make_float2(acc[mt][nt][2], acc[mt][nt][3]);
        }
    }
}

// ---------------- RoPE on q and k in place ----------------
__global__ void rope_kernel(float* __restrict__ q, float* __restrict__ k,
                            const int* __restrict__ pos) {
    int idx = blockIdx.x * blockDim.x + threadIdx.x;
    const int total = MTOK * (DM / 2);
    if (idx >= total) return;
    int tok  = idx >> 9;
    int pr   = idx & 511;
    int col  = pr * 2;
    int d0   = col & (DK - 1);
    float p  = (float)pos[tok];
    const float ln_theta = 9.210340371976184f;
    float inv_freq = __expf(-(float)d0 * (ln_theta / (float)DK));
    float ang = p * inv_freq;
    float s, c;
    sincosf(ang, &s, &c);
    size_t off = (size_t)tok * DM + col;
    float2 qv = *reinterpret_cast<float2*>(q + off);
    float2 kv = *reinterpret_cast<float2*>(k + off);
    float2 qo = make_float2(qv.x * c - qv.y * s, qv.x * s + qv.y * c);
    float2 ko = make_float2(kv.x * c - kv.y * s, kv.x * s + kv.y * c);
    *reinterpret_cast<float2*>(q + off) = qo;
    *reinterpret_cast<float2*>(k + off) = ko;
}

// ======================================================================
// mma-based causal flash attention
// CTA: 64 q-rows of one (b,h); 4 warps, 16 rows each; key tile 64.
// QK^T and P·V via m16n8k8 tf32 mma; online softmax in registers.
// ======================================================================
#define FQT 64
#define FKT 64
#define KS_STRIDE 68   // (68 mod 32 == 4): rows spread by g -> conflict-free
#define VS_STRIDE 65   // (8*65 mod 32 == 8): rows spread by tig -> conflict-free
#define PS_STRIDE 68
#define FS_KS 0
#define FS_VS (64 * KS_STRIDE)
#define FS_PS (FS_VS + 64 * VS_STRIDE)
#define FS_TOTAL (FS_PS + 64 * PS_STRIDE)   // 12864 floats = 51456 B

__global__ __launch_bounds__(128)
void flash_mma(const float* __restrict__ q,
               const float* __restrict__ k,
               const float* __restrict__ v,
               float* __restrict__ o) {
    extern __shared__ float fsm[];
    float* ks_ = fsm + FS_KS;
    float* vs_ = fsm + FS_VS;
    float* ps_ = fsm + FS_PS;

    const int tid  = threadIdx.x;
    const int w    = tid >> 5;
    const int lane = tid & 31;
    const int g    = lane >> 2;
    const int tig  = lane & 3;
    const int qb = gridDim.x - 1 - blockIdx.x;   // heavy tiles first
    const int h  = blockIdx.y;
    const int b  = blockIdx.z;
    const int q0 = qb * FQT;
    const size_t tokBase = (size_t)b * SD;
    const int rb = w * 16;

    // ---- stage Q tile (scaled + tf32) through ps_, then load a-frags ----
    {
        const float* qbase = q + (tokBase + q0) * DM + h * DK;
#pragma unroll
        for (int i = 0; i < 16; i++) {
            int j = tid + 128 * i;        // 2048 float2 slots
            int r = j >> 5, c2 = j & 31;
            float2 t2 = *reinterpret_cast<const float2*>(qbase + (size_t)r * DM + 2 * c2);
            ps_[r * PS_STRIDE + 2*c2]     = __uint_as_float(f32_to_tf32_rna_u(t2.x * 0.125f));
            ps_[r * PS_STRIDE + 2*c2 + 1] = __uint_as_float(f32_to_tf32_rna_u(t2.y * 0.125f));
        }
    }
    __syncthreads();
    uint32_t qa[8][4];
#pragma unroll
    for (int ks8 = 0; ks8 < 8; ks8++) {
        const float* p = ps_ + (rb + g) * PS_STRIDE + ks8 * 8 + tig;
        qa[ks8][0] = __float_as_uint(p[0]);
        qa[ks8][1] = __float_as_uint(p[8 * PS_STRIDE]);
        qa[ks8][2] = __float_as_uint(p[4]);
        qa[ks8][3] = __float_as_uint(p[8 * PS_STRIDE + 4]);
    }

    float m0 = -1e30f, m1 = -1e30f, l0 = 0.f, l1 = 0.f;
    float oacc[8][4];
#pragma unroll
    for (int n = 0; n < 8; n++)
#pragma unroll
        for (int c = 0; c < 4; c++) oacc[n][c] = 0.f;

    const int ntiles = q0 / FKT + 1;
    for (int kt = 0; kt < ntiles; kt++) {
        const int k0 = kt * FKT;
        __syncthreads();
        const float* kbase = k + (tokBase + k0) * DM + h * DK;
        const float* vbase = v + (tokBase + k0) * DM + h * DK;
#pragma unroll
        for (int i = 0; i < 16; i++) {
            int j = tid + 128 * i;
            int r = j >> 5, c2 = j & 31;
            float2 kk = *reinterpret_cast<const float2*>(kbase + (size_t)r * DM + 2 * c2);
            float2 vv = *reinterpret_cast<const float2*>(vbase + (size_t)r * DM + 2 * c2);
            ks_[r * KS_STRIDE + 2*c2]     = __uint_as_float(f32_to_tf32_rna_u(kk.x));
            ks_[r * KS_STRIDE + 2*c2 + 1] = __uint_as_float(f32_to_tf32_rna_u(kk.y));
            vs_[r * VS_STRIDE + 2*c2]     = __uint_as_float(f32_to_tf32_rna_u(vv.x));
            vs_[r * VS_STRIDE + 2*c2 + 1] = __uint_as_float(f32_to_tf32_rna_u(vv.y));
        }
        __syncthreads();

        // ---- QK^T: sacc[n] = Q(16xDK) . K^T, n over 8 key sub-tiles ----
        float sacc[8][4];
#pragma unroll
        for (int n = 0; n < 8; n++)
#pragma unroll
            for (int c = 0; c < 4; c++) sacc[n][c] = 0.f;
#pragma unroll
        for (int ks8 = 0; ks8 < 8; ks8++) {
#pragma unroll
            for (int n = 0; n < 8; n++) {
                const float* kp = ks_ + (n * 8 + g) * KS_STRIDE + ks8 * 8 + tig;
                mma_tf32(sacc[n], qa[ks8][0], qa[ks8][1], qa[ks8][2], qa[ks8][3],
                         __float_as_uint(kp[0]), __float_as_uint(kp[4]));
            }
        }

        // ---- causal mask on diagonal tile ----
        if (k0 == q0) {
            const int row0 = q0 + rb + g;
            const int row1 = row0 + 8;
#pragma unroll
            for (int n = 0; n < 8; n++) {
                int col = k0 + n * 8 + 2 * tig;
                if (col     > row0) sacc[n][0] = -1e30f;
                if (col + 1 > row0) sacc[n][1] = -1e30f;
                if (col     > row1) sacc[n][2] = -1e30f;
                if (col + 1 > row1) sacc[n][3] = -1e30f;
            }
        }

        // ---- online softmax (rows g and g+8) ----
        float mx0 = -1e30f, mx1 = -1e30f;
#pragma unroll
        for (int n = 0; n < 8; n++) {
            mx0 = fmaxf(mx0, fmaxf(sacc[n][0], sacc[n][1]));
            mx1 = fmaxf(mx1, fmaxf(sacc[n][2], sacc[n][3]));
        }
        mx0 = fmaxf(mx0, __shfl_xor_sync(0xffffffffu, mx0, 1));
        mx0 = fmaxf(mx0, __shfl_xor_sync(0xffffffffu, mx0, 2));
        mx1 = fmaxf(mx1, __shfl_xor_sync(0xffffffffu, mx1, 1));
        mx1 = fmaxf(mx1, __shfl_xor_sync(0xffffffffu, mx1, 2));

        float mn0 = fmaxf(m0, mx0), mn1 = fmaxf(m1, mx1);
        float al0 = __expf(m0 - mn0), al1 = __expf(m1 - mn1);
        m0 = mn0; m1 = mn1;
        l0 *= al0; l1 *= al1;

        float* ps0 = ps_ + (rb + g) * PS_STRIDE + 2 * tig;
        float* ps1 = ps0 + 8 * PS_STRIDE;
#pragma unroll
        for (int n = 0; n < 8; n++) {
            float p0 = __expf(sacc[n][0] - mn0);
            float p1 = __expf(sacc[n][1] - mn0);
            float p2 = __expf(sacc[n][2] - mn1);
            float p3 = __expf(sacc[n][3] - mn1);
            l0 += p0 + p1;
            l1 += p2 + p3;
            uint2 u01 = make_uint2(f32_to_tf32_rna_u(p0), f32_to_tf32_rna_u(p1));
            uint2 u23 = make_uint2(f32_to_tf32_rna_u(p2), f32_to_tf32_rna_u(p3));
            *reinterpret_cast<uint2*>(ps0 + n * 8) = u01;
            *reinterpret_cast<uint2*>(ps1 + n * 8) = u23;
            oacc[n][0] *= al0; oacc[n][1] *= al0;
            oacc[n][2] *= al1; oacc[n][3] *= al1;
        }
        __syncwarp();

        // ---- P . V : oacc[n] += P(16x64) . V(64x8n) ----
#pragma unroll
        for (int ks8 = 0; ks8 < 8; ks8++) {
            const float* pp = ps_ + (rb + g) * PS_STRIDE + ks8 * 8 + tig;
            uint32_t pa0 = __float_as_uint(pp[0]);
            uint32_t pa1 = __float_as_uint(pp[8 * PS_STRIDE]);
            uint32_t pa2 = __float_as_uint(pp[4]);
            uint32_t pa3 = __float_as_uint(pp[8 * PS_STRIDE + 4]);
#pragma unroll
            for (int n = 0; n < 8; n++) {
                const float* vp = vs_ + (ks8 * 8 + tig) * VS_STRIDE + n * 8 + g;
                mma_tf32(oacc[n], pa0, pa1, pa2, pa3,
                         __float_as_uint(vp[0]), __float_as_uint(vp[4 * VS_STRIDE]));
            }
        }
    }

    // ---- epilogue ----
    l0 += __shfl_xor_sync(0xffffffffu, l0, 1);
    l0 += __shfl_xor_sync(0xffffffffu, l0, 2);
    l1 += __shfl_xor_sync(0xffffffffu, l1, 1);
    l1 += __shfl_xor_sync(0xffffffffu, l1, 2);
    float inv0 = 1.f / l0, inv1 = 1.f / l1;

    float* o0 = o + (tokBase + q0 + rb + g) * DM + h * DK + 2 * tig;
    float* o1 = o0 + 8 * DM;
#pragma unroll
    for (int n = 0; n < 8; n++) {
        *reinterpret_cast<float2*>(o0 + n * 8) = make_float2(oacc[n][0] * inv0, oacc[n][1] * inv0);
        *reinterpret_cast<float2*>(o1 + n * 8) = make_float2(oacc[n][2] * inv1, oacc[n][3] * inv1);
    }
}

// ---------------- launch ----------------
extern "C" void kernel_launch(void* const* d_in, const int* in_sizes, int n_in,
                              void* d_out, int out_size) {
    const float* x  = (const float*)d_in[0];
    const int*   tp = (const int*)  d_in[1];
    const float* Qw = (const float*)d_in[2];
    const float* Kw = (const float*)d_in[3];
    const float* Vw = (const float*)d_in[4];
    const float* Ow = (const float*)d_in[5];
    float* out = (float*)d_out;

    float *gq, *gk, *gv, *gao;
    cudaGetSymbolAddress((void**)&gq,  g_q);
    cudaGetSymbolAddress((void**)&gk,  g_k);
    cudaGetSymbolAddress((void**)&gv,  g_v);
    cudaGetSymbolAddress((void**)&gao, g_ao);

    const int gemm_smem = SM_FLOATS * 4;    // 73728
    cudaFuncSetAttribute(gemm_tf32, cudaFuncAttributeMaxDynamicSharedMemorySize, gemm_smem);
    const int flash_smem = FS_TOTAL * 4;    // 51456
    cudaFuncSetAttribute(flash_mma, cudaFuncAttributeMaxDynamicSharedMemorySize, flash_smem);

    dim3 ggrid(DM / GBN, MTOK / GBM);   // (8, 64)
    gemm_tf32<<<ggrid, 256, gemm_smem>>>(x, Qw, gq);
    gemm_tf32<<<ggrid, 256, gemm_smem>>>(x, Kw, gk);
    gemm_tf32<<<ggrid, 256, gemm_smem>>>(x, Vw, gv);

    int rope_total  = MTOK * (DM / 2);
    int rope_blocks = (rope_total + 255) / 256;
    rope_kernel<<<rope_blocks, 256>>>(gq, gk, tp);

    dim3 fgrid(SD / FQT, NH, BD);       // (32, 16, 4)
    flash_mma<<<fgrid, 128, flash_smem>>>(gq, gk, gv, gao);

    gemm_tf32<<<ggrid, 256, gemm_smem>>>(gao, Ow, out);
}

// round 7
// speedup vs baseline: 3.7615x; 1.0041x over previous
#include <cuda_runtime.h>
#include <math.h>
#include <stdint.h>

// Problem constants
#define BD 4
#define SD 2048
#define DM 1024
#define NH 16
#define DK 64
#define MTOK (BD*SD)   // 8192 tokens

// ---------------- scratch (static device memory: allowed) ----------------
__device__ float g_q [(size_t)MTOK * DM];
__device__ float g_k [(size_t)MTOK * DM];
__device__ float g_v [(size_t)MTOK * DM];
__device__ float g_ao[(size_t)MTOK * DM];
__device__ float g_xc[(size_t)MTOK * DM];          // x pre-rounded to tf32
__device__ float g_wc[(size_t)4 * DM * DM];        // Qw,Kw,Vw,Ow pre-rounded

__device__ __forceinline__ uint32_t f32_to_tf32_rna_u(float f) {
    uint32_t r;
    asm("cvt.rna.tf32.f32 %0, %1;" : "=r"(r) : "f"(f));
    return r;
}

__device__ __forceinline__ uint32_t smem_u32(const void* p) {
    uint32_t a;
    asm("{ .reg .u64 t; cvta.to.shared.u64 t, %1; cvt.u32.u64 %0, t; }" : "=r"(a) : "l"(p));
    return a;
}

__device__ __forceinline__ void cp_async16(uint32_t dst, const void* src) {
    asm volatile("cp.async.cg.shared.global [%0], [%1], 16;" :: "r"(dst), "l"(src));
}
#define CP_COMMIT() asm volatile("cp.async.commit_group;" ::: "memory")
#define CP_WAIT1()  asm volatile("cp.async.wait_group 1;" ::: "memory")

__device__ __forceinline__ void mma_tf32(float* c, uint32_t a0, uint32_t a1,
                                         uint32_t a2, uint32_t a3,
                                         uint32_t b0, uint32_t b1) {
    asm volatile(
        "mma.sync.aligned.m16n8k8.row.col.f32.tf32.tf32.f32 "
        "{%0,%1,%2,%3}, {%4,%5,%6,%7}, {%8,%9}, {%0,%1,%2,%3};"
        : "+f"(c[0]), "+f"(c[1]), "+f"(c[2]), "+f"(c[3])
        : "r"(a0), "r"(a1), "r"(a2), "r"(a3), "r"(b0), "r"(b1));
}

// ---------------- one-time tf32 rounding pass ----------------
__global__ void cvt_tf32_kernel(const float* __restrict__ src,
                                float* __restrict__ dst, int n4) {
    int i = blockIdx.x * blockDim.x + threadIdx.x;
    if (i >= n4) return;
    float4 v = reinterpret_cast<const float4*>(src)[i];
    uint4 u = make_uint4(f32_to_tf32_rna_u(v.x), f32_to_tf32_rna_u(v.y),
                         f32_to_tf32_rna_u(v.z), f32_to_tf32_rna_u(v.w));
    reinterpret_cast<uint4*>(dst)[i] = u;
}

// ======================================================================
// tf32 mma GEMM on pre-rounded inputs: C[M,N] = A[M,K] @ W[N,K]^T
// CTA tile 128x128, 8 warps, warp tile 64x32, K-chunk 32,
// 3-stage cp.async pipeline, no cvt in the hot loop.
// ======================================================================
#define GBM 128
#define GBN 128
#define GBK 32
#define LDSW 36
#define TILE_FLOATS (GBM * LDSW)          // 4608
#define NCHUNK (DM / GBK)                 // 32
#define STAGE_FLOATS (2 * TILE_FLOATS)    // A + W per stage
#define GEMM_SMEM_BYTES (3 * STAGE_FLOATS * 4)   // 110592

__global__ __launch_bounds__(256)
void gemm_tf32(const float* __restrict__ A,
               const float* __restrict__ W,
               float* __restrict__ C) {
    extern __shared__ float smem[];
    const uint32_t sbase = smem_u32(smem);

    const int tid  = threadIdx.x;
    const int wid  = tid >> 5;
    const int lane = tid & 31;
    const int bm = blockIdx.y * GBM;
    const int bn = blockIdx.x * GBN;
    const int wm = wid >> 2;
    const int wn = wid & 3;
    const int g   = lane >> 2;
    const int tig = lane & 3;

    const int row   = tid >> 1;
    const int cbase = (tid & 1) * 16;
    const float* Ap = A + (size_t)(bm + row) * DM + cbase;
    const float* Wp = W + (size_t)(bn + row) * DM + cbase;
    const uint32_t sdoff = (uint32_t)(row * LDSW + cbase) * 4u;

    float acc[4][4][4];
#pragma unroll
    for (int i = 0; i < 4; i++)
#pragma unroll
        for (int j = 0; j < 4; j++)
#pragma unroll
            for (int r2 = 0; r2 < 4; r2++) acc[i][j][r2] = 0.f;

    // prologue: stages 0 and 1 in flight
#pragma unroll
    for (int s = 0; s < 2; s++) {
        const uint32_t ab = sbase + (uint32_t)s * (STAGE_FLOATS * 4);
        const float* ap = Ap + s * GBK;
        const float* wp = Wp + s * GBK;
#pragma unroll
        for (int i = 0; i < 4; i++) {
            cp_async16(ab + sdoff + i * 16, ap + i * 4);
            cp_async16(ab + TILE_FLOATS * 4 + sdoff + i * 16, wp + i * 4);
        }
        CP_COMMIT();
    }

    const int aoff = (wm * 64 + g) * LDSW + tig;
    const int boff = (wn * 32 + g) * LDSW + tig;

    for (int kt = 0; kt < NCHUNK; kt++) {
        CP_WAIT1();            // stage kt resident (kt+1 may be in flight)
        __syncthreads();       // fills of stage kt visible; stage (kt+2)%3 free

        if (kt + 2 < NCHUNK) {
            const int s = (kt + 2) % 3;
            const uint32_t ab = sbase + (uint32_t)s * (STAGE_FLOATS * 4);
            const float* ap = Ap + (kt + 2) * GBK;
            const float* wp = Wp + (kt + 2) * GBK;
#pragma unroll
            for (int i = 0; i < 4; i++) {
                cp_async16(ab + sdoff + i * 16, ap + i * 4);
                cp_async16(ab + TILE_FLOATS * 4 + sdoff + i * 16, wp + i * 4);
            }
        }
        CP_COMMIT();

        const float* aB = smem + (kt % 3) * STAGE_FLOATS + aoff;
        const float* bB = smem + (kt % 3) * STAGE_FLOATS + TILE_FLOATS + boff;
#pragma unroll
        for (int ks = 0; ks < 4; ks++) {
            uint32_t af[4][4];
#pragma unroll
            for (int mt = 0; mt < 4; mt++) {
                const float* p = aB + mt * (16 * LDSW) + ks * 8;
                af[mt][0] = __float_as_uint(p[0]);
                af[mt][1] = __float_as_uint(p[8 * LDSW]);
                af[mt][2] = __float_as_uint(p[4]);
                af[mt][3] = __float_as_uint(p[8 * LDSW + 4]);
            }
            uint32_t bf[4][2];
#pragma unroll
            for (int nt = 0; nt < 4; nt++) {
                const float* p = bB + nt * (8 * LDSW) + ks * 8;
                bf[nt][0] = __float_as_uint(p[0]);
                bf[nt][1] = __float_as_uint(p[4]);
            }
#pragma unroll
            for (int mt = 0; mt < 4; mt++)
#pragma unroll
                for (int nt = 0; nt < 4; nt++)
                    mma_tf32(acc[mt][nt], af[mt][0], af[mt][1], af[mt][2], af[mt][3],
                             bf[nt][0], bf[nt][1]);
        }
    }

    const int m0 = bm + wm * 64 + g;
    const int n0 = bn + wn * 32 + 2 * tig;
#pragma unroll
    for (int mt = 0; mt < 4; mt++) {
#pragma unroll
        for (int nt = 0; nt < 4; nt++) {
            float* p0 = C + (size_t)(m0 + mt * 16) * DM + n0 + nt * 8;
            float* p1 = p0 + 8 * DM;
            *reinterpret_cast<float2*>(p0) = make_float2(acc[mt][nt][0], acc[mt][nt][1]);
            *reinterpret_cast<float2*>(p1) = make_float2(acc[mt][nt][2], acc[mt][nt][3]);
        }
    }
}

// ---------------- RoPE on q and k in place ----------------
__global__ void rope_kernel(float* __restrict__ q, float* __restrict__ k,
                            const int* __restrict__ pos) {
    int idx = blockIdx.x * blockDim.x + threadIdx.x;
    const int total = MTOK * (DM / 2);
    if (idx >= total) return;
    int tok  = idx >> 9;
    int pr   = idx & 511;
    int col  = pr * 2;
    int d0   = col & (DK - 1);
    float p  = (float)pos[tok];
    const float ln_theta = 9.210340371976184f;
    float inv_freq = __expf(-(float)d0 * (ln_theta / (float)DK));
    float ang = p * inv_freq;
    float s, c;
    sincosf(ang, &s, &c);
    size_t off = (size_t)tok * DM + col;
    float2 qv = *reinterpret_cast<float2*>(q + off);
    float2 kv = *reinterpret_cast<float2*>(k + off);
    float2 qo = make_float2(qv.x * c - qv.y * s, qv.x * s + qv.y * c);
    float2 ko = make_float2(kv.x * c - kv.y * s, kv.x * s + kv.y * c);
    *reinterpret_cast<float2*>(q + off) = qo;
    *reinterpret_cast<float2*>(k + off) = ko;
}

// ======================================================================
// mma-based causal flash attention; epilogue writes tf32-rounded
// ======================================================================
#define FQT 64
#define FKT 64
#define KS_STRIDE 68
#define VS_STRIDE 65
#define PS_STRIDE 68
#define FS_KS 0
#define FS_VS (64 * KS_STRIDE)
#define FS_PS (FS_VS + 64 * VS_STRIDE)
#define FS_TOTAL (FS_PS + 64 * PS_STRIDE)   // 12864 floats = 51456 B

__global__ __launch_bounds__(128)
void flash_mma(const float* __restrict__ q,
               const float* __restrict__ k,
               const float* __restrict__ v,
               float* __restrict__ o) {
    extern __shared__ float fsm[];
    float* ks_ = fsm + FS_KS;
    float* vs_ = fsm + FS_VS;
    float* ps_ = fsm + FS_PS;

    const int tid  = threadIdx.x;
    const int w    = tid >> 5;
    const int lane = tid & 31;
    const int g    = lane >> 2;
    const int tig  = lane & 3;
    const int qb = gridDim.x - 1 - blockIdx.x;
    const int h  = blockIdx.y;
    const int b  = blockIdx.z;
    const int q0 = qb * FQT;
    const size_t tokBase = (size_t)b * SD;
    const int rb = w * 16;

    {
        const float* qbase = q + (tokBase + q0) * DM + h * DK;
#pragma unroll
        for (int i = 0; i < 16; i++) {
            int j = tid + 128 * i;
            int r = j >> 5, c2 = j & 31;
            float2 t2 = *reinterpret_cast<const float2*>(qbase + (size_t)r * DM + 2 * c2);
            ps_[r * PS_STRIDE + 2*c2]     = __uint_as_float(f32_to_tf32_rna_u(t2.x * 0.125f));
            ps_[r * PS_STRIDE + 2*c2 + 1] = __uint_as_float(f32_to_tf32_rna_u(t2.y * 0.125f));
        }
    }
    __syncthreads();
    uint32_t qa[8][4];
#pragma unroll
    for (int ks8 = 0; ks8 < 8; ks8++) {
        const float* p = ps_ + (rb + g) * PS_STRIDE + ks8 * 8 + tig;
        qa[ks8][0] = __float_as_uint(p[0]);
        qa[ks8][1] = __float_as_uint(p[8 * PS_STRIDE]);
        qa[ks8][2] = __float_as_uint(p[4]);
        qa[ks8][3] = __float_as_uint(p[8 * PS_STRIDE + 4]);
    }

    float m0 = -1e30f, m1 = -1e30f, l0 = 0.f, l1 = 0.f;
    float oacc[8][4];
#pragma unroll
    for (int n = 0; n < 8; n++)
#pragma unroll
        for (int c = 0; c < 4; c++) oacc[n][c] = 0.f;

    const int ntiles = q0 / FKT + 1;
    for (int kt = 0; kt < ntiles; kt++) {
        const int k0 = kt * FKT;
        __syncthreads();
        const float* kbase = k + (tokBase + k0) * DM + h * DK;
        const float* vbase = v + (tokBase + k0) * DM + h * DK;
#pragma unroll
        for (int i = 0; i < 16; i++) {
            int j = tid + 128 * i;
            int r = j >> 5, c2 = j & 31;
            float2 kk = *reinterpret_cast<const float2*>(kbase + (size_t)r * DM + 2 * c2);
            float2 vv = *reinterpret_cast<const float2*>(vbase + (size_t)r * DM + 2 * c2);
            ks_[r * KS_STRIDE + 2*c2]     = __uint_as_float(f32_to_tf32_rna_u(kk.x));
            ks_[r * KS_STRIDE + 2*c2 + 1] = __uint_as_float(f32_to_tf32_rna_u(kk.y));
            vs_[r * VS_STRIDE + 2*c2]     = __uint_as_float(f32_to_tf32_rna_u(vv.x));
            vs_[r * VS_STRIDE + 2*c2 + 1] = __uint_as_float(f32_to_tf32_rna_u(vv.y));
        }
        __syncthreads();

        float sacc[8][4];
#pragma unroll
        for (int n = 0; n < 8; n++)
#pragma unroll
            for (int c = 0; c < 4; c++) sacc[n][c] = 0.f;
#pragma unroll
        for (int ks8 = 0; ks8 < 8; ks8++) {
#pragma unroll
            for (int n = 0; n < 8; n++) {
                const float* kp = ks_ + (n * 8 + g) * KS_STRIDE + ks8 * 8 + tig;
                mma_tf32(sacc[n], qa[ks8][0], qa[ks8][1], qa[ks8][2], qa[ks8][3],
                         __float_as_uint(kp[0]), __float_as_uint(kp[4]));
            }
        }

        if (k0 == q0) {
            const int row0 = q0 + rb + g;
            const int row1 = row0 + 8;
#pragma unroll
            for (int n = 0; n < 8; n++) {
                int col = k0 + n * 8 + 2 * tig;
                if (col     > row0) sacc[n][0] = -1e30f;
                if (col + 1 > row0) sacc[n][1] = -1e30f;
                if (col     > row1) sacc[n][2] = -1e30f;
                if (col + 1 > row1) sacc[n][3] = -1e30f;
            }
        }

        float mx0 = -1e30f, mx1 = -1e30f;
#pragma unroll
        for (int n = 0; n < 8; n++) {
            mx0 = fmaxf(mx0, fmaxf(sacc[n][0], sacc[n][1]));
            mx1 = fmaxf(mx1, fmaxf(sacc[n][2], sacc[n][3]));
        }
        mx0 = fmaxf(mx0, __shfl_xor_sync(0xffffffffu, mx0, 1));
        mx0 = fmaxf(mx0, __shfl_xor_sync(0xffffffffu, mx0, 2));
        mx1 = fmaxf(mx1, __shfl_xor_sync(0xffffffffu, mx1, 1));
        mx1 = fmaxf(mx1, __shfl_xor_sync(0xffffffffu, mx1, 2));

        float mn0 = fmaxf(m0, mx0), mn1 = fmaxf(m1, mx1);
        float al0 = __expf(m0 - mn0), al1 = __expf(m1 - mn1);
        m0 = mn0; m1 = mn1;
        l0 *= al0; l1 *= al1;

        float* ps0 = ps_ + (rb + g) * PS_STRIDE + 2 * tig;
        float* ps1 = ps0 + 8 * PS_STRIDE;
#pragma unroll
        for (int n = 0; n < 8; n++) {
            float p0 = __expf(sacc[n][0] - mn0);
            float p1 = __expf(sacc[n][1] - mn0);
            float p2 = __expf(sacc[n][2] - mn1);
            float p3 = __expf(sacc[n][3] - mn1);
            l0 += p0 + p1;
            l1 += p2 + p3;
            uint2 u01 = make_uint2(f32_to_tf32_rna_u(p0), f32_to_tf32_rna_u(p1));
            uint2 u23 = make_uint2(f32_to_tf32_rna_u(p2), f32_to_tf32_rna_u(p3));
            *reinterpret_cast<uint2*>(ps0 + n * 8) = u01;
            *reinterpret_cast<uint2*>(ps1 + n * 8) = u23;
            oacc[n][0] *= al0; oacc[n][1] *= al0;
            oacc[n][2] *= al1; oacc[n][3] *= al1;
        }
        __syncwarp();

#pragma unroll
        for (int ks8 = 0; ks8 < 8; ks8++) {
            const float* pp = ps_ + (rb + g) * PS_STRIDE + ks8 * 8 + tig;
            uint32_t pa0 = __float_as_uint(pp[0]);
            uint32_t pa1 = __float_as_uint(pp[8 * PS_STRIDE]);
            uint32_t pa2 = __float_as_uint(pp[4]);
            uint32_t pa3 = __float_as_uint(pp[8 * PS_STRIDE + 4]);
#pragma unroll
            for (int n = 0; n < 8; n++) {
                const float* vp = vs_ + (ks8 * 8 + tig) * VS_STRIDE + n * 8 + g;
                mma_tf32(oacc[n], pa0, pa1, pa2, pa3,
                         __float_as_uint(vp[0]), __float_as_uint(vp[4 * VS_STRIDE]));
            }
        }
    }

    l0 += __shfl_xor_sync(0xffffffffu, l0, 1);
    l0 += __shfl_xor_sync(0xffffffffu, l0, 2);
    l1 += __shfl_xor_sync(0xffffffffu, l1, 1);
    l1 += __shfl_xor_sync(0xffffffffu, l1, 2);
    float inv0 = 1.f / l0, inv1 = 1.f / l1;

    // write tf32-rounded so the O-proj GEMM needs no conversion
    uint2* o0 = reinterpret_cast<uint2*>(o + (tokBase + q0 + rb + g) * DM + h * DK + 2 * tig);
    uint2* o1 = reinterpret_cast<uint2*>(o + (tokBase + q0 + rb + g + 8) * DM + h * DK + 2 * tig);
#pragma unroll
    for (int n = 0; n < 8; n++) {
        o0[n * 4] = make_uint2(f32_to_tf32_rna_u(oacc[n][0] * inv0),
                               f32_to_tf32_rna_u(oacc[n][1] * inv0));
        o1[n * 4] = make_uint2(f32_to_tf32_rna_u(oacc[n][2] * inv1),
                               f32_to_tf32_rna_u(oacc[n][3] * inv1));
    }
}

// ---------------- launch ----------------
extern "C" void kernel_launch(void* const* d_in, const int* in_sizes, int n_in,
                              void* d_out, int out_size) {
    const float* x  = (const float*)d_in[0];
    const int*   tp = (const int*)  d_in[1];
    const float* Qw = (const float*)d_in[2];
    const float* Kw = (const float*)d_in[3];
    const float* Vw = (const float*)d_in[4];
    const float* Ow = (const float*)d_in[5];
    float* out = (float*)d_out;

    float *gq, *gk, *gv, *gao, *gxc, *gwc;
    cudaGetSymbolAddress((void**)&gq,  g_q);
    cudaGetSymbolAddress((void**)&gk,  g_k);
    cudaGetSymbolAddress((void**)&gv,  g_v);
    cudaGetSymbolAddress((void**)&gao, g_ao);
    cudaGetSymbolAddress((void**)&gxc, g_xc);
    cudaGetSymbolAddress((void**)&gwc, g_wc);

    cudaFuncSetAttribute(gemm_tf32, cudaFuncAttributeMaxDynamicSharedMemorySize, GEMM_SMEM_BYTES);
    const int flash_smem = FS_TOTAL * 4;
    cudaFuncSetAttribute(flash_mma, cudaFuncAttributeMaxDynamicSharedMemorySize, flash_smem);

    const size_t wsz = (size_t)DM * DM;

    // one-time tf32 rounding of GEMM inputs
    {
        int n4 = (int)(MTOK * (size_t)DM / 4);
        cvt_tf32_kernel<<<(n4 + 255) / 256, 256>>>(x, gxc, n4);
        int w4 = (int)(wsz / 4);
        cvt_tf32_kernel<<<(w4 + 255) / 256, 256>>>(Qw, gwc + 0 * wsz, w4);
        cvt_tf32_kernel<<<(w4 + 255) / 256, 256>>>(Kw, gwc + 1 * wsz, w4);
        cvt_tf32_kernel<<<(w4 + 255) / 256, 256>>>(Vw, gwc + 2 * wsz, w4);
        cvt_tf32_kernel<<<(w4 + 255) / 256, 256>>>(Ow, gwc + 3 * wsz, w4);
    }

    dim3 ggrid(DM / GBN, MTOK / GBM);   // (8, 64)
    gemm_tf32<<<ggrid, 256, GEMM_SMEM_BYTES>>>(gxc, gwc + 0 * wsz, gq);
    gemm_tf32<<<ggrid, 256, GEMM_SMEM_BYTES>>>(gxc, gwc + 1 * wsz, gk);
    gemm_tf32<<<ggrid, 256, GEMM_SMEM_BYTES>>>(gxc, gwc + 2 * wsz, gv);

    int rope_total  = MTOK * (DM / 2);
    int rope_blocks = (rope_total + 255) / 256;
    rope_kernel<<<rope_blocks, 256>>>(gq, gk, tp);

    dim3 fgrid(SD / FQT, NH, BD);       // (32, 16, 4)
    flash_mma<<<fgrid, 128, flash_smem>>>(gq, gk, gv, gao);

    gemm_tf32<<<ggrid, 256, GEMM_SMEM_BYTES>>>(gao, gwc + 3 * wsz, out);
}

// round 8
// speedup vs baseline: 3.9934x; 1.0616x over previous
#include <cuda_runtime.h>
#include <math.h>
#include <stdint.h>

// Problem constants
#define BD 4
#define SD 2048
#define DM 1024
#define NH 16
#define DK 64
#define MTOK (BD*SD)   // 8192 tokens

// ---------------- scratch (static device memory: allowed) ----------------
__device__ float g_q   [(size_t)MTOK * DM];
__device__ float g_k   [(size_t)MTOK * DM];
__device__ float g_v   [(size_t)MTOK * DM];
__device__ float g_ao  [(size_t)MTOK * DM];
__device__ float g_xc  [(size_t)MTOK * DM];        // x pre-rounded to tf32
__device__ float g_wqkv[(size_t)3 * DM * DM];      // [Qw;Kw;Vw] pre-rounded
__device__ float g_wo  [(size_t)DM * DM];          // Ow pre-rounded

__device__ __forceinline__ uint32_t f32_to_tf32_rna_u(float f) {
    uint32_t r;
    asm("cvt.rna.tf32.f32 %0, %1;" : "=r"(r) : "f"(f));
    return r;
}
__device__ __forceinline__ float f32_to_tf32_rna(float f) {
    return __uint_as_float(f32_to_tf32_rna_u(f));
}

__device__ __forceinline__ uint32_t smem_u32(const void* p) {
    uint32_t a;
    asm("{ .reg .u64 t; cvta.to.shared.u64 t, %1; cvt.u32.u64 %0, t; }" : "=r"(a) : "l"(p));
    return a;
}

__device__ __forceinline__ void cp_async16(uint32_t dst, const void* src) {
    asm volatile("cp.async.cg.shared.global [%0], [%1], 16;" :: "r"(dst), "l"(src));
}
#define CP_COMMIT() asm volatile("cp.async.commit_group;" ::: "memory")
#define CP_WAIT1()  asm volatile("cp.async.wait_group 1;" ::: "memory")

__device__ __forceinline__ void mma_tf32(float* c, uint32_t a0, uint32_t a1,
                                         uint32_t a2, uint32_t a3,
                                         uint32_t b0, uint32_t b1) {
    asm volatile(
        "mma.sync.aligned.m16n8k8.row.col.f32.tf32.tf32.f32 "
        "{%0,%1,%2,%3}, {%4,%5,%6,%7}, {%8,%9}, {%0,%1,%2,%3};"
        : "+f"(c[0]), "+f"(c[1]), "+f"(c[2]), "+f"(c[3])
        : "r"(a0), "r"(a1), "r"(a2), "r"(a3), "r"(b0), "r"(b1));
}

// ---------------- pre-round kernels ----------------
__global__ void cvt_tf32_kernel(const float* __restrict__ src,
                                float* __restrict__ dst, int n4) {
    int i = blockIdx.x * blockDim.x + threadIdx.x;
    if (i >= n4) return;
    float4 v = reinterpret_cast<const float4*>(src)[i];
    uint4 u = make_uint4(f32_to_tf32_rna_u(v.x), f32_to_tf32_rna_u(v.y),
                         f32_to_tf32_rna_u(v.z), f32_to_tf32_rna_u(v.w));
    reinterpret_cast<uint4*>(dst)[i] = u;
}

__global__ void pack_qkv_w(const float* __restrict__ Qw,
                           const float* __restrict__ Kw,
                           const float* __restrict__ Vw,
                           float* __restrict__ dst) {
    const int W4 = DM * DM / 4;           // 262144
    int i = blockIdx.x * blockDim.x + threadIdx.x;
    if (i >= 3 * W4) return;
    const float* src = (i < W4) ? Qw : (i < 2 * W4 ? Kw : Vw);
    int li = i - (i < W4 ? 0 : (i < 2 * W4 ? W4 : 2 * W4));
    float4 v = reinterpret_cast<const float4*>(src)[li];
    uint4 u = make_uint4(f32_to_tf32_rna_u(v.x), f32_to_tf32_rna_u(v.y),
                         f32_to_tf32_rna_u(v.z), f32_to_tf32_rna_u(v.w));
    reinterpret_cast<uint4*>(dst)[i] = u;
}

// ======================================================================
// GEMM core pieces (CTA 128x128, 8 warps, warp 64x32, K-chunk 32,
// 3-stage cp.async). Shared by plain GEMM and fused-QKV GEMM.
// ======================================================================
#define GBM 128
#define GBN 128
#define GBK 32
#define LDSW 36
#define TILE_FLOATS (GBM * LDSW)          // 4608
#define NCHUNK (DM / GBK)                 // 32
#define STAGE_FLOATS (2 * TILE_FLOATS)
#define GEMM_SMEM_BYTES (3 * STAGE_FLOATS * 4)   // 110592

// mainloop: computes acc for tile (Arows = A + bm, Wrows = W + bng)
__device__ __forceinline__ void gemm_mainloop(
    const float* __restrict__ A, const float* __restrict__ W,
    float* smem, uint32_t sbase, int bm, int bng,
    int tid, int wm, int wn, int g, int tig,
    float acc[4][4][4])
{
    const int row   = tid >> 1;
    const int cbase = (tid & 1) * 16;
    const float* Ap = A + (size_t)(bm + row) * DM + cbase;
    const float* Wp = W + (size_t)(bng + row) * DM + cbase;
    const uint32_t sdoff = (uint32_t)(row * LDSW + cbase) * 4u;

#pragma unroll
    for (int s = 0; s < 2; s++) {
        const uint32_t ab = sbase + (uint32_t)s * (STAGE_FLOATS * 4);
        const float* ap = Ap + s * GBK;
        const float* wp = Wp + s * GBK;
#pragma unroll
        for (int i = 0; i < 4; i++) {
            cp_async16(ab + sdoff + i * 16, ap + i * 4);
            cp_async16(ab + TILE_FLOATS * 4 + sdoff + i * 16, wp + i * 4);
        }
        CP_COMMIT();
    }

    const int aoff = (wm * 64 + g) * LDSW + tig;
    const int boff = (wn * 32 + g) * LDSW + tig;

    for (int kt = 0; kt < NCHUNK; kt++) {
        CP_WAIT1();
        __syncthreads();

        if (kt + 2 < NCHUNK) {
            const int s = (kt + 2) % 3;
            const uint32_t ab = sbase + (uint32_t)s * (STAGE_FLOATS * 4);
            const float* ap = Ap + (kt + 2) * GBK;
            const float* wp = Wp + (kt + 2) * GBK;
#pragma unroll
            for (int i = 0; i < 4; i++) {
                cp_async16(ab + sdoff + i * 16, ap + i * 4);
                cp_async16(ab + TILE_FLOATS * 4 + sdoff + i * 16, wp + i * 4);
            }
        }
        CP_COMMIT();

        const float* aB = smem + (kt % 3) * STAGE_FLOATS + aoff;
        const float* bB = smem + (kt % 3) * STAGE_FLOATS + TILE_FLOATS + boff;
#pragma unroll
        for (int ks = 0; ks < 4; ks++) {
            uint32_t af[4][4];
#pragma unroll
            for (int mt = 0; mt < 4; mt++) {
                const float* p = aB + mt * (16 * LDSW) + ks * 8;
                af[mt][0] = __float_as_uint(p[0]);
                af[mt][1] = __float_as_uint(p[8 * LDSW]);
                af[mt][2] = __float_as_uint(p[4]);
                af[mt][3] = __float_as_uint(p[8 * LDSW + 4]);
            }
            uint32_t bf[4][2];
#pragma unroll
            for (int nt = 0; nt < 4; nt++) {
                const float* p = bB + nt * (8 * LDSW) + ks * 8;
                bf[nt][0] = __float_as_uint(p[0]);
                bf[nt][1] = __float_as_uint(p[4]);
            }
#pragma unroll
            for (int mt = 0; mt < 4; mt++)
#pragma unroll
                for (int nt = 0; nt < 4; nt++)
                    mma_tf32(acc[mt][nt], af[mt][0], af[mt][1], af[mt][2], af[mt][3],
                             bf[nt][0], bf[nt][1]);
        }
    }
}

// ---------------- plain GEMM (O-projection) ----------------
__global__ __launch_bounds__(256)
void gemm_tf32(const float* __restrict__ A,
               const float* __restrict__ W,
               float* __restrict__ C) {
    extern __shared__ float smem[];
    const uint32_t sbase = smem_u32(smem);
    const int tid  = threadIdx.x;
    const int wid  = tid >> 5;
    const int lane = tid & 31;
    const int bm = blockIdx.y * GBM;
    const int bn = blockIdx.x * GBN;
    const int wm = wid >> 2, wn = wid & 3;
    const int g = lane >> 2, tig = lane & 3;

    float acc[4][4][4];
#pragma unroll
    for (int i = 0; i < 4; i++)
#pragma unroll
        for (int j = 0; j < 4; j++)
#pragma unroll
            for (int r2 = 0; r2 < 4; r2++) acc[i][j][r2] = 0.f;

    gemm_mainloop(A, W, smem, sbase, bm, bn, tid, wm, wn, g, tig, acc);

    const int m0 = bm + wm * 64 + g;
    const int n0 = bn + wn * 32 + 2 * tig;
#pragma unroll
    for (int mt = 0; mt < 4; mt++) {
#pragma unroll
        for (int nt = 0; nt < 4; nt++) {
            float* p0 = C + (size_t)(m0 + mt * 16) * DM + n0 + nt * 8;
            float* p1 = p0 + 8 * DM;
            *reinterpret_cast<float2*>(p0) = make_float2(acc[mt][nt][0], acc[mt][nt][1]);
            *reinterpret_cast<float2*>(p1) = make_float2(acc[mt][nt][2], acc[mt][nt][3]);
        }
    }
}

// ---------------- fused QKV GEMM + RoPE + scale + tf32 round ----------------
__global__ __launch_bounds__(256)
void gemm_qkv(const float* __restrict__ A,
              const float* __restrict__ W,   // [3072,1024]
              const int*   __restrict__ pos, // [8192]
              float* __restrict__ outq,
              float* __restrict__ outk,
              float* __restrict__ outv) {
    extern __shared__ float smem[];
    const uint32_t sbase = smem_u32(smem);
    const int tid  = threadIdx.x;
    const int wid  = tid >> 5;
    const int lane = tid & 31;
    const int bm  = blockIdx.y * GBM;
    const int bng = blockIdx.x * GBN;          // 0..2944 (fused-N)
    const int wm = wid >> 2, wn = wid & 3;
    const int g = lane >> 2, tig = lane & 3;

    float acc[4][4][4];
#pragma unroll
    for (int i = 0; i < 4; i++)
#pragma unroll
        for (int j = 0; j < 4; j++)
#pragma unroll
            for (int r2 = 0; r2 < 4; r2++) acc[i][j][r2] = 0.f;

    gemm_mainloop(A, W, smem, sbase, bm, bng, tid, wm, wn, g, tig, acc);

    const int region = blockIdx.x >> 3;        // 0=q, 1=k, 2=v
    float* dst = (region == 0) ? outq : (region == 1 ? outk : outv);
    const int nbase = (blockIdx.x & 7) * GBN;
    const int m0 = bm + wm * 64 + g;
    const int n0 = nbase + wn * 32 + 2 * tig;

    if (region < 2) {
        const float scale = (region == 0) ? 0.125f : 1.0f;
        const float lt = 0.1439115683121279f;   // ln(10000)/64
        float invf[4];
#pragma unroll
        for (int nt = 0; nt < 4; nt++) {
            int c = (n0 + nt * 8) & (DK - 1);    // even head-local col
            invf[nt] = __expf(-(float)c * lt);
        }
#pragma unroll
        for (int mt = 0; mt < 4; mt++) {
            const int r0 = m0 + mt * 16;
            const float p0 = (float)pos[r0];
            const float p1 = (float)pos[r0 + 8];
#pragma unroll
            for (int nt = 0; nt < 4; nt++) {
                float s0, c0, s1, c1;
                sincosf(p0 * invf[nt], &s0, &c0);
                sincosf(p1 * invf[nt], &s1, &c1);
                float e0 = acc[mt][nt][0], o0v = acc[mt][nt][1];
                float e1 = acc[mt][nt][2], o1v = acc[mt][nt][3];
                acc[mt][nt][0] = (e0 * c0 - o0v * s0) * scale;
                acc[mt][nt][1] = (e0 * s0 + o0v * c0) * scale;
                acc[mt][nt][2] = (e1 * c1 - o1v * s1) * scale;
                acc[mt][nt][3] = (e1 * s1 + o1v * c1) * scale;
            }
        }
    }

#pragma unroll
    for (int mt = 0; mt < 4; mt++) {
#pragma unroll
        for (int nt = 0; nt < 4; nt++) {
            uint2* p0 = reinterpret_cast<uint2*>(dst + (size_t)(m0 + mt * 16) * DM + n0 + nt * 8);
            uint2* p1 = reinterpret_cast<uint2*>(dst + (size_t)(m0 + mt * 16 + 8) * DM + n0 + nt * 8);
            *p0 = make_uint2(f32_to_tf32_rna_u(acc[mt][nt][0]), f32_to_tf32_rna_u(acc[mt][nt][1]));
            *p1 = make_uint2(f32_to_tf32_rna_u(acc[mt][nt][2]), f32_to_tf32_rna_u(acc[mt][nt][3]));
        }
    }
}

// ======================================================================
// mma-based causal flash attention; inputs pre-rounded/pre-scaled,
// epilogue writes tf32-rounded for the O-projection.
// ======================================================================
#define FQT 64
#define FKT 64
#define KS_STRIDE 68
#define VS_STRIDE 65
#define PS_STRIDE 68
#define FS_KS 0
#define FS_VS (64 * KS_STRIDE)
#define FS_PS (FS_VS + 64 * VS_STRIDE)
#define FS_TOTAL (FS_PS + 64 * PS_STRIDE)   // 12864 floats = 51456 B

__global__ __launch_bounds__(128)
void flash_mma(const float* __restrict__ q,
               const float* __restrict__ k,
               const float* __restrict__ v,
               float* __restrict__ o) {
    extern __shared__ float fsm[];
    float* ks_ = fsm + FS_KS;
    float* vs_ = fsm + FS_VS;
    float* ps_ = fsm + FS_PS;

    const int tid  = threadIdx.x;
    const int w    = tid >> 5;
    const int lane = tid & 31;
    const int g    = lane >> 2;
    const int tig  = lane & 3;
    const int qb = gridDim.x - 1 - blockIdx.x;
    const int h  = blockIdx.y;
    const int b  = blockIdx.z;
    const int q0 = qb * FQT;
    const size_t tokBase = (size_t)b * SD;
    const int rb = w * 16;

    {
        const float* qbase = q + (tokBase + q0) * DM + h * DK;
#pragma unroll
        for (int i = 0; i < 16; i++) {
            int j = tid + 128 * i;
            int r = j >> 5, c2 = j & 31;
            float2 t2 = *reinterpret_cast<const float2*>(qbase + (size_t)r * DM + 2 * c2);
            ps_[r * PS_STRIDE + 2*c2]     = t2.x;
            ps_[r * PS_STRIDE + 2*c2 + 1] = t2.y;
        }
    }
    __syncthreads();
    uint32_t qa[8][4];
#pragma unroll
    for (int ks8 = 0; ks8 < 8; ks8++) {
        const float* p = ps_ + (rb + g) * PS_STRIDE + ks8 * 8 + tig;
        qa[ks8][0] = __float_as_uint(p[0]);
        qa[ks8][1] = __float_as_uint(p[8 * PS_STRIDE]);
        qa[ks8][2] = __float_as_uint(p[4]);
        qa[ks8][3] = __float_as_uint(p[8 * PS_STRIDE + 4]);
    }

    float m0 = -1e30f, m1 = -1e30f, l0 = 0.f, l1 = 0.f;
    float oacc[8][4];
#pragma unroll
    for (int n = 0; n < 8; n++)
#pragma unroll
        for (int c = 0; c < 4; c++) oacc[n][c] = 0.f;

    const int ntiles = q0 / FKT + 1;
    for (int kt = 0; kt < ntiles; kt++) {
        const int k0 = kt * FKT;
        __syncthreads();
        const float* kbase = k + (tokBase + k0) * DM + h * DK;
        const float* vbase = v + (tokBase + k0) * DM + h * DK;
#pragma unroll
        for (int i = 0; i < 16; i++) {
            int j = tid + 128 * i;
            int r = j >> 5, c2 = j & 31;
            float2 kk = *reinterpret_cast<const float2*>(kbase + (size_t)r * DM + 2 * c2);
            float2 vv = *reinterpret_cast<const float2*>(vbase + (size_t)r * DM + 2 * c2);
            ks_[r * KS_STRIDE + 2*c2]     = kk.x;
            ks_[r * KS_STRIDE + 2*c2 + 1] = kk.y;
            vs_[r * VS_STRIDE + 2*c2]     = vv.x;
            vs_[r * VS_STRIDE + 2*c2 + 1] = vv.y;
        }
        __syncthreads();

        float sacc[8][4];
#pragma unroll
        for (int n = 0; n < 8; n++)
#pragma unroll
            for (int c = 0; c < 4; c++) sacc[n][c] = 0.f;
#pragma unroll
        for (int ks8 = 0; ks8 < 8; ks8++) {
#pragma unroll
            for (int n = 0; n < 8; n++) {
                const float* kp = ks_ + (n * 8 + g) * KS_STRIDE + ks8 * 8 + tig;
                mma_tf32(sacc[n], qa[ks8][0], qa[ks8][1], qa[ks8][2], qa[ks8][3],
                         __float_as_uint(kp[0]), __float_as_uint(kp[4]));
            }
        }

        if (k0 == q0) {
            const int row0 = q0 + rb + g;
            const int row1 = row0 + 8;
#pragma unroll
            for (int n = 0; n < 8; n++) {
                int col = k0 + n * 8 + 2 * tig;
                if (col     > row0) sacc[n][0] = -1e30f;
                if (col + 1 > row0) sacc[n][1] = -1e30f;
                if (col     > row1) sacc[n][2] = -1e30f;
                if (col + 1 > row1) sacc[n][3] = -1e30f;
            }
        }

        float mx0 = -1e30f, mx1 = -1e30f;
#pragma unroll
        for (int n = 0; n < 8; n++) {
            mx0 = fmaxf(mx0, fmaxf(sacc[n][0], sacc[n][1]));
            mx1 = fmaxf(mx1, fmaxf(sacc[n][2], sacc[n][3]));
        }
        mx0 = fmaxf(mx0, __shfl_xor_sync(0xffffffffu, mx0, 1));
        mx0 = fmaxf(mx0, __shfl_xor_sync(0xffffffffu, mx0, 2));
        mx1 = fmaxf(mx1, __shfl_xor_sync(0xffffffffu, mx1, 1));
        mx1 = fmaxf(mx1, __shfl_xor_sync(0xffffffffu, mx1, 2));

        float mn0 = fmaxf(m0, mx0), mn1 = fmaxf(m1, mx1);
        float al0 = __expf(m0 - mn0), al1 = __expf(m1 - mn1);
        m0 = mn0; m1 = mn1;
        l0 *= al0; l1 *= al1;

        float* ps0 = ps_ + (rb + g) * PS_STRIDE + 2 * tig;
        float* ps1 = ps0 + 8 * PS_STRIDE;
#pragma unroll
        for (int n = 0; n < 8; n++) {
            float p0 = __expf(sacc[n][0] - mn0);
            float p1 = __expf(sacc[n][1] - mn0);
            float p2 = __expf(sacc[n][2] - mn1);
            float p3 = __expf(sacc[n][3] - mn1);
            l0 += p0 + p1;
            l1 += p2 + p3;
            uint2 u01 = make_uint2(f32_to_tf32_rna_u(p0), f32_to_tf32_rna_u(p1));
            uint2 u23 = make_uint2(f32_to_tf32_rna_u(p2), f32_to_tf32_rna_u(p3));
            *reinterpret_cast<uint2*>(ps0 + n * 8) = u01;
            *reinterpret_cast<uint2*>(ps1 + n * 8) = u23;
            oacc[n][0] *= al0; oacc[n][1] *= al0;
            oacc[n][2] *= al1; oacc[n][3] *= al1;
        }
        __syncwarp();

#pragma unroll
        for (int ks8 = 0; ks8 < 8; ks8++) {
            const float* pp = ps_ + (rb + g) * PS_STRIDE + ks8 * 8 + tig;
            uint32_t pa0 = __float_as_uint(pp[0]);
            uint32_t pa1 = __float_as_uint(pp[8 * PS_STRIDE]);
            uint32_t pa2 = __float_as_uint(pp[4]);
            uint32_t pa3 = __float_as_uint(pp[8 * PS_STRIDE + 4]);
#pragma unroll
            for (int n = 0; n < 8; n++) {
                const float* vp = vs_ + (ks8 * 8 + tig) * VS_STRIDE + n * 8 + g;
                mma_tf32(oacc[n], pa0, pa1, pa2, pa3,
                         __float_as_uint(vp[0]), __float_as_uint(vp[4 * VS_STRIDE]));
            }
        }
    }

    l0 += __shfl_xor_sync(0xffffffffu, l0, 1);
    l0 += __shfl_xor_sync(0xffffffffu, l0, 2);
    l1 += __shfl_xor_sync(0xffffffffu, l1, 1);
    l1 += __shfl_xor_sync(0xffffffffu, l1, 2);
    float inv0 = 1.f / l0, inv1 = 1.f / l1;

    uint2* o0 = reinterpret_cast<uint2*>(o + (tokBase + q0 + rb + g) * DM + h * DK + 2 * tig);
    uint2* o1 = reinterpret_cast<uint2*>(o + (tokBase + q0 + rb + g + 8) * DM + h * DK + 2 * tig);
#pragma unroll
    for (int n = 0; n < 8; n++) {
        o0[n * 4] = make_uint2(f32_to_tf32_rna_u(oacc[n][0] * inv0),
                               f32_to_tf32_rna_u(oacc[n][1] * inv0));
        o1[n * 4] = make_uint2(f32_to_tf32_rna_u(oacc[n][2] * inv1),
                               f32_to_tf32_rna_u(oacc[n][3] * inv1));
    }
}

// ---------------- launch ----------------
extern "C" void kernel_launch(void* const* d_in, const int* in_sizes, int n_in,
                              void* d_out, int out_size) {
    const float* x  = (const float*)d_in[0];
    const int*   tp = (const int*)  d_in[1];
    const float* Qw = (const float*)d_in[2];
    const float* Kw = (const float*)d_in[3];
    const float* Vw = (const float*)d_in[4];
    const float* Ow = (const float*)d_in[5];
    float* out = (float*)d_out;

    float *gq, *gk, *gv, *gao, *gxc, *gwqkv, *gwo;
    cudaGetSymbolAddress((void**)&gq,    g_q);
    cudaGetSymbolAddress((void**)&gk,    g_k);
    cudaGetSymbolAddress((void**)&gv,    g_v);
    cudaGetSymbolAddress((void**)&gao,   g_ao);
    cudaGetSymbolAddress((void**)&gxc,   g_xc);
    cudaGetSymbolAddress((void**)&gwqkv, g_wqkv);
    cudaGetSymbolAddress((void**)&gwo,   g_wo);

    cudaFuncSetAttribute(gemm_tf32, cudaFuncAttributeMaxDynamicSharedMemorySize, GEMM_SMEM_BYTES);
    cudaFuncSetAttribute(gemm_qkv,  cudaFuncAttributeMaxDynamicSharedMemorySize, GEMM_SMEM_BYTES);
    const int flash_smem = FS_TOTAL * 4;
    cudaFuncSetAttribute(flash_mma, cudaFuncAttributeMaxDynamicSharedMemorySize, flash_smem);

    // pre-round inputs
    {
        int n4 = (int)(MTOK * (size_t)DM / 4);
        cvt_tf32_kernel<<<(n4 + 255) / 256, 256>>>(x, gxc, n4);
        int p4 = 3 * DM * DM / 4;
        pack_qkv_w<<<(p4 + 255) / 256, 256>>>(Qw, Kw, Vw, gwqkv);
        int w4 = DM * DM / 4;
        cvt_tf32_kernel<<<(w4 + 255) / 256, 256>>>(Ow, gwo, w4);
    }

    // fused QKV projection + RoPE
    dim3 qgrid(3 * DM / GBN, MTOK / GBM);   // (24, 64)
    gemm_qkv<<<qgrid, 256, GEMM_SMEM_BYTES>>>(gxc, gwqkv, tp, gq, gk, gv);

    // attention
    dim3 fgrid(SD / FQT, NH, BD);           // (32, 16, 4)
    flash_mma<<<fgrid, 128, flash_smem>>>(gq, gk, gv, gao);

    // output projection
    dim3 ggrid(DM / GBN, MTOK / GBM);       // (8, 64)
    gemm_tf32<<<ggrid, 256, GEMM_SMEM_BYTES>>>(gao, gwo, out);
}

// round 9
// speedup vs baseline: 4.1076x; 1.0286x over previous
#include <cuda_runtime.h>
#include <math.h>
#include <stdint.h>

// Problem constants
#define BD 4
#define SD 2048
#define DM 1024
#define NH 16
#define DK 64
#define MTOK (BD*SD)   // 8192 tokens

// ---------------- scratch (static device memory: allowed) ----------------
__device__ float g_q   [(size_t)MTOK * DM];
__device__ float g_k   [(size_t)MTOK * DM];
__device__ float g_v   [(size_t)MTOK * DM];
__device__ float g_ao  [(size_t)MTOK * DM];
__device__ float g_xc  [(size_t)MTOK * DM];        // x pre-rounded to tf32
__device__ float g_wqkv[(size_t)3 * DM * DM];      // [Qw;Kw;Vw] pre-rounded
__device__ float g_wo  [(size_t)DM * DM];          // Ow pre-rounded

__device__ __forceinline__ uint32_t f32_to_tf32_rna_u(float f) {
    uint32_t r;
    asm("cvt.rna.tf32.f32 %0, %1;" : "=r"(r) : "f"(f));
    return r;
}

__device__ __forceinline__ uint32_t smem_u32(const void* p) {
    uint32_t a;
    asm("{ .reg .u64 t; cvta.to.shared.u64 t, %1; cvt.u32.u64 %0, t; }" : "=r"(a) : "l"(p));
    return a;
}

__device__ __forceinline__ void cp_async16(uint32_t dst, const void* src) {
    asm volatile("cp.async.cg.shared.global [%0], [%1], 16;" :: "r"(dst), "l"(src));
}
#define CP_COMMIT() asm volatile("cp.async.commit_group;" ::: "memory")
#define CP_WAIT1()  asm volatile("cp.async.wait_group 1;" ::: "memory")

__device__ __forceinline__ void mma_tf32(float* c, uint32_t a0, uint32_t a1,
                                         uint32_t a2, uint32_t a3,
                                         uint32_t b0, uint32_t b1) {
    asm volatile(
        "mma.sync.aligned.m16n8k8.row.col.f32.tf32.tf32.f32 "
        "{%0,%1,%2,%3}, {%4,%5,%6,%7}, {%8,%9}, {%0,%1,%2,%3};"
        : "+f"(c[0]), "+f"(c[1]), "+f"(c[2]), "+f"(c[3])
        : "r"(a0), "r"(a1), "r"(a2), "r"(a3), "r"(b0), "r"(b1));
}

// ---------------- pre-round kernels ----------------
__global__ void cvt_tf32_kernel(const float* __restrict__ src,
                                float* __restrict__ dst, int n4) {
    int i = blockIdx.x * blockDim.x + threadIdx.x;
    if (i >= n4) return;
    float4 v = reinterpret_cast<const float4*>(src)[i];
    uint4 u = make_uint4(f32_to_tf32_rna_u(v.x), f32_to_tf32_rna_u(v.y),
                         f32_to_tf32_rna_u(v.z), f32_to_tf32_rna_u(v.w));
    reinterpret_cast<uint4*>(dst)[i] = u;
}

__global__ void pack_qkv_w(const float* __restrict__ Qw,
                           const float* __restrict__ Kw,
                           const float* __restrict__ Vw,
                           float* __restrict__ dst) {
    const int W4 = DM * DM / 4;           // 262144
    int i = blockIdx.x * blockDim.x + threadIdx.x;
    if (i >= 3 * W4) return;
    const float* src = (i < W4) ? Qw : (i < 2 * W4 ? Kw : Vw);
    int li = i - (i < W4 ? 0 : (i < 2 * W4 ? W4 : 2 * W4));
    float4 v = reinterpret_cast<const float4*>(src)[li];
    uint4 u = make_uint4(f32_to_tf32_rna_u(v.x), f32_to_tf32_rna_u(v.y),
                         f32_to_tf32_rna_u(v.z), f32_to_tf32_rna_u(v.w));
    reinterpret_cast<uint4*>(dst)[i] = u;
}

// ======================================================================
// GEMM core (CTA 128x128, 8 warps, warp 64x32, K-chunk 32,
// 2-stage cp.async so TWO CTAs co-reside per SM).
// ======================================================================
#define GBM 128
#define GBN 128
#define GBK 32
#define LDSW 36
#define TILE_FLOATS (GBM * LDSW)          // 4608
#define NCHUNK (DM / GBK)                 // 32
#define STAGE_FLOATS (2 * TILE_FLOATS)    // A + W per stage
#define GEMM_SMEM_BYTES (2 * STAGE_FLOATS * 4)   // 73728

__device__ __forceinline__ void gemm_mainloop(
    const float* __restrict__ A, const float* __restrict__ W,
    float* smem, uint32_t sbase, int bm, int bng,
    int tid, int wm, int wn, int g, int tig,
    float acc[4][4][4])
{
    const int row   = tid >> 1;
    const int cbase = (tid & 1) * 16;
    const float* Ap = A + (size_t)(bm + row) * DM + cbase;
    const float* Wp = W + (size_t)(bng + row) * DM + cbase;
    const uint32_t sdoff = (uint32_t)(row * LDSW + cbase) * 4u;

    // prologue: chunks 0 and 1 in flight (one group each)
#pragma unroll
    for (int s = 0; s < 2; s++) {
        const uint32_t ab = sbase + (uint32_t)s * (STAGE_FLOATS * 4);
        const float* ap = Ap + s * GBK;
        const float* wp = Wp + s * GBK;
#pragma unroll
        for (int i = 0; i < 4; i++) {
            cp_async16(ab + sdoff + i * 16, ap + i * 4);
            cp_async16(ab + TILE_FLOATS * 4 + sdoff + i * 16, wp + i * 4);
        }
        CP_COMMIT();
    }

    const int aoff = (wm * 64 + g) * LDSW + tig;
    const int boff = (wn * 32 + g) * LDSW + tig;

    for (int kt = 0; kt < NCHUNK; kt++) {
        // one group committed per iteration => "all but newest done" == chunk kt resident
        CP_WAIT1();
        __syncthreads();

        const float* aB = smem + (kt & 1) * STAGE_FLOATS + aoff;
        const float* bB = smem + (kt & 1) * STAGE_FLOATS + TILE_FLOATS + boff;
#pragma unroll
        for (int ks = 0; ks < 4; ks++) {
            uint32_t af[4][4];
#pragma unroll
            for (int mt = 0; mt < 4; mt++) {
                const float* p = aB + mt * (16 * LDSW) + ks * 8;
                af[mt][0] = __float_as_uint(p[0]);
                af[mt][1] = __float_as_uint(p[8 * LDSW]);
                af[mt][2] = __float_as_uint(p[4]);
                af[mt][3] = __float_as_uint(p[8 * LDSW + 4]);
            }
            uint32_t bf[4][2];
#pragma unroll
            for (int nt = 0; nt < 4; nt++) {
                const float* p = bB + nt * (8 * LDSW) + ks * 8;
                bf[nt][0] = __float_as_uint(p[0]);
                bf[nt][1] = __float_as_uint(p[4]);
            }
#pragma unroll
            for (int mt = 0; mt < 4; mt++)
#pragma unroll
                for (int nt = 0; nt < 4; nt++)
                    mma_tf32(acc[mt][nt], af[mt][0], af[mt][1], af[mt][2], af[mt][3],
                             bf[nt][0], bf[nt][1]);
        }

        __syncthreads();   // all reads of stage kt&1 done before refilling it

        if (kt + 2 < NCHUNK) {
            const uint32_t ab = sbase + (uint32_t)(kt & 1) * (STAGE_FLOATS * 4);
            const float* ap = Ap + (kt + 2) * GBK;
            const float* wp = Wp + (kt + 2) * GBK;
#pragma unroll
            for (int i = 0; i < 4; i++) {
                cp_async16(ab + sdoff + i * 16, ap + i * 4);
                cp_async16(ab + TILE_FLOATS * 4 + sdoff + i * 16, wp + i * 4);
            }
        }
        CP_COMMIT();       // empty group when nothing to fill: keeps accounting aligned
    }
}

// ---------------- plain GEMM (O-projection) ----------------
__global__ __launch_bounds__(256, 2)
void gemm_tf32(const float* __restrict__ A,
               const float* __restrict__ W,
               float* __restrict__ C) {
    extern __shared__ float smem[];
    const uint32_t sbase = smem_u32(smem);
    const int tid  = threadIdx.x;
    const int wid  = tid >> 5;
    const int lane = tid & 31;
    const int bm = blockIdx.y * GBM;
    const int bn = blockIdx.x * GBN;
    const int wm = wid >> 2, wn = wid & 3;
    const int g = lane >> 2, tig = lane & 3;

    float acc[4][4][4];
#pragma unroll
    for (int i = 0; i < 4; i++)
#pragma unroll
        for (int j = 0; j < 4; j++)
#pragma unroll
            for (int r2 = 0; r2 < 4; r2++) acc[i][j][r2] = 0.f;

    gemm_mainloop(A, W, smem, sbase, bm, bn, tid, wm, wn, g, tig, acc);

    const int m0 = bm + wm * 64 + g;
    const int n0 = bn + wn * 32 + 2 * tig;
#pragma unroll
    for (int mt = 0; mt < 4; mt++) {
#pragma unroll
        for (int nt = 0; nt < 4; nt++) {
            float* p0 = C + (size_t)(m0 + mt * 16) * DM + n0 + nt * 8;
            float* p1 = p0 + 8 * DM;
            *reinterpret_cast<float2*>(p0) = make_float2(acc[mt][nt][0], acc[mt][nt][1]);
            *reinterpret_cast<float2*>(p1) = make_float2(acc[mt][nt][2], acc[mt][nt][3]);
        }
    }
}

// ---------------- fused QKV GEMM + RoPE + scale + tf32 round ----------------
__global__ __launch_bounds__(256, 2)
void gemm_qkv(const float* __restrict__ A,
              const float* __restrict__ W,   // [3072,1024]
              const int*   __restrict__ pos, // [8192]
              float* __restrict__ outq,
              float* __restrict__ outk,
              float* __restrict__ outv) {
    extern __shared__ float smem[];
    const uint32_t sbase = smem_u32(smem);
    const int tid  = threadIdx.x;
    const int wid  = tid >> 5;
    const int lane = tid & 31;
    const int bm  = blockIdx.y * GBM;
    const int bng = blockIdx.x * GBN;
    const int wm = wid >> 2, wn = wid & 3;
    const int g = lane >> 2, tig = lane & 3;

    float acc[4][4][4];
#pragma unroll
    for (int i = 0; i < 4; i++)
#pragma unroll
        for (int j = 0; j < 4; j++)
#pragma unroll
            for (int r2 = 0; r2 < 4; r2++) acc[i][j][r2] = 0.f;

    gemm_mainloop(A, W, smem, sbase, bm, bng, tid, wm, wn, g, tig, acc);

    const int region = blockIdx.x >> 3;        // 0=q, 1=k, 2=v
    float* dst = (region == 0) ? outq : (region == 1 ? outk : outv);
    const int nbase = (blockIdx.x & 7) * GBN;
    const int m0 = bm + wm * 64 + g;
    const int n0 = nbase + wn * 32 + 2 * tig;

    if (region < 2) {
        const float scale = (region == 0) ? 0.125f : 1.0f;
        const float lt = 0.1439115683121279f;   // ln(10000)/64
        float invf[4];
#pragma unroll
        for (int nt = 0; nt < 4; nt++) {
            int c = (n0 + nt * 8) & (DK - 1);
            invf[nt] = __expf(-(float)c * lt);
        }
#pragma unroll
        for (int mt = 0; mt < 4; mt++) {
            const int r0 = m0 + mt * 16;
            const float p0 = (float)pos[r0];
            const float p1 = (float)pos[r0 + 8];
#pragma unroll
            for (int nt = 0; nt < 4; nt++) {
                float s0, c0, s1, c1;
                sincosf(p0 * invf[nt], &s0, &c0);
                sincosf(p1 * invf[nt], &s1, &c1);
                float e0 = acc[mt][nt][0], o0v = acc[mt][nt][1];
                float e1 = acc[mt][nt][2], o1v = acc[mt][nt][3];
                acc[mt][nt][0] = (e0 * c0 - o0v * s0) * scale;
                acc[mt][nt][1] = (e0 * s0 + o0v * c0) * scale;
                acc[mt][nt][2] = (e1 * c1 - o1v * s1) * scale;
                acc[mt][nt][3] = (e1 * s1 + o1v * c1) * scale;
            }
        }
    }

#pragma unroll
    for (int mt = 0; mt < 4; mt++) {
#pragma unroll
        for (int nt = 0; nt < 4; nt++) {
            uint2* p0 = reinterpret_cast<uint2*>(dst + (size_t)(m0 + mt * 16) * DM + n0 + nt * 8);
            uint2* p1 = reinterpret_cast<uint2*>(dst + (size_t)(m0 + mt * 16 + 8) * DM + n0 + nt * 8);
            *p0 = make_uint2(f32_to_tf32_rna_u(acc[mt][nt][0]), f32_to_tf32_rna_u(acc[mt][nt][1]));
            *p1 = make_uint2(f32_to_tf32_rna_u(acc[mt][nt][2]), f32_to_tf32_rna_u(acc[mt][nt][3]));
        }
    }
}

// ======================================================================
// mma-based causal flash attention
// ======================================================================
#define FQT 64
#define FKT 64
#define KS_STRIDE 68
#define VS_STRIDE 65
#define PS_STRIDE 68
#define FS_KS 0
#define FS_VS (64 * KS_STRIDE)
#define FS_PS (FS_VS + 64 * VS_STRIDE)
#define FS_TOTAL (FS_PS + 64 * PS_STRIDE)   // 12864 floats = 51456 B

__global__ __launch_bounds__(128)
void flash_mma(const float* __restrict__ q,
               const float* __restrict__ k,
               const float* __restrict__ v,
               float* __restrict__ o) {
    extern __shared__ float fsm[];
    float* ks_ = fsm + FS_KS;
    float* vs_ = fsm + FS_VS;
    float* ps_ = fsm + FS_PS;

    const int tid  = threadIdx.x;
    const int w    = tid >> 5;
    const int lane = tid & 31;
    const int g    = lane >> 2;
    const int tig  = lane & 3;
    const int qb = gridDim.x - 1 - blockIdx.x;
    const int h  = blockIdx.y;
    const int b  = blockIdx.z;
    const int q0 = qb * FQT;
    const size_t tokBase = (size_t)b * SD;
    const int rb = w * 16;

    {
        const float* qbase = q + (tokBase + q0) * DM + h * DK;
#pragma unroll
        for (int i = 0; i < 16; i++) {
            int j = tid + 128 * i;
            int r = j >> 5, c2 = j & 31;
            float2 t2 = *reinterpret_cast<const float2*>(qbase + (size_t)r * DM + 2 * c2);
            ps_[r * PS_STRIDE + 2*c2]     = t2.x;
            ps_[r * PS_STRIDE + 2*c2 + 1] = t2.y;
        }
    }
    __syncthreads();
    uint32_t qa[8][4];
#pragma unroll
    for (int ks8 = 0; ks8 < 8; ks8++) {
        const float* p = ps_ + (rb + g) * PS_STRIDE + ks8 * 8 + tig;
        qa[ks8][0] = __float_as_uint(p[0]);
        qa[ks8][1] = __float_as_uint(p[8 * PS_STRIDE]);
        qa[ks8][2] = __float_as_uint(p[4]);
        qa[ks8][3] = __float_as_uint(p[8 * PS_STRIDE + 4]);
    }

    float m0 = -1e30f, m1 = -1e30f, l0 = 0.f, l1 = 0.f;
    float oacc[8][4];
#pragma unroll
    for (int n = 0; n < 8; n++)
#pragma unroll
        for (int c = 0; c < 4; c++) oacc[n][c] = 0.f;

    const int ntiles = q0 / FKT + 1;
    for (int kt = 0; kt < ntiles; kt++) {
        const int k0 = kt * FKT;
        __syncthreads();
        const float* kbase = k + (tokBase + k0) * DM + h * DK;
        const float* vbase = v + (tokBase + k0) * DM + h * DK;
#pragma unroll
        for (int i = 0; i < 16; i++) {
            int j = tid + 128 * i;
            int r = j >> 5, c2 = j & 31;
            float2 kk = *reinterpret_cast<const float2*>(kbase + (size_t)r * DM + 2 * c2);
            float2 vv = *reinterpret_cast<const float2*>(vbase + (size_t)r * DM + 2 * c2);
            ks_[r * KS_STRIDE + 2*c2]     = kk.x;
            ks_[r * KS_STRIDE + 2*c2 + 1] = kk.y;
            vs_[r * VS_STRIDE + 2*c2]     = vv.x;
            vs_[r * VS_STRIDE + 2*c2 + 1] = vv.y;
        }
        __syncthreads();

        float sacc[8][4];
#pragma unroll
        for (int n = 0; n < 8; n++)
#pragma unroll
            for (int c = 0; c < 4; c++) sacc[n][c] = 0.f;
#pragma unroll
        for (int ks8 = 0; ks8 < 8; ks8++) {
#pragma unroll
            for (int n = 0; n < 8; n++) {
                const float* kp = ks_ + (n * 8 + g) * KS_STRIDE + ks8 * 8 + tig;
                mma_tf32(sacc[n], qa[ks8][0], qa[ks8][1], qa[ks8][2], qa[ks8][3],
                         __float_as_uint(kp[0]), __float_as_uint(kp[4]));
            }
        }

        if (k0 == q0) {
            const int row0 = q0 + rb + g;
            const int row1 = row0 + 8;
#pragma unroll
            for (int n = 0; n < 8; n++) {
                int col = k0 + n * 8 + 2 * tig;
                if (col     > row0) sacc[n][0] = -1e30f;
                if (col + 1 > row0) sacc[n][1] = -1e30f;
                if (col     > row1) sacc[n][2] = -1e30f;
                if (col + 1 > row1) sacc[n][3] = -1e30f;
            }
        }

        float mx0 = -1e30f, mx1 = -1e30f;
#pragma unroll
        for (int n = 0; n < 8; n++) {
            mx0 = fmaxf(mx0, fmaxf(sacc[n][0], sacc[n][1]));
            mx1 = fmaxf(mx1, fmaxf(sacc[n][2], sacc[n][3]));
        }
        mx0 = fmaxf(mx0, __shfl_xor_sync(0xffffffffu, mx0, 1));
        mx0 = fmaxf(mx0, __shfl_xor_sync(0xffffffffu, mx0, 2));
        mx1 = fmaxf(mx1, __shfl_xor_sync(0xffffffffu, mx1, 1));
        mx1 = fmaxf(mx1, __shfl_xor_sync(0xffffffffu, mx1, 2));

        float mn0 = fmaxf(m0, mx0), mn1 = fmaxf(m1, mx1);
        float al0 = __expf(m0 - mn0), al1 = __expf(m1 - mn1);
        m0 = mn0; m1 = mn1;
        l0 *= al0; l1 *= al1;

        float* ps0 = ps_ + (rb + g) * PS_STRIDE + 2 * tig;
        float* ps1 = ps0 + 8 * PS_STRIDE;
#pragma unroll
        for (int n = 0; n < 8; n++) {
            float p0 = __expf(sacc[n][0] - mn0);
            float p1 = __expf(sacc[n][1] - mn0);
            float p2 = __expf(sacc[n][2] - mn1);
            float p3 = __expf(sacc[n][3] - mn1);
            l0 += p0 + p1;
            l1 += p2 + p3;
            uint2 u01 = make_uint2(f32_to_tf32_rna_u(p0), f32_to_tf32_rna_u(p1));
            uint2 u23 = make_uint2(f32_to_tf32_rna_u(p2), f32_to_tf32_rna_u(p3));
            *reinterpret_cast<uint2*>(ps0 + n * 8) = u01;
            *reinterpret_cast<uint2*>(ps1 + n * 8) = u23;
            oacc[n][0] *= al0; oacc[n][1] *= al0;
            oacc[n][2] *= al1; oacc[n][3] *= al1;
        }
        __syncwarp();

#pragma unroll
        for (int ks8 = 0; ks8 < 8; ks8++) {
            const float* pp = ps_ + (rb + g) * PS_STRIDE + ks8 * 8 + tig;
            uint32_t pa0 = __float_as_uint(pp[0]);
            uint32_t pa1 = __float_as_uint(pp[8 * PS_STRIDE]);
            uint32_t pa2 = __float_as_uint(pp[4]);
            uint32_t pa3 = __float_as_uint(pp[8 * PS_STRIDE + 4]);
#pragma unroll
            for (int n = 0; n < 8; n++) {
                const float* vp = vs_ + (ks8 * 8 + tig) * VS_STRIDE + n * 8 + g;
                mma_tf32(oacc[n], pa0, pa1, pa2, pa3,
                         __float_as_uint(vp[0]), __float_as_uint(vp[4 * VS_STRIDE]));
            }
        }
    }

    l0 += __shfl_xor_sync(0xffffffffu, l0, 1);
    l0 += __shfl_xor_sync(0xffffffffu, l0, 2);
    l1 += __shfl_xor_sync(0xffffffffu, l1, 1);
    l1 += __shfl_xor_sync(0xffffffffu, l1, 2);
    float inv0 = 1.f / l0, inv1 = 1.f / l1;

    uint2* o0 = reinterpret_cast<uint2*>(o + (tokBase + q0 + rb + g) * DM + h * DK + 2 * tig);
    uint2* o1 = reinterpret_cast<uint2*>(o + (tokBase + q0 + rb + g + 8) * DM + h * DK + 2 * tig);
#pragma unroll
    for (int n = 0; n < 8; n++) {
        o0[n * 4] = make_uint2(f32_to_tf32_rna_u(oacc[n][0] * inv0),
                               f32_to_tf32_rna_u(oacc[n][1] * inv0));
        o1[n * 4] = make_uint2(f32_to_tf32_rna_u(oacc[n][2] * inv1),
                               f32_to_tf32_rna_u(oacc[n][3] * inv1));
    }
}

// ---------------- launch ----------------
extern "C" void kernel_launch(void* const* d_in, const int* in_sizes, int n_in,
                              void* d_out, int out_size) {
    const float* x  = (const float*)d_in[0];
    const int*   tp = (const int*)  d_in[1];
    const float* Qw = (const float*)d_in[2];
    const float* Kw = (const float*)d_in[3];
    const float* Vw = (const float*)d_in[4];
    const float* Ow = (const float*)d_in[5];
    float* out = (float*)d_out;

    float *gq, *gk, *gv, *gao, *gxc, *gwqkv, *gwo;
    cudaGetSymbolAddress((void**)&gq,    g_q);
    cudaGetSymbolAddress((void**)&gk,    g_k);
    cudaGetSymbolAddress((void**)&gv,    g_v);
    cudaGetSymbolAddress((void**)&gao,   g_ao);
    cudaGetSymbolAddress((void**)&gxc,   g_xc);
    cudaGetSymbolAddress((void**)&gwqkv, g_wqkv);
    cudaGetSymbolAddress((void**)&gwo,   g_wo);

    cudaFuncSetAttribute(gemm_tf32, cudaFuncAttributeMaxDynamicSharedMemorySize, GEMM_SMEM_BYTES);
    cudaFuncSetAttribute(gemm_qkv,  cudaFuncAttributeMaxDynamicSharedMemorySize, GEMM_SMEM_BYTES);
    const int flash_smem = FS_TOTAL * 4;
    cudaFuncSetAttribute(flash_mma, cudaFuncAttributeMaxDynamicSharedMemorySize, flash_smem);

    // pre-round inputs
    {
        int n4 = (int)(MTOK * (size_t)DM / 4);
        cvt_tf32_kernel<<<(n4 + 255) / 256, 256>>>(x, gxc, n4);
        int p4 = 3 * DM * DM / 4;
        pack_qkv_w<<<(p4 + 255) / 256, 256>>>(Qw, Kw, Vw, gwqkv);
        int w4 = DM * DM / 4;
        cvt_tf32_kernel<<<(w4 + 255) / 256, 256>>>(Ow, gwo, w4);
    }

    // fused QKV projection + RoPE
    dim3 qgrid(3 * DM / GBN, MTOK / GBM);   // (24, 64)
    gemm_qkv<<<qgrid, 256, GEMM_SMEM_BYTES>>>(gxc, gwqkv, tp, gq, gk, gv);

    // attention
    dim3 fgrid(SD / FQT, NH, BD);           // (32, 16, 4)
    flash_mma<<<fgrid, 128, flash_smem>>>(gq, gk, gv, gao);

    // output projection
    dim3 ggrid(DM / GBN, MTOK / GBM);       // (8, 64)
    gemm_tf32<<<ggrid, 256, GEMM_SMEM_BYTES>>>(gao, gwo, out);
}

// round 10
// speedup vs baseline: 9.0000x; 2.1911x over previous
#include <cuda_runtime.h>
#include <cuda_fp16.h>
#include <math.h>
#include <stdint.h>

// Problem constants
#define BD 4
#define SD 2048
#define DM 1024
#define NH 16
#define DK 64
#define MTOK (BD*SD)   // 8192 tokens

// ---------------- scratch (static device memory: allowed) ----------------
__device__ __half g_q   [(size_t)MTOK * DM];
__device__ __half g_k   [(size_t)MTOK * DM];
__device__ __half g_v   [(size_t)MTOK * DM];
__device__ __half g_ao  [(size_t)MTOK * DM];
__device__ __half g_xc  [(size_t)MTOK * DM];       // x pre-rounded to fp16
__device__ __half g_wqkv[(size_t)3 * DM * DM];     // [Qw;Kw;Vw] fp16
__device__ __half g_wo  [(size_t)DM * DM];         // Ow fp16

__device__ __forceinline__ uint32_t smem_u32(const void* p) {
    uint32_t a;
    asm("{ .reg .u64 t; cvta.to.shared.u64 t, %1; cvt.u32.u64 %0, t; }" : "=r"(a) : "l"(p));
    return a;
}

__device__ __forceinline__ void cp_async16(uint32_t dst, const void* src) {
    asm volatile("cp.async.cg.shared.global [%0], [%1], 16;" :: "r"(dst), "l"(src));
}
#define CP_COMMIT() asm volatile("cp.async.commit_group;" ::: "memory")
#define CP_WAIT1()  asm volatile("cp.async.wait_group 1;" ::: "memory")

__device__ __forceinline__ void mma_f16(float* c, uint32_t a0, uint32_t a1,
                                        uint32_t a2, uint32_t a3,
                                        uint32_t b0, uint32_t b1) {
    asm volatile(
        "mma.sync.aligned.m16n8k16.row.col.f32.f16.f16.f32 "
        "{%0,%1,%2,%3}, {%4,%5,%6,%7}, {%8,%9}, {%0,%1,%2,%3};"
        : "+f"(c[0]), "+f"(c[1]), "+f"(c[2]), "+f"(c[3])
        : "r"(a0), "r"(a1), "r"(a2), "r"(a3), "r"(b0), "r"(b1));
}

__device__ __forceinline__ uint32_t lds_u32(const __half* p) {
    return *reinterpret_cast<const uint32_t*>(p);
}

// ---------------- pre-round kernels (fp32 -> fp16) ----------------
__global__ void cvt_f16_kernel(const float* __restrict__ src,
                               __half* __restrict__ dst, int n4) {
    int i = blockIdx.x * blockDim.x + threadIdx.x;
    if (i >= n4) return;
    float4 v = reinterpret_cast<const float4*>(src)[i];
    __half2* d = reinterpret_cast<__half2*>(dst) + 2 * i;
    d[0] = __floats2half2_rn(v.x, v.y);
    d[1] = __floats2half2_rn(v.z, v.w);
}

__global__ void pack_qkv_w(const float* __restrict__ Qw,
                           const float* __restrict__ Kw,
                           const float* __restrict__ Vw,
                           __half* __restrict__ dst) {
    const int W4 = DM * DM / 4;
    int i = blockIdx.x * blockDim.x + threadIdx.x;
    if (i >= 3 * W4) return;
    const float* src = (i < W4) ? Qw : (i < 2 * W4 ? Kw : Vw);
    int li = i - (i < W4 ? 0 : (i < 2 * W4 ? W4 : 2 * W4));
    float4 v = reinterpret_cast<const float4*>(src)[li];
    __half2* d = reinterpret_cast<__half2*>(dst) + 2 * i;
    d[0] = __floats2half2_rn(v.x, v.y);
    d[1] = __floats2half2_rn(v.z, v.w);
}

// ======================================================================
// fp16 mma GEMM core: CTA 128x128, 8 warps, warp 64x32, K-chunk 64 halfs,
// 2-stage cp.async, 2 CTAs/SM.
// ======================================================================
#define GBM 128
#define GBN 128
#define GBK 64
#define LDSWH 72                          // halfs per smem row
#define TILE_HALFS (GBM * LDSWH)          // 9216
#define NCHUNK (DM / GBK)                 // 16
#define STAGE_HALFS (2 * TILE_HALFS)
#define GEMM_SMEM_BYTES (2 * STAGE_HALFS * 2)   // 73728

__device__ __forceinline__ void gemm_mainloop(
    const __half* __restrict__ A, const __half* __restrict__ W,
    __half* smem, uint32_t sbase, int bm, int bng,
    int tid, int wm, int wn, int g, int tig,
    float acc[4][4][4])
{
    const int row = tid >> 1;
    const int seg = tid & 1;                    // 32-half (64B) segment
    const __half* Ap = A + (size_t)(bm + row) * DM + seg * 32;
    const __half* Wp = W + (size_t)(bng + row) * DM + seg * 32;
    const uint32_t sdoff = (uint32_t)(row * LDSWH + seg * 32) * 2u;   // bytes

#pragma unroll
    for (int s = 0; s < 2; s++) {
        const uint32_t ab = sbase + (uint32_t)s * (STAGE_HALFS * 2);
        const __half* ap = Ap + s * GBK;
        const __half* wp = Wp + s * GBK;
#pragma unroll
        for (int i = 0; i < 4; i++) {
            cp_async16(ab + sdoff + i * 16, ap + i * 8);
            cp_async16(ab + TILE_HALFS * 2 + sdoff + i * 16, wp + i * 8);
        }
        CP_COMMIT();
    }

    const int aoff = (wm * 64 + g) * LDSWH + 2 * tig;
    const int boff = (wn * 32 + g) * LDSWH + 2 * tig;

    for (int kt = 0; kt < NCHUNK; kt++) {
        CP_WAIT1();
        __syncthreads();

        const __half* aB = smem + (kt & 1) * STAGE_HALFS + aoff;
        const __half* bB = smem + (kt & 1) * STAGE_HALFS + TILE_HALFS + boff;
#pragma unroll
        for (int ks = 0; ks < 4; ks++) {      // 4 x k16
            uint32_t af[4][4];
#pragma unroll
            for (int mt = 0; mt < 4; mt++) {
                const __half* p = aB + mt * (16 * LDSWH) + ks * 16;
                af[mt][0] = lds_u32(p);
                af[mt][1] = lds_u32(p + 8 * LDSWH);
                af[mt][2] = lds_u32(p + 8);
                af[mt][3] = lds_u32(p + 8 * LDSWH + 8);
            }
            uint32_t bf[4][2];
#pragma unroll
            for (int nt = 0; nt < 4; nt++) {
                const __half* p = bB + nt * (8 * LDSWH) + ks * 16;
                bf[nt][0] = lds_u32(p);
                bf[nt][1] = lds_u32(p + 8);
            }
#pragma unroll
            for (int mt = 0; mt < 4; mt++)
#pragma unroll
                for (int nt = 0; nt < 4; nt++)
                    mma_f16(acc[mt][nt], af[mt][0], af[mt][1], af[mt][2], af[mt][3],
                            bf[nt][0], bf[nt][1]);
        }

        __syncthreads();

        if (kt + 2 < NCHUNK) {
            const uint32_t ab = sbase + (uint32_t)(kt & 1) * (STAGE_HALFS * 2);
            const __half* ap = Ap + (kt + 2) * GBK;
            const __half* wp = Wp + (kt + 2) * GBK;
#pragma unroll
            for (int i = 0; i < 4; i++) {
                cp_async16(ab + sdoff + i * 16, ap + i * 8);
                cp_async16(ab + TILE_HALFS * 2 + sdoff + i * 16, wp + i * 8);
            }
        }
        CP_COMMIT();
    }
}

// ---------------- O-projection GEMM (half in, float out) ----------------
__global__ __launch_bounds__(256, 2)
void gemm_f16(const __half* __restrict__ A,
              const __half* __restrict__ W,
              float* __restrict__ C) {
    extern __shared__ __half smemh[];
    const uint32_t sbase = smem_u32(smemh);
    const int tid  = threadIdx.x;
    const int wid  = tid >> 5;
    const int lane = tid & 31;
    const int bm = blockIdx.y * GBM;
    const int bn = blockIdx.x * GBN;
    const int wm = wid >> 2, wn = wid & 3;
    const int g = lane >> 2, tig = lane & 3;

    float acc[4][4][4];
#pragma unroll
    for (int i = 0; i < 4; i++)
#pragma unroll
        for (int j = 0; j < 4; j++)
#pragma unroll
            for (int r2 = 0; r2 < 4; r2++) acc[i][j][r2] = 0.f;

    gemm_mainloop(A, W, smemh, sbase, bm, bn, tid, wm, wn, g, tig, acc);

    const int m0 = bm + wm * 64 + g;
    const int n0 = bn + wn * 32 + 2 * tig;
#pragma unroll
    for (int mt = 0; mt < 4; mt++) {
#pragma unroll
        for (int nt = 0; nt < 4; nt++) {
            float* p0 = C + (size_t)(m0 + mt * 16) * DM + n0 + nt * 8;
            float* p1 = p0 + 8 * DM;
            *reinterpret_cast<float2*>(p0) = make_float2(acc[mt][nt][0], acc[mt][nt][1]);
            *reinterpret_cast<float2*>(p1) = make_float2(acc[mt][nt][2], acc[mt][nt][3]);
        }
    }
}

// ---------------- fused QKV GEMM + RoPE + scale -> fp16 outputs ----------------
__global__ __launch_bounds__(256, 2)
void gemm_qkv(const __half* __restrict__ A,
              const __half* __restrict__ W,   // [3072,1024]
              const int*    __restrict__ pos, // [8192]
              __half* __restrict__ outq,
              __half* __restrict__ outk,
              __half* __restrict__ outv) {
    extern __shared__ __half smemh[];
    const uint32_t sbase = smem_u32(smemh);
    const int tid  = threadIdx.x;
    const int wid  = tid >> 5;
    const int lane = tid & 31;
    const int bm  = blockIdx.y * GBM;
    const int bng = blockIdx.x * GBN;
    const int wm = wid >> 2, wn = wid & 3;
    const int g = lane >> 2, tig = lane & 3;

    float acc[4][4][4];
#pragma unroll
    for (int i = 0; i < 4; i++)
#pragma unroll
        for (int j = 0; j < 4; j++)
#pragma unroll
            for (int r2 = 0; r2 < 4; r2++) acc[i][j][r2] = 0.f;

    gemm_mainloop(A, W, smemh, sbase, bm, bng, tid, wm, wn, g, tig, acc);

    const int region = blockIdx.x >> 3;        // 0=q, 1=k, 2=v
    __half* dst = (region == 0) ? outq : (region == 1 ? outk : outv);
    const int nbase = (blockIdx.x & 7) * GBN;
    const int m0 = bm + wm * 64 + g;
    const int n0 = nbase + wn * 32 + 2 * tig;

    if (region < 2) {
        const float scale = (region == 0) ? 0.125f : 1.0f;
        const float lt = 0.1439115683121279f;   // ln(10000)/64
        float invf[4];
#pragma unroll
        for (int nt = 0; nt < 4; nt++) {
            int c = (n0 + nt * 8) & (DK - 1);
            invf[nt] = __expf(-(float)c * lt);
        }
#pragma unroll
        for (int mt = 0; mt < 4; mt++) {
            const int r0 = m0 + mt * 16;
            const float p0 = (float)pos[r0];
            const float p1 = (float)pos[r0 + 8];
#pragma unroll
            for (int nt = 0; nt < 4; nt++) {
                float s0, c0, s1, c1;
                sincosf(p0 * invf[nt], &s0, &c0);
                sincosf(p1 * invf[nt], &s1, &c1);
                float e0 = acc[mt][nt][0], o0v = acc[mt][nt][1];
                float e1 = acc[mt][nt][2], o1v = acc[mt][nt][3];
                acc[mt][nt][0] = (e0 * c0 - o0v * s0) * scale;
                acc[mt][nt][1] = (e0 * s0 + o0v * c0) * scale;
                acc[mt][nt][2] = (e1 * c1 - o1v * s1) * scale;
                acc[mt][nt][3] = (e1 * s1 + o1v * c1) * scale;
            }
        }
    }

#pragma unroll
    for (int mt = 0; mt < 4; mt++) {
#pragma unroll
        for (int nt = 0; nt < 4; nt++) {
            __half2* p0 = reinterpret_cast<__half2*>(dst + (size_t)(m0 + mt * 16) * DM + n0 + nt * 8);
            __half2* p1 = reinterpret_cast<__half2*>(dst + (size_t)(m0 + mt * 16 + 8) * DM + n0 + nt * 8);
            *p0 = __floats2half2_rn(acc[mt][nt][0], acc[mt][nt][1]);
            *p1 = __floats2half2_rn(acc[mt][nt][2], acc[mt][nt][3]);
        }
    }
}

// ======================================================================
// fp16 mma causal flash attention.
// CTA: 64 q-rows of one (b,h); 4 warps; key tile 64.
// QK^T / P.V via m16n8k16; V B-frags via ldmatrix.x4.trans.
// ======================================================================
#define FQT 64
#define FKT 64
#define SH 72                      // halfs per smem row (all three tiles)
#define FS_KS 0
#define FS_VS (64 * SH)
#define FS_PS (2 * 64 * SH)
#define FS_TOTAL (3 * 64 * SH)     // 13824 halfs = 27648 B

__global__ __launch_bounds__(128)
void flash_mma(const __half* __restrict__ q,
               const __half* __restrict__ k,
               const __half* __restrict__ v,
               __half* __restrict__ o) {
    extern __shared__ __half fsm[];
    __half* ks_ = fsm + FS_KS;
    __half* vs_ = fsm + FS_VS;
    __half* ps_ = fsm + FS_PS;
    const uint32_t vs_u = smem_u32(fsm) + FS_VS * 2;

    const int tid  = threadIdx.x;
    const int w    = tid >> 5;
    const int lane = tid & 31;
    const int g    = lane >> 2;
    const int tig  = lane & 3;
    const int qb = gridDim.x - 1 - blockIdx.x;   // heavy tiles first
    const int h  = blockIdx.y;
    const int b  = blockIdx.z;
    const int q0 = qb * FQT;
    const size_t tokBase = (size_t)b * SD;
    const int rb = w * 16;

    // ---- stage Q tile through ps_, load a-frags (4 k16 steps) ----
    {
        const __half* qbase = q + (tokBase + q0) * DM + h * DK;
#pragma unroll
        for (int i = 0; i < 16; i++) {
            int j = tid + 128 * i;          // 64 rows x 32 half2
            int r = j >> 5, c2 = j & 31;
            __half2 t2 = *reinterpret_cast<const __half2*>(qbase + (size_t)r * DM + 2 * c2);
            *reinterpret_cast<__half2*>(ps_ + r * SH + 2 * c2) = t2;
        }
    }
    __syncthreads();
    uint32_t qa[4][4];
#pragma unroll
    for (int ks = 0; ks < 4; ks++) {
        const __half* p = ps_ + (rb + g) * SH + ks * 16 + 2 * tig;
        qa[ks][0] = lds_u32(p);
        qa[ks][1] = lds_u32(p + 8 * SH);
        qa[ks][2] = lds_u32(p + 8);
        qa[ks][3] = lds_u32(p + 8 * SH + 8);
    }

    float m0 = -1e30f, m1 = -1e30f, l0 = 0.f, l1 = 0.f;
    float oacc[8][4];
#pragma unroll
    for (int n = 0; n < 8; n++)
#pragma unroll
        for (int c = 0; c < 4; c++) oacc[n][c] = 0.f;

    const int ntiles = q0 / FKT + 1;
    for (int kt = 0; kt < ntiles; kt++) {
        const int k0 = kt * FKT;
        __syncthreads();
        const __half* kbase = k + (tokBase + k0) * DM + h * DK;
        const __half* vbase = v + (tokBase + k0) * DM + h * DK;
#pragma unroll
        for (int i = 0; i < 16; i++) {
            int j = tid + 128 * i;
            int r = j >> 5, c2 = j & 31;
            __half2 kk = *reinterpret_cast<const __half2*>(kbase + (size_t)r * DM + 2 * c2);
            __half2 vv = *reinterpret_cast<const __half2*>(vbase + (size_t)r * DM + 2 * c2);
            *reinterpret_cast<__half2*>(ks_ + r * SH + 2 * c2) = kk;
            *reinterpret_cast<__half2*>(vs_ + r * SH + 2 * c2) = vv;
        }
        __syncthreads();

        // ---- QK^T ----
        float sacc[8][4];
#pragma unroll
        for (int n = 0; n < 8; n++)
#pragma unroll
            for (int c = 0; c < 4; c++) sacc[n][c] = 0.f;
#pragma unroll
        for (int ks = 0; ks < 4; ks++) {
#pragma unroll
            for (int n = 0; n < 8; n++) {
                const __half* kp = ks_ + (n * 8 + g) * SH + ks * 16 + 2 * tig;
                mma_f16(sacc[n], qa[ks][0], qa[ks][1], qa[ks][2], qa[ks][3],
                        lds_u32(kp), lds_u32(kp + 8));
            }
        }

        // ---- causal mask on diagonal tile ----
        if (k0 == q0) {
            const int row0 = q0 + rb + g;
            const int row1 = row0 + 8;
#pragma unroll
            for (int n = 0; n < 8; n++) {
                int col = k0 + n * 8 + 2 * tig;
                if (col     > row0) sacc[n][0] = -1e30f;
                if (col + 1 > row0) sacc[n][1] = -1e30f;
                if (col     > row1) sacc[n][2] = -1e30f;
                if (col + 1 > row1) sacc[n][3] = -1e30f;
            }
        }

        // ---- online softmax ----
        float mx0 = -1e30f, mx1 = -1e30f;
#pragma unroll
        for (int n = 0; n < 8; n++) {
            mx0 = fmaxf(mx0, fmaxf(sacc[n][0], sacc[n][1]));
            mx1 = fmaxf(mx1, fmaxf(sacc[n][2], sacc[n][3]));
        }
        mx0 = fmaxf(mx0, __shfl_xor_sync(0xffffffffu, mx0, 1));
        mx0 = fmaxf(mx0, __shfl_xor_sync(0xffffffffu, mx0, 2));
        mx1 = fmaxf(mx1, __shfl_xor_sync(0xffffffffu, mx1, 1));
        mx1 = fmaxf(mx1, __shfl_xor_sync(0xffffffffu, mx1, 2));

        float mn0 = fmaxf(m0, mx0), mn1 = fmaxf(m1, mx1);
        float al0 = __expf(m0 - mn0), al1 = __expf(m1 - mn1);
        m0 = mn0; m1 = mn1;
        l0 *= al0; l1 *= al1;

        __half* ps0 = ps_ + (rb + g) * SH + 2 * tig;
        __half* ps1 = ps0 + 8 * SH;
#pragma unroll
        for (int n = 0; n < 8; n++) {
            float p0 = __expf(sacc[n][0] - mn0);
            float p1 = __expf(sacc[n][1] - mn0);
            float p2 = __expf(sacc[n][2] - mn1);
            float p3 = __expf(sacc[n][3] - mn1);
            l0 += p0 + p1;
            l1 += p2 + p3;
            *reinterpret_cast<__half2*>(ps0 + n * 8) = __floats2half2_rn(p0, p1);
            *reinterpret_cast<__half2*>(ps1 + n * 8) = __floats2half2_rn(p2, p3);
            oacc[n][0] *= al0; oacc[n][1] *= al0;
            oacc[n][2] *= al1; oacc[n][3] *= al1;
        }
        __syncwarp();

        // ---- P . V  (V b-frags via ldmatrix.x4.trans) ----
#pragma unroll
        for (int ks = 0; ks < 4; ks++) {       // 16 keys per step
            const __half* pp = ps_ + (rb + g) * SH + ks * 16 + 2 * tig;
            uint32_t pa0 = lds_u32(pp);
            uint32_t pa1 = lds_u32(pp + 8 * SH);
            uint32_t pa2 = lds_u32(pp + 8);
            uint32_t pa3 = lds_u32(pp + 8 * SH + 8);
#pragma unroll
            for (int dblk = 0; dblk < 4; dblk++) {   // 16 d per block -> 2 ntiles
                uint32_t addr = vs_u +
                    (uint32_t)((ks * 16 + (lane & 15)) * SH + dblk * 16 + ((lane >> 4) << 3)) * 2u;
                uint32_t r0, r1, r2, r3;
                asm volatile(
                    "ldmatrix.sync.aligned.m8n8.x4.trans.shared.b16 {%0,%1,%2,%3}, [%4];"
                    : "=r"(r0), "=r"(r1), "=r"(r2), "=r"(r3) : "r"(addr));
                mma_f16(oacc[2 * dblk],     pa0, pa1, pa2, pa3, r0, r1);
                mma_f16(oacc[2 * dblk + 1], pa0, pa1, pa2, pa3, r2, r3);
            }
        }
    }

    // ---- epilogue ----
    l0 += __shfl_xor_sync(0xffffffffu, l0, 1);
    l0 += __shfl_xor_sync(0xffffffffu, l0, 2);
    l1 += __shfl_xor_sync(0xffffffffu, l1, 1);
    l1 += __shfl_xor_sync(0xffffffffu, l1, 2);
    float inv0 = 1.f / l0, inv1 = 1.f / l1;

    __half* o0 = o + (tokBase + q0 + rb + g) * DM + h * DK + 2 * tig;
    __half* o1 = o + (tokBase + q0 + rb + g + 8) * DM + h * DK + 2 * tig;
#pragma unroll
    for (int n = 0; n < 8; n++) {
        *reinterpret_cast<__half2*>(o0 + n * 8) =
            __floats2half2_rn(oacc[n][0] * inv0, oacc[n][1] * inv0);
        *reinterpret_cast<__half2*>(o1 + n * 8) =
            __floats2half2_rn(oacc[n][2] * inv1, oacc[n][3] * inv1);
    }
}

// ---------------- launch ----------------
extern "C" void kernel_launch(void* const* d_in, const int* in_sizes, int n_in,
                              void* d_out, int out_size) {
    const float* x  = (const float*)d_in[0];
    const int*   tp = (const int*)  d_in[1];
    const float* Qw = (const float*)d_in[2];
    const float* Kw = (const float*)d_in[3];
    const float* Vw = (const float*)d_in[4];
    const float* Ow = (const float*)d_in[5];
    float* out = (float*)d_out;

    __half *gq, *gk, *gv, *gao, *gxc, *gwqkv, *gwo;
    cudaGetSymbolAddress((void**)&gq,    g_q);
    cudaGetSymbolAddress((void**)&gk,    g_k);
    cudaGetSymbolAddress((void**)&gv,    g_v);
    cudaGetSymbolAddress((void**)&gao,   g_ao);
    cudaGetSymbolAddress((void**)&gxc,   g_xc);
    cudaGetSymbolAddress((void**)&gwqkv, g_wqkv);
    cudaGetSymbolAddress((void**)&gwo,   g_wo);

    cudaFuncSetAttribute(gemm_f16, cudaFuncAttributeMaxDynamicSharedMemorySize, GEMM_SMEM_BYTES);
    cudaFuncSetAttribute(gemm_qkv, cudaFuncAttributeMaxDynamicSharedMemorySize, GEMM_SMEM_BYTES);
    const int flash_smem = FS_TOTAL * 2;    // 27648
    cudaFuncSetAttribute(flash_mma, cudaFuncAttributeMaxDynamicSharedMemorySize, flash_smem);

    // pre-round inputs to fp16
    {
        int n4 = (int)(MTOK * (size_t)DM / 4);
        cvt_f16_kernel<<<(n4 + 255) / 256, 256>>>(x, gxc, n4);
        int p4 = 3 * DM * DM / 4;
        pack_qkv_w<<<(p4 + 255) / 256, 256>>>(Qw, Kw, Vw, gwqkv);
        int w4 = DM * DM / 4;
        cvt_f16_kernel<<<(w4 + 255) / 256, 256>>>(Ow, gwo, w4);
    }

    // fused QKV projection + RoPE
    dim3 qgrid(3 * DM / GBN, MTOK / GBM);   // (24, 64)
    gemm_qkv<<<qgrid, 256, GEMM_SMEM_BYTES>>>(gxc, gwqkv, tp, gq, gk, gv);

    // attention
    dim3 fgrid(SD / FQT, NH, BD);           // (32, 16, 4)
    flash_mma<<<fgrid, 128, flash_smem>>>(gq, gk, gv, gao);

    // output projection (half in, float out)
    dim3 ggrid(DM / GBN, MTOK / GBM);       // (8, 64)
    gemm_f16<<<ggrid, 256, GEMM_SMEM_BYTES>>>(gao, gwo, out);
}

// round 11
// speedup vs baseline: 9.7502x; 1.0834x over previous
#include <cuda_runtime.h>
#include <cuda_fp16.h>
#include <math.h>
#include <stdint.h>

// Problem constants
#define BD 4
#define SD 2048
#define DM 1024
#define NH 16
#define DK 64
#define MTOK (BD*SD)   // 8192 tokens

// ---------------- scratch (static device memory: allowed) ----------------
__device__ __half g_q   [(size_t)MTOK * DM];
__device__ __half g_k   [(size_t)MTOK * DM];
__device__ __half g_v   [(size_t)MTOK * DM];
__device__ __half g_ao  [(size_t)MTOK * DM];
__device__ __half g_xc  [(size_t)MTOK * DM];
__device__ __half g_wqkv[(size_t)3 * DM * DM];
__device__ __half g_wo  [(size_t)DM * DM];

__device__ __forceinline__ uint32_t smem_u32(const void* p) {
    uint32_t a;
    asm("{ .reg .u64 t; cvta.to.shared.u64 t, %1; cvt.u32.u64 %0, t; }" : "=r"(a) : "l"(p));
    return a;
}

__device__ __forceinline__ void cp_async16(uint32_t dst, const void* src) {
    asm volatile("cp.async.cg.shared.global [%0], [%1], 16;" :: "r"(dst), "l"(src));
}
#define CP_COMMIT() asm volatile("cp.async.commit_group;" ::: "memory")
#define CP_WAIT1()  asm volatile("cp.async.wait_group 1;" ::: "memory")

__device__ __forceinline__ void mma_f16(float* c, uint32_t a0, uint32_t a1,
                                        uint32_t a2, uint32_t a3,
                                        uint32_t b0, uint32_t b1) {
    asm volatile(
        "mma.sync.aligned.m16n8k16.row.col.f32.f16.f16.f32 "
        "{%0,%1,%2,%3}, {%4,%5,%6,%7}, {%8,%9}, {%0,%1,%2,%3};"
        : "+f"(c[0]), "+f"(c[1]), "+f"(c[2]), "+f"(c[3])
        : "r"(a0), "r"(a1), "r"(a2), "r"(a3), "r"(b0), "r"(b1));
}

__device__ __forceinline__ void ldsm_x4(uint32_t* r, uint32_t addr) {
    asm volatile("ldmatrix.sync.aligned.m8n8.x4.shared.b16 {%0,%1,%2,%3}, [%4];"
        : "=r"(r[0]), "=r"(r[1]), "=r"(r[2]), "=r"(r[3]) : "r"(addr));
}

// ---------------- pre-round kernels (fp32 -> fp16) ----------------
__global__ void cvt_f16_kernel(const float* __restrict__ src,
                               __half* __restrict__ dst, int n4) {
    int i = blockIdx.x * blockDim.x + threadIdx.x;
    if (i >= n4) return;
    float4 v = reinterpret_cast<const float4*>(src)[i];
    __half2* d = reinterpret_cast<__half2*>(dst) + 2 * i;
    d[0] = __floats2half2_rn(v.x, v.y);
    d[1] = __floats2half2_rn(v.z, v.w);
}

__global__ void pack_qkv_w(const float* __restrict__ Qw,
                           const float* __restrict__ Kw,
                           const float* __restrict__ Vw,
                           __half* __restrict__ dst) {
    const int W4 = DM * DM / 4;
    int i = blockIdx.x * blockDim.x + threadIdx.x;
    if (i >= 3 * W4) return;
    const float* src = (i < W4) ? Qw : (i < 2 * W4 ? Kw : Vw);
    int li = i - (i < W4 ? 0 : (i < 2 * W4 ? W4 : 2 * W4));
    float4 v = reinterpret_cast<const float4*>(src)[li];
    __half2* d = reinterpret_cast<__half2*>(dst) + 2 * i;
    d[0] = __floats2half2_rn(v.x, v.y);
    d[1] = __floats2half2_rn(v.z, v.w);
}

// ======================================================================
// fp16 mma GEMM core: CTA 128x128, 8 warps, warp 64x32, K-chunk 64 halfs,
// 2-stage cp.async, 2 CTAs/SM, ldmatrix fragment loads.
// ======================================================================
#define GBM 128
#define GBN 128
#define GBK 64
#define LDSWH 72
#define TILE_HALFS (GBM * LDSWH)          // 9216
#define NCHUNK (DM / GBK)                 // 16
#define STAGE_HALFS (2 * TILE_HALFS)
#define GEMM_SMEM_BYTES (2 * STAGE_HALFS * 2)   // 73728

__device__ __forceinline__ void gemm_mainloop(
    const __half* __restrict__ A, const __half* __restrict__ W,
    uint32_t sbase, int bm, int bng,
    int tid, int wm, int wn, int lane,
    float acc[4][4][4])
{
    const int row = tid >> 1;
    const int seg = tid & 1;
    const __half* Ap = A + (size_t)(bm + row) * DM + seg * 32;
    const __half* Wp = W + (size_t)(bng + row) * DM + seg * 32;
    const uint32_t sdoff = (uint32_t)(row * LDSWH + seg * 32) * 2u;

#pragma unroll
    for (int s = 0; s < 2; s++) {
        const uint32_t ab = sbase + (uint32_t)s * (STAGE_HALFS * 2);
        const __half* ap = Ap + s * GBK;
        const __half* wp = Wp + s * GBK;
#pragma unroll
        for (int i = 0; i < 4; i++) {
            cp_async16(ab + sdoff + i * 16, ap + i * 8);
            cp_async16(ab + TILE_HALFS * 2 + sdoff + i * 16, wp + i * 8);
        }
        CP_COMMIT();
    }

    // per-lane ldmatrix base addresses (bytes)
    const int lr   = lane & 7;
    const int quad = lane >> 3;
    const uint32_t aAddr0 = sbase +
        (uint32_t)((wm * 64 + (quad & 1) * 8 + lr) * LDSWH + (quad >> 1) * 8) * 2u;
    const uint32_t bAddr0 = sbase + TILE_HALFS * 2 +
        (uint32_t)((wn * 32 + (quad >> 1) * 8 + lr) * LDSWH + (quad & 1) * 8) * 2u;

    for (int kt = 0; kt < NCHUNK; kt++) {
        CP_WAIT1();
        __syncthreads();

        const uint32_t sb = (uint32_t)(kt & 1) * (STAGE_HALFS * 2);
#pragma unroll
        for (int ks = 0; ks < 4; ks++) {
            uint32_t af[4][4];
#pragma unroll
            for (int mt = 0; mt < 4; mt++)
                ldsm_x4(af[mt], aAddr0 + sb + (uint32_t)(mt * (16 * LDSWH) + ks * 16) * 2u);
            uint32_t bf01[4], bf23[4];
            ldsm_x4(bf01, bAddr0 + sb + (uint32_t)(ks * 16) * 2u);
            ldsm_x4(bf23, bAddr0 + sb + (uint32_t)(16 * LDSWH + ks * 16) * 2u);
#pragma unroll
            for (int mt = 0; mt < 4; mt++) {
                mma_f16(acc[mt][0], af[mt][0], af[mt][1], af[mt][2], af[mt][3], bf01[0], bf01[1]);
                mma_f16(acc[mt][1], af[mt][0], af[mt][1], af[mt][2], af[mt][3], bf01[2], bf01[3]);
                mma_f16(acc[mt][2], af[mt][0], af[mt][1], af[mt][2], af[mt][3], bf23[0], bf23[1]);
                mma_f16(acc[mt][3], af[mt][0], af[mt][1], af[mt][2], af[mt][3], bf23[2], bf23[3]);
            }
        }

        __syncthreads();

        if (kt + 2 < NCHUNK) {
            const uint32_t ab = sbase + (uint32_t)(kt & 1) * (STAGE_HALFS * 2);
            const __half* ap = Ap + (kt + 2) * GBK;
            const __half* wp = Wp + (kt + 2) * GBK;
#pragma unroll
            for (int i = 0; i < 4; i++) {
                cp_async16(ab + sdoff + i * 16, ap + i * 8);
                cp_async16(ab + TILE_HALFS * 2 + sdoff + i * 16, wp + i * 8);
            }
        }
        CP_COMMIT();
    }
}

// ---------------- O-projection GEMM (half in, float out) ----------------
__global__ __launch_bounds__(256, 2)
void gemm_f16(const __half* __restrict__ A,
              const __half* __restrict__ W,
              float* __restrict__ C) {
    extern __shared__ __half smemh[];
    const uint32_t sbase = smem_u32(smemh);
    const int tid  = threadIdx.x;
    const int wid  = tid >> 5;
    const int lane = tid & 31;
    const int bm = blockIdx.y * GBM;
    const int bn = blockIdx.x * GBN;
    const int wm = wid >> 2, wn = wid & 3;
    const int g = lane >> 2, tig = lane & 3;

    float acc[4][4][4];
#pragma unroll
    for (int i = 0; i < 4; i++)
#pragma unroll
        for (int j = 0; j < 4; j++)
#pragma unroll
            for (int r2 = 0; r2 < 4; r2++) acc[i][j][r2] = 0.f;

    gemm_mainloop(A, W, sbase, bm, bn, tid, wm, wn, lane, acc);

    const int m0 = bm + wm * 64 + g;
    const int n0 = bn + wn * 32 + 2 * tig;
#pragma unroll
    for (int mt = 0; mt < 4; mt++) {
#pragma unroll
        for (int nt = 0; nt < 4; nt++) {
            float* p0 = C + (size_t)(m0 + mt * 16) * DM + n0 + nt * 8;
            float* p1 = p0 + 8 * DM;
            *reinterpret_cast<float2*>(p0) = make_float2(acc[mt][nt][0], acc[mt][nt][1]);
            *reinterpret_cast<float2*>(p1) = make_float2(acc[mt][nt][2], acc[mt][nt][3]);
        }
    }
}

// ---------------- fused QKV GEMM + RoPE + scale -> fp16 ----------------
__global__ __launch_bounds__(256, 2)
void gemm_qkv(const __half* __restrict__ A,
              const __half* __restrict__ W,
              const int*    __restrict__ pos,
              __half* __restrict__ outq,
              __half* __restrict__ outk,
              __half* __restrict__ outv) {
    extern __shared__ __half smemh[];
    const uint32_t sbase = smem_u32(smemh);
    const int tid  = threadIdx.x;
    const int wid  = tid >> 5;
    const int lane = tid & 31;
    const int bm  = blockIdx.y * GBM;
    const int bng = blockIdx.x * GBN;
    const int wm = wid >> 2, wn = wid & 3;
    const int g = lane >> 2, tig = lane & 3;

    float acc[4][4][4];
#pragma unroll
    for (int i = 0; i < 4; i++)
#pragma unroll
        for (int j = 0; j < 4; j++)
#pragma unroll
            for (int r2 = 0; r2 < 4; r2++) acc[i][j][r2] = 0.f;

    gemm_mainloop(A, W, sbase, bm, bng, tid, wm, wn, lane, acc);

    const int region = blockIdx.x >> 3;
    __half* dst = (region == 0) ? outq : (region == 1 ? outk : outv);
    const int nbase = (blockIdx.x & 7) * GBN;
    const int m0 = bm + wm * 64 + g;
    const int n0 = nbase + wn * 32 + 2 * tig;

    if (region < 2) {
        const float scale = (region == 0) ? 0.125f : 1.0f;
        const float lt = 0.1439115683121279f;
        float invf[4];
#pragma unroll
        for (int nt = 0; nt < 4; nt++) {
            int c = (n0 + nt * 8) & (DK - 1);
            invf[nt] = __expf(-(float)c * lt);
        }
#pragma unroll
        for (int mt = 0; mt < 4; mt++) {
            const int r0 = m0 + mt * 16;
            const float p0 = (float)pos[r0];
            const float p1 = (float)pos[r0 + 8];
#pragma unroll
            for (int nt = 0; nt < 4; nt++) {
                float s0, c0, s1, c1;
                sincosf(p0 * invf[nt], &s0, &c0);
                sincosf(p1 * invf[nt], &s1, &c1);
                float e0 = acc[mt][nt][0], o0v = acc[mt][nt][1];
                float e1 = acc[mt][nt][2], o1v = acc[mt][nt][3];
                acc[mt][nt][0] = (e0 * c0 - o0v * s0) * scale;
                acc[mt][nt][1] = (e0 * s0 + o0v * c0) * scale;
                acc[mt][nt][2] = (e1 * c1 - o1v * s1) * scale;
                acc[mt][nt][3] = (e1 * s1 + o1v * c1) * scale;
            }
        }
    }

#pragma unroll
    for (int mt = 0; mt < 4; mt++) {
#pragma unroll
        for (int nt = 0; nt < 4; nt++) {
            __half2* p0 = reinterpret_cast<__half2*>(dst + (size_t)(m0 + mt * 16) * DM + n0 + nt * 8);
            __half2* p1 = reinterpret_cast<__half2*>(dst + (size_t)(m0 + mt * 16 + 8) * DM + n0 + nt * 8);
            *p0 = __floats2half2_rn(acc[mt][nt][0], acc[mt][nt][1]);
            *p1 = __floats2half2_rn(acc[mt][nt][2], acc[mt][nt][3]);
        }
    }
}

// ======================================================================
// fp16 mma causal flash attention (ldmatrix fragment loads)
// ======================================================================
#define FQT 64
#define FKT 64
#define SH 72
#define FS_KS 0
#define FS_VS (64 * SH)
#define FS_PS (2 * 64 * SH)
#define FS_TOTAL (3 * 64 * SH)     // 27648 B

__global__ __launch_bounds__(128)
void flash_mma(const __half* __restrict__ q,
               const __half* __restrict__ k,
               const __half* __restrict__ v,
               __half* __restrict__ o) {
    extern __shared__ __half fsm[];
    __half* ks_ = fsm + FS_KS;
    __half* vs_ = fsm + FS_VS;
    __half* ps_ = fsm + FS_PS;
    const uint32_t base_u = smem_u32(fsm);
    const uint32_t vs_u = base_u + FS_VS * 2;

    const int tid  = threadIdx.x;
    const int w    = tid >> 5;
    const int lane = tid & 31;
    const int g    = lane >> 2;
    const int tig  = lane & 3;
    const int lr   = lane & 7;
    const int quad = lane >> 3;
    const int qb = gridDim.x - 1 - blockIdx.x;
    const int h  = blockIdx.y;
    const int b  = blockIdx.z;
    const int q0 = qb * FQT;
    const size_t tokBase = (size_t)b * SD;
    const int rb = w * 16;

    // ldmatrix base addrs (bytes)
    const uint32_t aAddr0 = base_u + FS_PS * 2 +
        (uint32_t)((rb + (quad & 1) * 8 + lr) * SH + (quad >> 1) * 8) * 2u;   // P/Q a-frags
    const uint32_t kAddr0 = base_u +
        (uint32_t)(((quad >> 1) * 8 + lr) * SH + (quad & 1) * 8) * 2u;        // K b-frags

    // ---- stage Q tile through ps_, load a-frags ----
    {
        const __half* qbase = q + (tokBase + q0) * DM + h * DK;
#pragma unroll
        for (int i = 0; i < 16; i++) {
            int j = tid + 128 * i;
            int r = j >> 5, c2 = j & 31;
            __half2 t2 = *reinterpret_cast<const __half2*>(qbase + (size_t)r * DM + 2 * c2);
            *reinterpret_cast<__half2*>(ps_ + r * SH + 2 * c2) = t2;
        }
    }
    __syncthreads();
    uint32_t qa[4][4];
#pragma unroll
    for (int ks = 0; ks < 4; ks++)
        ldsm_x4(qa[ks], aAddr0 + (uint32_t)(ks * 16) * 2u);

    float m0 = -1e30f, m1 = -1e30f, l0 = 0.f, l1 = 0.f;
    float oacc[8][4];
#pragma unroll
    for (int n = 0; n < 8; n++)
#pragma unroll
        for (int c = 0; c < 4; c++) oacc[n][c] = 0.f;

    const int ntiles = q0 / FKT + 1;
    for (int kt = 0; kt < ntiles; kt++) {
        const int k0 = kt * FKT;
        __syncthreads();
        const __half* kbase = k + (tokBase + k0) * DM + h * DK;
        const __half* vbase = v + (tokBase + k0) * DM + h * DK;
#pragma unroll
        for (int i = 0; i < 16; i++) {
            int j = tid + 128 * i;
            int r = j >> 5, c2 = j & 31;
            __half2 kk = *reinterpret_cast<const __half2*>(kbase + (size_t)r * DM + 2 * c2);
            __half2 vv = *reinterpret_cast<const __half2*>(vbase + (size_t)r * DM + 2 * c2);
            *reinterpret_cast<__half2*>(ks_ + r * SH + 2 * c2) = kk;
            *reinterpret_cast<__half2*>(vs_ + r * SH + 2 * c2) = vv;
        }
        __syncthreads();

        // ---- QK^T ----
        float sacc[8][4];
#pragma unroll
        for (int n = 0; n < 8; n++)
#pragma unroll
            for (int c = 0; c < 4; c++) sacc[n][c] = 0.f;
#pragma unroll
        for (int ks = 0; ks < 4; ks++) {
#pragma unroll
            for (int np = 0; np < 4; np++) {
                uint32_t kb[4];
                ldsm_x4(kb, kAddr0 + (uint32_t)(np * (16 * SH) + ks * 16) * 2u);
                mma_f16(sacc[2 * np],     qa[ks][0], qa[ks][1], qa[ks][2], qa[ks][3], kb[0], kb[1]);
                mma_f16(sacc[2 * np + 1], qa[ks][0], qa[ks][1], qa[ks][2], qa[ks][3], kb[2], kb[3]);
            }
        }

        // ---- causal mask on diagonal tile ----
        if (k0 == q0) {
            const int row0 = q0 + rb + g;
            const int row1 = row0 + 8;
#pragma unroll
            for (int n = 0; n < 8; n++) {
                int col = k0 + n * 8 + 2 * tig;
                if (col     > row0) sacc[n][0] = -1e30f;
                if (col + 1 > row0) sacc[n][1] = -1e30f;
                if (col     > row1) sacc[n][2] = -1e30f;
                if (col + 1 > row1) sacc[n][3] = -1e30f;
            }
        }

        // ---- online softmax ----
        float mx0 = -1e30f, mx1 = -1e30f;
#pragma unroll
        for (int n = 0; n < 8; n++) {
            mx0 = fmaxf(mx0, fmaxf(sacc[n][0], sacc[n][1]));
            mx1 = fmaxf(mx1, fmaxf(sacc[n][2], sacc[n][3]));
        }
        mx0 = fmaxf(mx0, __shfl_xor_sync(0xffffffffu, mx0, 1));
        mx0 = fmaxf(mx0, __shfl_xor_sync(0xffffffffu, mx0, 2));
        mx1 = fmaxf(mx1, __shfl_xor_sync(0xffffffffu, mx1, 1));
        mx1 = fmaxf(mx1, __shfl_xor_sync(0xffffffffu, mx1, 2));

        float mn0 = fmaxf(m0, mx0), mn1 = fmaxf(m1, mx1);
        float al0 = __expf(m0 - mn0), al1 = __expf(m1 - mn1);
        m0 = mn0; m1 = mn1;
        l0 *= al0; l1 *= al1;

        __half* ps0 = ps_ + (rb + g) * SH + 2 * tig;
        __half* ps1 = ps0 + 8 * SH;
#pragma unroll
        for (int n = 0; n < 8; n++) {
            float p0 = __expf(sacc[n][0] - mn0);
            float p1 = __expf(sacc[n][1] - mn0);
            float p2 = __expf(sacc[n][2] - mn1);
            float p3 = __expf(sacc[n][3] - mn1);
            l0 += p0 + p1;
            l1 += p2 + p3;
            *reinterpret_cast<__half2*>(ps0 + n * 8) = __floats2half2_rn(p0, p1);
            *reinterpret_cast<__half2*>(ps1 + n * 8) = __floats2half2_rn(p2, p3);
            oacc[n][0] *= al0; oacc[n][1] *= al0;
            oacc[n][2] *= al1; oacc[n][3] *= al1;
        }
        __syncwarp();

        // ---- P . V ----
#pragma unroll
        for (int ks = 0; ks < 4; ks++) {
            uint32_t pa[4];
            ldsm_x4(pa, aAddr0 + (uint32_t)(ks * 16) * 2u);
#pragma unroll
            for (int dblk = 0; dblk < 4; dblk++) {
                uint32_t addr = vs_u +
                    (uint32_t)((ks * 16 + (lane & 15)) * SH + dblk * 16 + ((lane >> 4) << 3)) * 2u;
                uint32_t r0, r1, r2, r3;
                asm volatile(
                    "ldmatrix.sync.aligned.m8n8.x4.trans.shared.b16 {%0,%1,%2,%3}, [%4];"
                    : "=r"(r0), "=r"(r1), "=r"(r2), "=r"(r3) : "r"(addr));
                mma_f16(oacc[2 * dblk],     pa[0], pa[1], pa[2], pa[3], r0, r1);
                mma_f16(oacc[2 * dblk + 1], pa[0], pa[1], pa[2], pa[3], r2, r3);
            }
        }
    }

    // ---- epilogue ----
    l0 += __shfl_xor_sync(0xffffffffu, l0, 1);
    l0 += __shfl_xor_sync(0xffffffffu, l0, 2);
    l1 += __shfl_xor_sync(0xffffffffu, l1, 1);
    l1 += __shfl_xor_sync(0xffffffffu, l1, 2);
    float inv0 = 1.f / l0, inv1 = 1.f / l1;

    __half* o0 = o + (tokBase + q0 + rb + g) * DM + h * DK + 2 * tig;
    __half* o1 = o + (tokBase + q0 + rb + g + 8) * DM + h * DK + 2 * tig;
#pragma unroll
    for (int n = 0; n < 8; n++) {
        *reinterpret_cast<__half2*>(o0 + n * 8) =
            __floats2half2_rn(oacc[n][0] * inv0, oacc[n][1] * inv0);
        *reinterpret_cast<__half2*>(o1 + n * 8) =
            __floats2half2_rn(oacc[n][2] * inv1, oacc[n][3] * inv1);
    }
}

// ---------------- launch ----------------
extern "C" void kernel_launch(void* const* d_in, const int* in_sizes, int n_in,
                              void* d_out, int out_size) {
    const float* x  = (const float*)d_in[0];
    const int*   tp = (const int*)  d_in[1];
    const float* Qw = (const float*)d_in[2];
    const float* Kw = (const float*)d_in[3];
    const float* Vw = (const float*)d_in[4];
    const float* Ow = (const float*)d_in[5];
    float* out = (float*)d_out;

    __half *gq, *gk, *gv, *gao, *gxc, *gwqkv, *gwo;
    cudaGetSymbolAddress((void**)&gq,    g_q);
    cudaGetSymbolAddress((void**)&gk,    g_k);
    cudaGetSymbolAddress((void**)&gv,    g_v);
    cudaGetSymbolAddress((void**)&gao,   g_ao);
    cudaGetSymbolAddress((void**)&gxc,   g_xc);
    cudaGetSymbolAddress((void**)&gwqkv, g_wqkv);
    cudaGetSymbolAddress((void**)&gwo,   g_wo);

    cudaFuncSetAttribute(gemm_f16, cudaFuncAttributeMaxDynamicSharedMemorySize, GEMM_SMEM_BYTES);
    cudaFuncSetAttribute(gemm_qkv, cudaFuncAttributeMaxDynamicSharedMemorySize, GEMM_SMEM_BYTES);
    const int flash_smem = FS_TOTAL * 2;
    cudaFuncSetAttribute(flash_mma, cudaFuncAttributeMaxDynamicSharedMemorySize, flash_smem);

    {
        int n4 = (int)(MTOK * (size_t)DM / 4);
        cvt_f16_kernel<<<(n4 + 255) / 256, 256>>>(x, gxc, n4);
        int p4 = 3 * DM * DM / 4;
        pack_qkv_w<<<(p4 + 255) / 256, 256>>>(Qw, Kw, Vw, gwqkv);
        int w4 = DM * DM / 4;
        cvt_f16_kernel<<<(w4 + 255) / 256, 256>>>(Ow, gwo, w4);
    }

    dim3 qgrid(3 * DM / GBN, MTOK / GBM);   // (24, 64)
    gemm_qkv<<<qgrid, 256, GEMM_SMEM_BYTES>>>(gxc, gwqkv, tp, gq, gk, gv);

    dim3 fgrid(SD / FQT, NH, BD);           // (32, 16, 4)
    flash_mma<<<fgrid, 128, flash_smem>>>(gq, gk, gv, gao);

    dim3 ggrid(DM / GBN, MTOK / GBM);       // (8, 64)
    gemm_f16<<<ggrid, 256, GEMM_SMEM_BYTES>>>(gao, gwo, out);
}

// round 12
// speedup vs baseline: 10.0088x; 1.0265x over previous
#include <cuda_runtime.h>
#include <cuda_fp16.h>
#include <math.h>
#include <stdint.h>

// Problem constants
#define BD 4
#define SD 2048
#define DM 1024
#define NH 16
#define DK 64
#define MTOK (BD*SD)   // 8192 tokens

// ---------------- scratch (static device memory: allowed) ----------------
__device__ __half g_q   [(size_t)MTOK * DM];
__device__ __half g_k   [(size_t)MTOK * DM];
__device__ __half g_v   [(size_t)MTOK * DM];
__device__ __half g_ao  [(size_t)MTOK * DM];
__device__ __half g_xc  [(size_t)MTOK * DM];
__device__ __half g_wqkv[(size_t)3 * DM * DM];
__device__ __half g_wo  [(size_t)DM * DM];

__device__ __forceinline__ uint32_t smem_u32(const void* p) {
    uint32_t a;
    asm("{ .reg .u64 t; cvta.to.shared.u64 t, %1; cvt.u32.u64 %0, t; }" : "=r"(a) : "l"(p));
    return a;
}

__device__ __forceinline__ void cp_async16(uint32_t dst, const void* src) {
    asm volatile("cp.async.cg.shared.global [%0], [%1], 16;" :: "r"(dst), "l"(src));
}
#define CP_COMMIT() asm volatile("cp.async.commit_group;" ::: "memory")
#define CP_WAIT1()  asm volatile("cp.async.wait_group 1;" ::: "memory")
#define CP_WAIT0()  asm volatile("cp.async.wait_group 0;" ::: "memory")

__device__ __forceinline__ void mma_f16(float* c, uint32_t a0, uint32_t a1,
                                        uint32_t a2, uint32_t a3,
                                        uint32_t b0, uint32_t b1) {
    asm volatile(
        "mma.sync.aligned.m16n8k16.row.col.f32.f16.f16.f32 "
        "{%0,%1,%2,%3}, {%4,%5,%6,%7}, {%8,%9}, {%0,%1,%2,%3};"
        : "+f"(c[0]), "+f"(c[1]), "+f"(c[2]), "+f"(c[3])
        : "r"(a0), "r"(a1), "r"(a2), "r"(a3), "r"(b0), "r"(b1));
}

__device__ __forceinline__ void ldsm_x4(uint32_t* r, uint32_t addr) {
    asm volatile("ldmatrix.sync.aligned.m8n8.x4.shared.b16 {%0,%1,%2,%3}, [%4];"
        : "=r"(r[0]), "=r"(r[1]), "=r"(r[2]), "=r"(r[3]) : "r"(addr));
}

// ---------------- pre-round kernels (fp32 -> fp16) ----------------
__global__ void cvt_f16_kernel(const float* __restrict__ src,
                               __half* __restrict__ dst, int n4) {
    int i = blockIdx.x * blockDim.x + threadIdx.x;
    if (i >= n4) return;
    float4 v = reinterpret_cast<const float4*>(src)[i];
    __half2* d = reinterpret_cast<__half2*>(dst) + 2 * i;
    d[0] = __floats2half2_rn(v.x, v.y);
    d[1] = __floats2half2_rn(v.z, v.w);
}

__global__ void pack_qkv_w(const float* __restrict__ Qw,
                           const float* __restrict__ Kw,
                           const float* __restrict__ Vw,
                           __half* __restrict__ dst) {
    const int W4 = DM * DM / 4;
    int i = blockIdx.x * blockDim.x + threadIdx.x;
    if (i >= 3 * W4) return;
    const float* src = (i < W4) ? Qw : (i < 2 * W4 ? Kw : Vw);
    int li = i - (i < W4 ? 0 : (i < 2 * W4 ? W4 : 2 * W4));
    float4 v = reinterpret_cast<const float4*>(src)[li];
    __half2* d = reinterpret_cast<__half2*>(dst) + 2 * i;
    d[0] = __floats2half2_rn(v.x, v.y);
    d[1] = __floats2half2_rn(v.z, v.w);
}

// ======================================================================
// fp16 mma GEMM core: CTA 128x128, 8 warps, warp 64x32, K-chunk 64 halfs,
// 3-stage cp.async, ONE barrier per chunk, 2 CTAs/SM.
// ======================================================================
#define GBM 128
#define GBN 128
#define GBK 64
#define LDSWH 72
#define TILE_HALFS (GBM * LDSWH)          // 9216
#define NCHUNK (DM / GBK)                 // 16
#define STAGE_HALFS (2 * TILE_HALFS)
#define GEMM_SMEM_BYTES (3 * STAGE_HALFS * 2)   // 110592

__device__ __forceinline__ void gemm_mainloop(
    const __half* __restrict__ A, const __half* __restrict__ W,
    uint32_t sbase, int bm, int bng,
    int tid, int wm, int wn, int lane,
    float acc[4][4][4])
{
    const int row = tid >> 1;
    const int seg = tid & 1;
    const __half* Ap = A + (size_t)(bm + row) * DM + seg * 32;
    const __half* Wp = W + (size_t)(bng + row) * DM + seg * 32;
    const uint32_t sdoff = (uint32_t)(row * LDSWH + seg * 32) * 2u;

#pragma unroll
    for (int s = 0; s < 2; s++) {
        const uint32_t ab = sbase + (uint32_t)s * (STAGE_HALFS * 2);
        const __half* ap = Ap + s * GBK;
        const __half* wp = Wp + s * GBK;
#pragma unroll
        for (int i = 0; i < 4; i++) {
            cp_async16(ab + sdoff + i * 16, ap + i * 8);
            cp_async16(ab + TILE_HALFS * 2 + sdoff + i * 16, wp + i * 8);
        }
        CP_COMMIT();
    }

    const int lr   = lane & 7;
    const int quad = lane >> 3;
    const uint32_t aAddr0 = sbase +
        (uint32_t)((wm * 64 + (quad & 1) * 8 + lr) * LDSWH + (quad >> 1) * 8) * 2u;
    const uint32_t bAddr0 = sbase + TILE_HALFS * 2 +
        (uint32_t)((wn * 32 + (quad >> 1) * 8 + lr) * LDSWH + (quad & 1) * 8) * 2u;

    for (int kt = 0; kt < NCHUNK; kt++) {
        CP_WAIT1();            // chunk kt resident (kt+1 in flight)
        __syncthreads();       // fills visible; compute of kt-1 retired by all warps

        // fill chunk kt+2 into stage (kt+2)%3 == (kt-1)%3 (retired) -- overlaps compute
        if (kt + 2 < NCHUNK) {
            const uint32_t ab = sbase + (uint32_t)((kt + 2) % 3) * (STAGE_HALFS * 2);
            const __half* ap = Ap + (kt + 2) * GBK;
            const __half* wp = Wp + (kt + 2) * GBK;
#pragma unroll
            for (int i = 0; i < 4; i++) {
                cp_async16(ab + sdoff + i * 16, ap + i * 8);
                cp_async16(ab + TILE_HALFS * 2 + sdoff + i * 16, wp + i * 8);
            }
        }
        CP_COMMIT();           // exactly one group per iteration

        const uint32_t sb = (uint32_t)(kt % 3) * (STAGE_HALFS * 2);
#pragma unroll
        for (int ks = 0; ks < 4; ks++) {
            uint32_t af[4][4];
#pragma unroll
            for (int mt = 0; mt < 4; mt++)
                ldsm_x4(af[mt], aAddr0 + sb + (uint32_t)(mt * (16 * LDSWH) + ks * 16) * 2u);
            uint32_t bf01[4], bf23[4];
            ldsm_x4(bf01, bAddr0 + sb + (uint32_t)(ks * 16) * 2u);
            ldsm_x4(bf23, bAddr0 + sb + (uint32_t)(16 * LDSWH + ks * 16) * 2u);
#pragma unroll
            for (int mt = 0; mt < 4; mt++) {
                mma_f16(acc[mt][0], af[mt][0], af[mt][1], af[mt][2], af[mt][3], bf01[0], bf01[1]);
                mma_f16(acc[mt][1], af[mt][0], af[mt][1], af[mt][2], af[mt][3], bf01[2], bf01[3]);
                mma_f16(acc[mt][2], af[mt][0], af[mt][1], af[mt][2], af[mt][3], bf23[0], bf23[1]);
                mma_f16(acc[mt][3], af[mt][0], af[mt][1], af[mt][2], af[mt][3], bf23[2], bf23[3]);
            }
        }
    }
}

// ---------------- O-projection GEMM (half in, float out) ----------------
__global__ __launch_bounds__(256, 2)
void gemm_f16(const __half* __restrict__ A,
              const __half* __restrict__ W,
              float* __restrict__ C) {
    extern __shared__ __half smemh[];
    const uint32_t sbase = smem_u32(smemh);
    const int tid  = threadIdx.x;
    const int wid  = tid >> 5;
    const int lane = tid & 31;
    const int bm = blockIdx.y * GBM;
    const int bn = blockIdx.x * GBN;
    const int wm = wid >> 2, wn = wid & 3;
    const int g = lane >> 2, tig = lane & 3;

    float acc[4][4][4];
#pragma unroll
    for (int i = 0; i < 4; i++)
#pragma unroll
        for (int j = 0; j < 4; j++)
#pragma unroll
            for (int r2 = 0; r2 < 4; r2++) acc[i][j][r2] = 0.f;

    gemm_mainloop(A, W, sbase, bm, bn, tid, wm, wn, lane, acc);

    const int m0 = bm + wm * 64 + g;
    const int n0 = bn + wn * 32 + 2 * tig;
#pragma unroll
    for (int mt = 0; mt < 4; mt++) {
#pragma unroll
        for (int nt = 0; nt < 4; nt++) {
            float* p0 = C + (size_t)(m0 + mt * 16) * DM + n0 + nt * 8;
            float* p1 = p0 + 8 * DM;
            *reinterpret_cast<float2*>(p0) = make_float2(acc[mt][nt][0], acc[mt][nt][1]);
            *reinterpret_cast<float2*>(p1) = make_float2(acc[mt][nt][2], acc[mt][nt][3]);
        }
    }
}

// ---------------- fused QKV GEMM + RoPE + scale -> fp16 ----------------
__global__ __launch_bounds__(256, 2)
void gemm_qkv(const __half* __restrict__ A,
              const __half* __restrict__ W,
              const int*    __restrict__ pos,
              __half* __restrict__ outq,
              __half* __restrict__ outk,
              __half* __restrict__ outv) {
    extern __shared__ __half smemh[];
    const uint32_t sbase = smem_u32(smemh);
    const int tid  = threadIdx.x;
    const int wid  = tid >> 5;
    const int lane = tid & 31;
    const int bm  = blockIdx.y * GBM;
    const int bng = blockIdx.x * GBN;
    const int wm = wid >> 2, wn = wid & 3;
    const int g = lane >> 2, tig = lane & 3;

    float acc[4][4][4];
#pragma unroll
    for (int i = 0; i < 4; i++)
#pragma unroll
        for (int j = 0; j < 4; j++)
#pragma unroll
            for (int r2 = 0; r2 < 4; r2++) acc[i][j][r2] = 0.f;

    gemm_mainloop(A, W, sbase, bm, bng, tid, wm, wn, lane, acc);

    const int region = blockIdx.x >> 3;
    __half* dst = (region == 0) ? outq : (region == 1 ? outk : outv);
    const int nbase = (blockIdx.x & 7) * GBN;
    const int m0 = bm + wm * 64 + g;
    const int n0 = nbase + wn * 32 + 2 * tig;

    if (region < 2) {
        const float scale = (region == 0) ? 0.125f : 1.0f;
        const float lt = 0.1439115683121279f;
        float invf[4];
#pragma unroll
        for (int nt = 0; nt < 4; nt++) {
            int c = (n0 + nt * 8) & (DK - 1);
            invf[nt] = __expf(-(float)c * lt);
        }
#pragma unroll
        for (int mt = 0; mt < 4; mt++) {
            const int r0 = m0 + mt * 16;
            const float p0 = (float)pos[r0];
            const float p1 = (float)pos[r0 + 8];
#pragma unroll
            for (int nt = 0; nt < 4; nt++) {
                float s0, c0, s1, c1;
                sincosf(p0 * invf[nt], &s0, &c0);
                sincosf(p1 * invf[nt], &s1, &c1);
                float e0 = acc[mt][nt][0], o0v = acc[mt][nt][1];
                float e1 = acc[mt][nt][2], o1v = acc[mt][nt][3];
                acc[mt][nt][0] = (e0 * c0 - o0v * s0) * scale;
                acc[mt][nt][1] = (e0 * s0 + o0v * c0) * scale;
                acc[mt][nt][2] = (e1 * c1 - o1v * s1) * scale;
                acc[mt][nt][3] = (e1 * s1 + o1v * c1) * scale;
            }
        }
    }

#pragma unroll
    for (int mt = 0; mt < 4; mt++) {
#pragma unroll
        for (int nt = 0; nt < 4; nt++) {
            __half2* p0 = reinterpret_cast<__half2*>(dst + (size_t)(m0 + mt * 16) * DM + n0 + nt * 8);
            __half2* p1 = reinterpret_cast<__half2*>(dst + (size_t)(m0 + mt * 16 + 8) * DM + n0 + nt * 8);
            *p0 = __floats2half2_rn(acc[mt][nt][0], acc[mt][nt][1]);
            *p1 = __floats2half2_rn(acc[mt][nt][2], acc[mt][nt][3]);
        }
    }
}

// ======================================================================
// fp16 mma causal flash attention, double-buffered cp.async K/V.
// ======================================================================
#define FQT 64
#define FKT 64
#define SH 72
#define KV_STAGE (2 * 64 * SH)            // K tile + V tile per stage (halfs)
#define FS_PS (2 * KV_STAGE)              // after the 2 stages
#define FS_TOTAL (FS_PS + 64 * SH)        // 23040 halfs = 46080 B

__global__ __launch_bounds__(128)
void flash_mma(const __half* __restrict__ q,
               const __half* __restrict__ k,
               const __half* __restrict__ v,
               __half* __restrict__ o) {
    extern __shared__ __half fsm[];
    __half* ps_ = fsm + FS_PS;
    const uint32_t base_u = smem_u32(fsm);

    const int tid  = threadIdx.x;
    const int w    = tid >> 5;
    const int lane = tid & 31;
    const int g    = lane >> 2;
    const int tig  = lane & 3;
    const int lr   = lane & 7;
    const int quad = lane >> 3;
    const int qb = gridDim.x - 1 - blockIdx.x;
    const int h  = blockIdx.y;
    const int b  = blockIdx.z;
    const int q0 = qb * FQT;
    const size_t tokBase = (size_t)b * SD;
    const int rb = w * 16;

    const __half* kbase0 = k + tokBase * DM + h * DK;
    const __half* vbase0 = v + tokBase * DM + h * DK;

    // per-thread fill mapping: 512 cp.async16 per matrix / 128 threads = 4 each
    const int fr0 = tid >> 1;            // unused placeholder removal
    // ldmatrix base addrs (bytes)
    const uint32_t aAddr0 = base_u + FS_PS * 2 +
        (uint32_t)((rb + (quad & 1) * 8 + lr) * SH + (quad >> 1) * 8) * 2u;   // P/Q a-frags
    const uint32_t kAddr0 = base_u +
        (uint32_t)(((quad >> 1) * 8 + lr) * SH + (quad & 1) * 8) * 2u;        // K b-frags (+stage)
    const uint32_t vAddrBase = base_u + (64 * SH) * 2u;                       // V within stage

    // ---- stage Q tile into ps_, prologue-fill K/V tile 0 ----
    {
        const __half* qbase = q + (tokBase + q0) * DM + h * DK;
#pragma unroll
        for (int i = 0; i < 16; i++) {
            int j = tid + 128 * i;
            int r = j >> 5, c2 = j & 31;
            __half2 t2 = *reinterpret_cast<const __half2*>(qbase + (size_t)r * DM + 2 * c2);
            *reinterpret_cast<__half2*>(ps_ + r * SH + 2 * c2) = t2;
        }
#pragma unroll
        for (int i = 0; i < 4; i++) {
            int j = tid + 128 * i;            // 512 segments
            int r = j >> 3, s8 = j & 7;
            uint32_t doff = (uint32_t)(r * SH + s8 * 8) * 2u;
            cp_async16(base_u + doff, kbase0 + (size_t)r * DM + s8 * 8);
            cp_async16(base_u + (64 * SH) * 2u + doff, vbase0 + (size_t)r * DM + s8 * 8);
        }
        CP_COMMIT();
    }
    __syncthreads();
    uint32_t qa[4][4];
#pragma unroll
    for (int ks = 0; ks < 4; ks++)
        ldsm_x4(qa[ks], aAddr0 + (uint32_t)(ks * 16) * 2u);

    float m0 = -1e30f, m1 = -1e30f, l0 = 0.f, l1 = 0.f;
    float oacc[8][4];
#pragma unroll
    for (int n = 0; n < 8; n++)
#pragma unroll
        for (int c = 0; c < 4; c++) oacc[n][c] = 0.f;

    const int ntiles = q0 / FKT + 1;
    for (int kt = 0; kt < ntiles; kt++) {
        const int k0 = kt * FKT;
        CP_WAIT0();           // tile kt resident
        __syncthreads();      // fills visible; compute of kt-1 retired

        // fill tile kt+1 into the other stage (retired at kt-1) -- overlaps compute
        if (kt + 1 < ntiles) {
            const uint32_t sb = (uint32_t)((kt + 1) & 1) * (KV_STAGE * 2);
            const __half* kb = kbase0 + (size_t)(k0 + FKT) * DM;
            const __half* vb = vbase0 + (size_t)(k0 + FKT) * DM;
#pragma unroll
            for (int i = 0; i < 4; i++) {
                int j = tid + 128 * i;
                int r = j >> 3, s8 = j & 7;
                uint32_t doff = (uint32_t)(r * SH + s8 * 8) * 2u;
                cp_async16(base_u + sb + doff, kb + (size_t)r * DM + s8 * 8);
                cp_async16(base_u + sb + (64 * SH) * 2u + doff, vb + (size_t)r * DM + s8 * 8);
            }
        }
        CP_COMMIT();

        const uint32_t sb = (uint32_t)(kt & 1) * (KV_STAGE * 2);

        // ---- QK^T ----
        float sacc[8][4];
#pragma unroll
        for (int n = 0; n < 8; n++)
#pragma unroll
            for (int c = 0; c < 4; c++) sacc[n][c] = 0.f;
#pragma unroll
        for (int ks = 0; ks < 4; ks++) {
#pragma unroll
            for (int np = 0; np < 4; np++) {
                uint32_t kb[4];
                ldsm_x4(kb, kAddr0 + sb + (uint32_t)(np * (16 * SH) + ks * 16) * 2u);
                mma_f16(sacc[2 * np],     qa[ks][0], qa[ks][1], qa[ks][2], qa[ks][3], kb[0], kb[1]);
                mma_f16(sacc[2 * np + 1], qa[ks][0], qa[ks][1], qa[ks][2], qa[ks][3], kb[2], kb[3]);
            }
        }

        // ---- causal mask on diagonal tile ----
        if (k0 == q0) {
            const int row0 = q0 + rb + g;
            const int row1 = row0 + 8;
#pragma unroll
            for (int n = 0; n < 8; n++) {
                int col = k0 + n * 8 + 2 * tig;
                if (col     > row0) sacc[n][0] = -1e30f;
                if (col + 1 > row0) sacc[n][1] = -1e30f;
                if (col     > row1) sacc[n][2] = -1e30f;
                if (col + 1 > row1) sacc[n][3] = -1e30f;
            }
        }

        // ---- online softmax ----
        float mx0 = -1e30f, mx1 = -1e30f;
#pragma unroll
        for (int n = 0; n < 8; n++) {
            mx0 = fmaxf(mx0, fmaxf(sacc[n][0], sacc[n][1]));
            mx1 = fmaxf(mx1, fmaxf(sacc[n][2], sacc[n][3]));
        }
        mx0 = fmaxf(mx0, __shfl_xor_sync(0xffffffffu, mx0, 1));
        mx0 = fmaxf(mx0, __shfl_xor_sync(0xffffffffu, mx0, 2));
        mx1 = fmaxf(mx1, __shfl_xor_sync(0xffffffffu, mx1, 1));
        mx1 = fmaxf(mx1, __shfl_xor_sync(0xffffffffu, mx1, 2));

        float mn0 = fmaxf(m0, mx0), mn1 = fmaxf(m1, mx1);
        float al0 = __expf(m0 - mn0), al1 = __expf(m1 - mn1);
        m0 = mn0; m1 = mn1;
        l0 *= al0; l1 *= al1;

        __half* ps0 = ps_ + (rb + g) * SH + 2 * tig;
        __half* ps1 = ps0 + 8 * SH;
#pragma unroll
        for (int n = 0; n < 8; n++) {
            float p0 = __expf(sacc[n][0] - mn0);
            float p1 = __expf(sacc[n][1] - mn0);
            float p2 = __expf(sacc[n][2] - mn1);
            float p3 = __expf(sacc[n][3] - mn1);
            l0 += p0 + p1;
            l1 += p2 + p3;
            *reinterpret_cast<__half2*>(ps0 + n * 8) = __floats2half2_rn(p0, p1);
            *reinterpret_cast<__half2*>(ps1 + n * 8) = __floats2half2_rn(p2, p3);
            oacc[n][0] *= al0; oacc[n][1] *= al0;
            oacc[n][2] *= al1; oacc[n][3] *= al1;
        }
        __syncwarp();

        // ---- P . V ----
#pragma unroll
        for (int ks = 0; ks < 4; ks++) {
            uint32_t pa[4];
            ldsm_x4(pa, aAddr0 + (uint32_t)(ks * 16) * 2u);
#pragma unroll
            for (int dblk = 0; dblk < 4; dblk++) {
                uint32_t addr = vAddrBase + sb +
                    (uint32_t)((ks * 16 + (lane & 15)) * SH + dblk * 16 + ((lane >> 4) << 3)) * 2u;
                uint32_t r0, r1, r2, r3;
                asm volatile(
                    "ldmatrix.sync.aligned.m8n8.x4.trans.shared.b16 {%0,%1,%2,%3}, [%4];"
                    : "=r"(r0), "=r"(r1), "=r"(r2), "=r"(r3) : "r"(addr));
                mma_f16(oacc[2 * dblk],     pa[0], pa[1], pa[2], pa[3], r0, r1);
                mma_f16(oacc[2 * dblk + 1], pa[0], pa[1], pa[2], pa[3], r2, r3);
            }
        }
    }

    // ---- epilogue ----
    l0 += __shfl_xor_sync(0xffffffffu, l0, 1);
    l0 += __shfl_xor_sync(0xffffffffu, l0, 2);
    l1 += __shfl_xor_sync(0xffffffffu, l1, 1);
    l1 += __shfl_xor_sync(0xffffffffu, l1, 2);
    float inv0 = 1.f / l0, inv1 = 1.f / l1;

    __half* o0 = o + (tokBase + q0 + rb + g) * DM + h * DK + 2 * tig;
    __half* o1 = o + (tokBase + q0 + rb + g + 8) * DM + h * DK + 2 * tig;
#pragma unroll
    for (int n = 0; n < 8; n++) {
        *reinterpret_cast<__half2*>(o0 + n * 8) =
            __floats2half2_rn(oacc[n][0] * inv0, oacc[n][1] * inv0);
        *reinterpret_cast<__half2*>(o1 + n * 8) =
            __floats2half2_rn(oacc[n][2] * inv1, oacc[n][3] * inv1);
    }
}

// ---------------- launch ----------------
extern "C" void kernel_launch(void* const* d_in, const int* in_sizes, int n_in,
                              void* d_out, int out_size) {
    const float* x  = (const float*)d_in[0];
    const int*   tp = (const int*)  d_in[1];
    const float* Qw = (const float*)d_in[2];
    const float* Kw = (const float*)d_in[3];
    const float* Vw = (const float*)d_in[4];
    const float* Ow = (const float*)d_in[5];
    float* out = (float*)d_out;

    __half *gq, *gk, *gv, *gao, *gxc, *gwqkv, *gwo;
    cudaGetSymbolAddress((void**)&gq,    g_q);
    cudaGetSymbolAddress((void**)&gk,    g_k);
    cudaGetSymbolAddress((void**)&gv,    g_v);
    cudaGetSymbolAddress((void**)&gao,   g_ao);
    cudaGetSymbolAddress((void**)&gxc,   g_xc);
    cudaGetSymbolAddress((void**)&gwqkv, g_wqkv);
    cudaGetSymbolAddress((void**)&gwo,   g_wo);

    cudaFuncSetAttribute(gemm_f16, cudaFuncAttributeMaxDynamicSharedMemorySize, GEMM_SMEM_BYTES);
    cudaFuncSetAttribute(gemm_qkv, cudaFuncAttributeMaxDynamicSharedMemorySize, GEMM_SMEM_BYTES);
    const int flash_smem = FS_TOTAL * 2;    // 46080
    cudaFuncSetAttribute(flash_mma, cudaFuncAttributeMaxDynamicSharedMemorySize, flash_smem);

    {
        int n4 = (int)(MTOK * (size_t)DM / 4);
        cvt_f16_kernel<<<(n4 + 255) / 256, 256>>>(x, gxc, n4);
        int p4 = 3 * DM * DM / 4;
        pack_qkv_w<<<(p4 + 255) / 256, 256>>>(Qw, Kw, Vw, gwqkv);
        int w4 = DM * DM / 4;
        cvt_f16_kernel<<<(w4 + 255) / 256, 256>>>(Ow, gwo, w4);
    }

    dim3 qgrid(3 * DM / GBN, MTOK / GBM);   // (24, 64)
    gemm_qkv<<<qgrid, 256, GEMM_SMEM_BYTES>>>(gxc, gwqkv, tp, gq, gk, gv);

    dim3 fgrid(SD / FQT, NH, BD);           // (32, 16, 4)
    flash_mma<<<fgrid, 128, flash_smem>>>(gq, gk, gv, gao);

    dim3 ggrid(DM / GBN, MTOK / GBM);       // (8, 64)
    gemm_f16<<<ggrid, 256, GEMM_SMEM_BYTES>>>(gao, gwo, out);
}